// round 1
// baseline (speedup 1.0000x reference)
#include <cuda_runtime.h>
#include <math.h>

// Problem constants
#define B_       2
#define T_       2048
#define C_       2048
#define NH_      16
#define HD_      128
#define GATE_CH_ 32
#define M_       (B_*T_)   // 4096 rows

// Scratch (device globals: allocation-free per harness rules)
__device__ float g_q[(size_t)M_*C_];
__device__ float g_k[(size_t)M_*C_];
__device__ float g_v[(size_t)M_*C_];
__device__ float g_y[(size_t)M_*C_];

// ---------------------------------------------------------------------------
// SGEMM: C = A[MxK] * B[KxN], row-major, 128x128 block tile, BK=8,
// 256 threads, 8x8 per-thread register tile.
// ---------------------------------------------------------------------------
__global__ __launch_bounds__(256) void sgemm128(
    const float* __restrict__ A, const float* __restrict__ Bm,
    float* __restrict__ Cm, int M, int N, int K)
{
    __shared__ float As[8][132];  // transposed A tile [k][m]
    __shared__ float Bs[8][132];  // B tile [k][n]

    const int tid  = threadIdx.x;
    const int row0 = blockIdx.y * 128;
    const int col0 = blockIdx.x * 128;
    const int ty = tid >> 4;      // 0..15 -> C rows ty*8..+8
    const int tx = tid & 15;      // 0..15 -> C cols tx*8..+8

    const int arow = tid >> 1;            // 0..127
    const int acol = (tid & 1) * 4;       // 0 or 4
    const int brow = tid >> 5;            // 0..7
    const int bcol = (tid & 31) * 4;      // 0..124

    float acc[8][8];
    #pragma unroll
    for (int i = 0; i < 8; i++)
        #pragma unroll
        for (int j = 0; j < 8; j++) acc[i][j] = 0.f;

    for (int k0 = 0; k0 < K; k0 += 8) {
        float4 av = *(const float4*)(A + (size_t)(row0 + arow) * K + k0 + acol);
        float4 bv = *(const float4*)(Bm + (size_t)(k0 + brow) * N + col0 + bcol);
        As[acol + 0][arow] = av.x;
        As[acol + 1][arow] = av.y;
        As[acol + 2][arow] = av.z;
        As[acol + 3][arow] = av.w;
        *(float4*)&Bs[brow][bcol] = bv;
        __syncthreads();

        #pragma unroll
        for (int kk = 0; kk < 8; kk++) {
            float a[8], b[8];
            float4 a0 = *(float4*)&As[kk][ty * 8];
            float4 a1 = *(float4*)&As[kk][ty * 8 + 4];
            float4 b0 = *(float4*)&Bs[kk][tx * 8];
            float4 b1 = *(float4*)&Bs[kk][tx * 8 + 4];
            a[0]=a0.x; a[1]=a0.y; a[2]=a0.z; a[3]=a0.w;
            a[4]=a1.x; a[5]=a1.y; a[6]=a1.z; a[7]=a1.w;
            b[0]=b0.x; b[1]=b0.y; b[2]=b0.z; b[3]=b0.w;
            b[4]=b1.x; b[5]=b1.y; b[6]=b1.z; b[7]=b1.w;
            #pragma unroll
            for (int i = 0; i < 8; i++)
                #pragma unroll
                for (int j = 0; j < 8; j++)
                    acc[i][j] += a[i] * b[j];
        }
        __syncthreads();
    }

    #pragma unroll
    for (int i = 0; i < 8; i++) {
        float4 w0 = make_float4(acc[i][0], acc[i][1], acc[i][2], acc[i][3]);
        float4 w1 = make_float4(acc[i][4], acc[i][5], acc[i][6], acc[i][7]);
        size_t base = (size_t)(row0 + ty * 8 + i) * N + col0 + tx * 8;
        *(float4*)(Cm + base)     = w0;
        *(float4*)(Cm + base + 4) = w1;
    }
}

// ---------------------------------------------------------------------------
// Prep: v += gate*ve ; q,k <- rmsnorm(rotary(.))   one block per (b,t),
// one warp per head (16 warps = 512 threads).
// ---------------------------------------------------------------------------
__device__ __forceinline__ float warp_sum(float v) {
    #pragma unroll
    for (int d = 16; d >= 1; d >>= 1) v += __shfl_xor_sync(0xffffffffu, v, d);
    return v;
}

__device__ __forceinline__ void rope_rms(float* v, const float* cr, const float* sr, int lane) {
    const int d0 = lane, d1 = lane + 32;
    float x1a = v[d0],      x2a = v[d0 + 64];
    float x1b = v[d1],      x2b = v[d1 + 64];
    float ca = cr[d0], sa = sr[d0], cb = cr[d1], sb = sr[d1];
    float o1a =  x1a * ca + x2a * sa;
    float o2a = -x1a * sa + x2a * ca;
    float o1b =  x1b * cb + x2b * sb;
    float o2b = -x1b * sb + x2b * cb;
    float ss = warp_sum(o1a*o1a + o2a*o2a + o1b*o1b + o2b*o2b);
    float r = rsqrtf(ss * (1.f / 128.f) + 1e-6f);
    v[d0]      = o1a * r;
    v[d0 + 64] = o2a * r;
    v[d1]      = o1b * r;
    v[d1 + 64] = o2b * r;
}

__global__ __launch_bounds__(512) void prep_kernel(
    const float* __restrict__ x, const float* __restrict__ ve,
    const float* __restrict__ cosb, const float* __restrict__ sinb,
    const float* __restrict__ Wgate)
{
    const int bt   = blockIdx.x;          // 0..4095
    const int t    = bt & (T_ - 1);
    const int h    = threadIdx.x >> 5;    // 0..15
    const int lane = threadIdx.x & 31;

    const float* xr = x + (size_t)bt * C_;
    // gate = 2*sigmoid(x[:,:32] @ Wgate[:,h])
    float sacc = warp_sum(xr[lane] * Wgate[lane * NH_ + h]);
    float g = 2.f / (1.f + __expf(-sacc));

    const size_t base = (size_t)bt * C_ + h * HD_;
    #pragma unroll
    for (int i = 0; i < 4; i++) {
        int d = lane + i * 32;
        g_v[base + d] += g * ve[base + d];
    }

    const float* cr = cosb + (size_t)t * 64;
    const float* sr = sinb + (size_t)t * 64;
    rope_rms(g_q + base, cr, sr, lane);
    rope_rms(g_k + base, cr, sr, lane);
}

// ---------------------------------------------------------------------------
// Flash attention (causal, fp32). BM=BN=64, HD=128, 256 threads.
// grid = (T/64, NH, B). Dynamic smem ~118 KB.
// ---------------------------------------------------------------------------
#define QK_STRIDE 68   // 64 + 4 pad, multiple of 4 (16B-aligned rows)
#define V_STRIDE  132  // 128 + 4 pad
#define S_STRIDE  68

__global__ __launch_bounds__(256) void flash_kernel()
{
    extern __shared__ float sm[];
    float* QsT = sm;                          // [128][QK_STRIDE]  (d-major)
    float* KsT = QsT + 128 * QK_STRIDE;       // [128][QK_STRIDE]
    float* Vs  = KsT + 128 * QK_STRIDE;       // [64][V_STRIDE]
    float* Ss  = Vs  + 64  * V_STRIDE;        // [64][S_STRIDE]

    const int tid = threadIdx.x;
    const int qt  = blockIdx.x;   // query tile
    const int h   = blockIdx.y;
    const int b   = blockIdx.z;

    const int ro  = (tid >> 4) * 4;  // 4 S-rows
    const int co4 = (tid & 15) * 4;  // 4 S-cols
    const int co8 = (tid & 15) * 8;  // 8 O-cols

    // Load Q tile transposed: QsT[d][r]
    const float* qbase = g_q + ((size_t)(b * T_ + qt * 64)) * C_ + h * HD_;
    for (int i = tid; i < 64 * 32; i += 256) {
        int r  = i >> 5;
        int c4 = (i & 31) << 2;
        float4 v = *(const float4*)(qbase + (size_t)r * C_ + c4);
        QsT[(c4 + 0) * QK_STRIDE + r] = v.x;
        QsT[(c4 + 1) * QK_STRIDE + r] = v.y;
        QsT[(c4 + 2) * QK_STRIDE + r] = v.z;
        QsT[(c4 + 3) * QK_STRIDE + r] = v.w;
    }

    float m_i[4], l_i[4], o[4][8];
    #pragma unroll
    for (int i = 0; i < 4; i++) {
        m_i[i] = -1e30f; l_i[i] = 0.f;
        #pragma unroll
        for (int c = 0; c < 8; c++) o[i][c] = 0.f;
    }

    const float scale = 0.08838834764831845f;  // 1/sqrt(128)

    for (int kb = 0; kb <= qt; kb++) {
        const float* kbase = g_k + ((size_t)(b * T_ + kb * 64)) * C_ + h * HD_;
        const float* vbase = g_v + ((size_t)(b * T_ + kb * 64)) * C_ + h * HD_;
        for (int i = tid; i < 64 * 32; i += 256) {
            int r  = i >> 5;
            int c4 = (i & 31) << 2;
            float4 kv = *(const float4*)(kbase + (size_t)r * C_ + c4);
            KsT[(c4 + 0) * QK_STRIDE + r] = kv.x;
            KsT[(c4 + 1) * QK_STRIDE + r] = kv.y;
            KsT[(c4 + 2) * QK_STRIDE + r] = kv.z;
            KsT[(c4 + 3) * QK_STRIDE + r] = kv.w;
            float4 vv = *(const float4*)(vbase + (size_t)r * C_ + c4);
            *(float4*)(Vs + r * V_STRIDE + c4) = vv;
        }
        __syncthreads();

        // S = Q K^T (4x4 per thread)
        float s[4][4];
        #pragma unroll
        for (int i = 0; i < 4; i++)
            #pragma unroll
            for (int j = 0; j < 4; j++) s[i][j] = 0.f;

        for (int kk = 0; kk < HD_; kk++) {
            float4 af = *(float4*)(QsT + kk * QK_STRIDE + ro);
            float4 bf = *(float4*)(KsT + kk * QK_STRIDE + co4);
            float a[4] = {af.x, af.y, af.z, af.w};
            float bb[4] = {bf.x, bf.y, bf.z, bf.w};
            #pragma unroll
            for (int i = 0; i < 4; i++)
                #pragma unroll
                for (int j = 0; j < 4; j++)
                    s[i][j] += a[i] * bb[j];
        }

        // scale + causal mask (only diagonal tile)
        if (kb == qt) {
            #pragma unroll
            for (int i = 0; i < 4; i++)
                #pragma unroll
                for (int j = 0; j < 4; j++)
                    s[i][j] = (co4 + j <= ro + i) ? s[i][j] * scale : -1e30f;
        } else {
            #pragma unroll
            for (int i = 0; i < 4; i++)
                #pragma unroll
                for (int j = 0; j < 4; j++)
                    s[i][j] *= scale;
        }

        // online softmax per row (row spread over 16 lanes of a half-warp)
        #pragma unroll
        for (int i = 0; i < 4; i++) {
            float mx = fmaxf(fmaxf(s[i][0], s[i][1]), fmaxf(s[i][2], s[i][3]));
            #pragma unroll
            for (int d = 8; d >= 1; d >>= 1)
                mx = fmaxf(mx, __shfl_xor_sync(0xffffffffu, mx, d));
            float mn = fmaxf(m_i[i], mx);
            float alpha = __expf(m_i[i] - mn);
            float rs = 0.f;
            #pragma unroll
            for (int j = 0; j < 4; j++) {
                float p = __expf(s[i][j] - mn);
                s[i][j] = p;
                rs += p;
            }
            #pragma unroll
            for (int d = 8; d >= 1; d >>= 1)
                rs += __shfl_xor_sync(0xffffffffu, rs, d);
            l_i[i] = l_i[i] * alpha + rs;
            m_i[i] = mn;
            #pragma unroll
            for (int c = 0; c < 8; c++) o[i][c] *= alpha;
            #pragma unroll
            for (int j = 0; j < 4; j++)
                Ss[(ro + i) * S_STRIDE + co4 + j] = s[i][j];
        }
        __syncthreads();

        // O += P V   (4 rows x 8 cols per thread)
        for (int j = 0; j < 64; j++) {
            float4 v0 = *(float4*)(Vs + j * V_STRIDE + co8);
            float4 v1 = *(float4*)(Vs + j * V_STRIDE + co8 + 4);
            float vv[8] = {v0.x, v0.y, v0.z, v0.w, v1.x, v1.y, v1.z, v1.w};
            #pragma unroll
            for (int i = 0; i < 4; i++) {
                float p = Ss[(ro + i) * S_STRIDE + j];
                #pragma unroll
                for (int c = 0; c < 8; c++)
                    o[i][c] += p * vv[c];
            }
        }
        __syncthreads();
    }

    // epilogue: O / l  -> g_y
    float* ybase = g_y + ((size_t)(b * T_ + qt * 64)) * C_ + h * HD_;
    #pragma unroll
    for (int i = 0; i < 4; i++) {
        float inv = 1.f / l_i[i];
        float4 w0 = make_float4(o[i][0]*inv, o[i][1]*inv, o[i][2]*inv, o[i][3]*inv);
        float4 w1 = make_float4(o[i][4]*inv, o[i][5]*inv, o[i][6]*inv, o[i][7]*inv);
        *(float4*)(ybase + (size_t)(ro + i) * C_ + co8)     = w0;
        *(float4*)(ybase + (size_t)(ro + i) * C_ + co8 + 4) = w1;
    }
}

// ---------------------------------------------------------------------------
// Launch
// ---------------------------------------------------------------------------
extern "C" void kernel_launch(void* const* d_in, const int* in_sizes, int n_in,
                              void* d_out, int out_size)
{
    (void)in_sizes; (void)n_in; (void)out_size;
    const float* x     = (const float*)d_in[0];
    const float* ve    = (const float*)d_in[1];
    const float* cosb  = (const float*)d_in[2];
    const float* sinb  = (const float*)d_in[3];
    const float* Wq    = (const float*)d_in[4];
    const float* Wk    = (const float*)d_in[5];
    const float* Wv    = (const float*)d_in[6];
    const float* Wgate = (const float*)d_in[7];
    const float* Wproj = (const float*)d_in[8];
    float* out = (float*)d_out;

    float *q, *k, *v, *y;
    cudaGetSymbolAddress((void**)&q, g_q);
    cudaGetSymbolAddress((void**)&k, g_k);
    cudaGetSymbolAddress((void**)&v, g_v);
    cudaGetSymbolAddress((void**)&y, g_y);

    dim3 gemm_grid(C_ / 128, M_ / 128);   // (16, 32)
    sgemm128<<<gemm_grid, 256>>>(x, Wq, q, M_, C_, C_);
    sgemm128<<<gemm_grid, 256>>>(x, Wk, k, M_, C_, C_);
    sgemm128<<<gemm_grid, 256>>>(x, Wv, v, M_, C_, C_);

    prep_kernel<<<M_, 512>>>(x, ve, cosb, sinb, Wgate);

    const int smem = (128 * QK_STRIDE * 2 + 64 * V_STRIDE + 64 * S_STRIDE) * 4;
    cudaFuncSetAttribute(flash_kernel, cudaFuncAttributeMaxDynamicSharedMemorySize, smem);
    flash_kernel<<<dim3(T_ / 64, NH_, B_), 256, smem>>>();

    sgemm128<<<gemm_grid, 256>>>(y, Wproj, out, M_, C_, C_);
}

// round 3
// speedup vs baseline: 1.6592x; 1.6592x over previous
#include <cuda_runtime.h>
#include <cuda_bf16.h>
#include <math.h>

// Problem constants
#define B_       2
#define T_       2048
#define C_       2048
#define NH_      16
#define HD_      128
#define GATE_CH_ 32
#define M_       (B_*T_)   // 4096 rows

// ---------------------------------------------------------------------------
// Scratch (device globals: allocation-free per harness rules)
// ---------------------------------------------------------------------------
__device__ float g_q[(size_t)M_*C_];
__device__ float g_k[(size_t)M_*C_];
__device__ float g_v[(size_t)M_*C_];
__device__ float g_y[(size_t)M_*C_];

__device__ __nv_bfloat16 g_xh[(size_t)M_*C_];
__device__ __nv_bfloat16 g_xl[(size_t)M_*C_];
__device__ __nv_bfloat16 g_yh[(size_t)M_*C_];
__device__ __nv_bfloat16 g_yl[(size_t)M_*C_];
// transposed split weights [N][K] for Wq, Wk, Wv, Wproj
__device__ __nv_bfloat16 g_wth[4][(size_t)C_*C_];
__device__ __nv_bfloat16 g_wtl[4][(size_t)C_*C_];

// ---------------------------------------------------------------------------
// PTX helpers (sm_103 baseline-safe: mma.sync + ldmatrix + cp.async)
// ---------------------------------------------------------------------------
__device__ __forceinline__ unsigned smem_u32(const void* p) {
    unsigned a;
    asm("{ .reg .u64 t; cvta.to.shared.u64 t, %1; cvt.u32.u64 %0, t; }"
        : "=r"(a) : "l"(p));
    return a;
}

#define CP_ASYNC16(dst_u32, src_ptr) \
    asm volatile("cp.async.cg.shared.global [%0], [%1], 16;" \
                 :: "r"(dst_u32), "l"(src_ptr))
#define CP_COMMIT() asm volatile("cp.async.commit_group;" ::: "memory")
#define CP_WAIT0()  asm volatile("cp.async.wait_group 0;" ::: "memory")
#define CP_WAIT1()  asm volatile("cp.async.wait_group 1;" ::: "memory")

__device__ __forceinline__ void ldmatrix_x4(unsigned* r, unsigned addr) {
    asm volatile("ldmatrix.sync.aligned.m8n8.x4.shared.b16 {%0,%1,%2,%3}, [%4];"
                 : "=r"(r[0]), "=r"(r[1]), "=r"(r[2]), "=r"(r[3]) : "r"(addr));
}
__device__ __forceinline__ void mma_bf16(float* c, const unsigned* a, const unsigned* b) {
    asm volatile(
        "mma.sync.aligned.m16n8k16.row.col.f32.bf16.bf16.f32 "
        "{%0,%1,%2,%3}, {%4,%5,%6,%7}, {%8,%9}, {%0,%1,%2,%3};"
        : "+f"(c[0]), "+f"(c[1]), "+f"(c[2]), "+f"(c[3])
        : "r"(a[0]), "r"(a[1]), "r"(a[2]), "r"(a[3]), "r"(b[0]), "r"(b[1]));
}

// ---------------------------------------------------------------------------
// convert_split: fp32 -> bf16 hi/lo (same layout)
// ---------------------------------------------------------------------------
__global__ __launch_bounds__(256) void convert_split(
    const float* __restrict__ in, __nv_bfloat16* __restrict__ h,
    __nv_bfloat16* __restrict__ l, int n4)
{
    int i = blockIdx.x * blockDim.x + threadIdx.x;
    if (i >= n4) return;
    float4 v = ((const float4*)in)[i];
    __nv_bfloat16 h0 = __float2bfloat16(v.x);
    __nv_bfloat16 h1 = __float2bfloat16(v.y);
    __nv_bfloat16 h2 = __float2bfloat16(v.z);
    __nv_bfloat16 h3 = __float2bfloat16(v.w);
    __nv_bfloat16 l0 = __float2bfloat16(v.x - __bfloat162float(h0));
    __nv_bfloat16 l1 = __float2bfloat16(v.y - __bfloat162float(h1));
    __nv_bfloat16 l2 = __float2bfloat16(v.z - __bfloat162float(h2));
    __nv_bfloat16 l3 = __float2bfloat16(v.w - __bfloat162float(h3));
    __nv_bfloat162* hp = (__nv_bfloat162*)(h + (size_t)i * 4);
    __nv_bfloat162* lp = (__nv_bfloat162*)(l + (size_t)i * 4);
    hp[0] = __nv_bfloat162(h0, h1); hp[1] = __nv_bfloat162(h2, h3);
    lp[0] = __nv_bfloat162(l0, l1); lp[1] = __nv_bfloat162(l2, l3);
}

// ---------------------------------------------------------------------------
// transpose_split: W[K][N] fp32 -> Wt_h/Wt_l[N][K] bf16
// ---------------------------------------------------------------------------
__global__ __launch_bounds__(256) void transpose_split(
    const float* __restrict__ W, __nv_bfloat16* __restrict__ th,
    __nv_bfloat16* __restrict__ tl, int K, int N)
{
    __shared__ float tile[32][33];
    int k0 = blockIdx.y * 32, n0 = blockIdx.x * 32;
    int tx = threadIdx.x, ty = threadIdx.y;  // block (32, 8)
    #pragma unroll
    for (int r = 0; r < 4; r++)
        tile[ty + 8 * r][tx] = W[(size_t)(k0 + ty + 8 * r) * N + n0 + tx];
    __syncthreads();
    #pragma unroll
    for (int r = 0; r < 4; r++) {
        float v = tile[tx][ty + 8 * r];
        __nv_bfloat16 h = __float2bfloat16(v);
        __nv_bfloat16 l = __float2bfloat16(v - __bfloat162float(h));
        size_t o = (size_t)(n0 + ty + 8 * r) * K + k0 + tx;
        th[o] = h; tl[o] = l;
    }
}

// ---------------------------------------------------------------------------
// HMMA split-bf16 GEMM: C[M][N] = A[M][K] * B[K][N]
// A as Ah/Al [M][K] bf16; B as Bh/Bl transposed [N][K] bf16.
// 128x128 CTA tile, 8 warps (4x2), warp tile 32x64, k-chunk 32,
// cp.async double-buffered. 3 products: AhBh + AhBl + AlBh.
// ---------------------------------------------------------------------------
#define KC        32
#define AS_STRIDE 40                        // bf16 elems per smem row (80B)
#define TILE_E    (128 * AS_STRIDE)         // elems per matrix tile
#define STAGE_E   (4 * TILE_E)              // Ah | Al | Bh | Bl

__global__ __launch_bounds__(256) void gemm_mma_bf16x3(
    const __nv_bfloat16* __restrict__ Ah, const __nv_bfloat16* __restrict__ Al,
    const __nv_bfloat16* __restrict__ Bh, const __nv_bfloat16* __restrict__ Bl,
    float* __restrict__ Cm, int Ncols, int K)
{
    extern __shared__ __nv_bfloat16 smb[];
    const int tid = threadIdx.x, wid = tid >> 5, lane = tid & 31;
    const int m0 = blockIdx.y * 128, n0 = blockIdx.x * 128;
    const int NCH = K / KC;
    const int wm = wid & 3;   // m block: 32 rows
    const int wn = wid >> 2;  // n block: 64 cols

    // loader: 512 16B-chunks per matrix = 2 per thread per matrix
    auto load_stage = [&](int c, int s) {
        const int k0 = c * KC;
        __nv_bfloat16* base = smb + s * STAGE_E;
        #pragma unroll
        for (int i = 0; i < 2; i++) {
            int cidx = tid + i * 256;       // 0..511
            int row  = cidx >> 2;
            int col8 = (cidx & 3) * 8;
            unsigned so = smem_u32(base + row * AS_STRIDE + col8);
            size_t ga = (size_t)(m0 + row) * K + k0 + col8;
            size_t gb = (size_t)(n0 + row) * K + k0 + col8;
            CP_ASYNC16(so,                           Ah + ga);
            CP_ASYNC16(so + TILE_E * 2,              Al + ga);
            CP_ASYNC16(so + TILE_E * 4,              Bh + gb);
            CP_ASYNC16(so + TILE_E * 6,              Bl + gb);
        }
    };

    float acc[2][8][4];
    #pragma unroll
    for (int mt = 0; mt < 2; mt++)
        #pragma unroll
        for (int nt = 0; nt < 8; nt++)
            #pragma unroll
            for (int r = 0; r < 4; r++) acc[mt][nt][r] = 0.f;

    load_stage(0, 0);
    CP_COMMIT();

    // ldmatrix lane addressing precompute
    const int a_row = wm * 32 + (lane & 15);         // + mt*16
    const int a_k8  = (lane >> 4) * 8;
    const int b_r   = lane & 7;
    const int b_grp = lane >> 3;
    const int b_row = wn * 64 + (b_grp >> 1) * 8 + b_r;  // + j*16
    const int b_k8  = (b_grp & 1) * 8;

    for (int c = 0; c < NCH; c++) {
        if (c + 1 < NCH) {
            load_stage(c + 1, (c + 1) & 1);
            CP_COMMIT();
            CP_WAIT1();
        } else {
            CP_WAIT0();
        }
        __syncthreads();

        const __nv_bfloat16* st = smb + (c & 1) * STAGE_E;
        const __nv_bfloat16* sAh = st;
        const __nv_bfloat16* sAl = st + TILE_E;
        const __nv_bfloat16* sBh = st + 2 * TILE_E;
        const __nv_bfloat16* sBl = st + 3 * TILE_E;

        #pragma unroll
        for (int k16 = 0; k16 < 2; k16++) {
            const int kb = k16 * 16;
            unsigned ah[2][4], al[2][4];
            #pragma unroll
            for (int mt = 0; mt < 2; mt++) {
                unsigned addr_h = smem_u32(sAh + (a_row + mt * 16) * AS_STRIDE + kb + a_k8);
                unsigned addr_l = smem_u32(sAl + (a_row + mt * 16) * AS_STRIDE + kb + a_k8);
                ldmatrix_x4(ah[mt], addr_h);
                ldmatrix_x4(al[mt], addr_l);
            }
            #pragma unroll
            for (int j = 0; j < 4; j++) {
                unsigned bh[4], bl[4];
                unsigned baddr_h = smem_u32(sBh + (b_row + j * 16) * AS_STRIDE + kb + b_k8);
                unsigned baddr_l = smem_u32(sBl + (b_row + j * 16) * AS_STRIDE + kb + b_k8);
                ldmatrix_x4(bh, baddr_h);
                ldmatrix_x4(bl, baddr_l);
                #pragma unroll
                for (int t = 0; t < 2; t++) {
                    const int nt = j * 2 + t;
                    #pragma unroll
                    for (int mt = 0; mt < 2; mt++) {
                        mma_bf16(acc[mt][nt], ah[mt], bh + t * 2);
                        mma_bf16(acc[mt][nt], ah[mt], bl + t * 2);
                        mma_bf16(acc[mt][nt], al[mt], bh + t * 2);
                    }
                }
            }
        }
        __syncthreads();
    }

    // Epilogue: C fragment -> global fp32
    const int cg = lane >> 2, ct = lane & 3;
    #pragma unroll
    for (int mt = 0; mt < 2; mt++) {
        const int row = m0 + wm * 32 + mt * 16 + cg;
        #pragma unroll
        for (int nt = 0; nt < 8; nt++) {
            const int col = n0 + wn * 64 + nt * 8 + ct * 2;
            float2 w0 = make_float2(acc[mt][nt][0], acc[mt][nt][1]);
            float2 w1 = make_float2(acc[mt][nt][2], acc[mt][nt][3]);
            *(float2*)(Cm + (size_t)row * Ncols + col)       = w0;
            *(float2*)(Cm + (size_t)(row + 8) * Ncols + col) = w1;
        }
    }
}

// ---------------------------------------------------------------------------
// Prep: v += gate*ve ; q,k <- rmsnorm(rotary(.))
// ---------------------------------------------------------------------------
__device__ __forceinline__ float warp_sum(float v) {
    #pragma unroll
    for (int d = 16; d >= 1; d >>= 1) v += __shfl_xor_sync(0xffffffffu, v, d);
    return v;
}

__device__ __forceinline__ void rope_rms(float* v, const float* cr, const float* sr, int lane) {
    const int d0 = lane, d1 = lane + 32;
    float x1a = v[d0],      x2a = v[d0 + 64];
    float x1b = v[d1],      x2b = v[d1 + 64];
    float ca = cr[d0], sa = sr[d0], cb = cr[d1], sb = sr[d1];
    float o1a =  x1a * ca + x2a * sa;
    float o2a = -x1a * sa + x2a * ca;
    float o1b =  x1b * cb + x2b * sb;
    float o2b = -x1b * sb + x2b * cb;
    float ss = warp_sum(o1a*o1a + o2a*o2a + o1b*o1b + o2b*o2b);
    float r = rsqrtf(ss * (1.f / 128.f) + 1e-6f);
    v[d0]      = o1a * r;
    v[d0 + 64] = o2a * r;
    v[d1]      = o1b * r;
    v[d1 + 64] = o2b * r;
}

__global__ __launch_bounds__(512) void prep_kernel(
    const float* __restrict__ x, const float* __restrict__ ve,
    const float* __restrict__ cosb, const float* __restrict__ sinb,
    const float* __restrict__ Wgate)
{
    const int bt   = blockIdx.x;
    const int t    = bt & (T_ - 1);
    const int h    = threadIdx.x >> 5;
    const int lane = threadIdx.x & 31;

    const float* xr = x + (size_t)bt * C_;
    float sacc = warp_sum(xr[lane] * Wgate[lane * NH_ + h]);
    float g = 2.f / (1.f + __expf(-sacc));

    const size_t base = (size_t)bt * C_ + h * HD_;
    #pragma unroll
    for (int i = 0; i < 4; i++) {
        int d = lane + i * 32;
        g_v[base + d] += g * ve[base + d];
    }

    const float* cr = cosb + (size_t)t * 64;
    const float* sr = sinb + (size_t)t * 64;
    rope_rms(g_q + base, cr, sr, lane);
    rope_rms(g_k + base, cr, sr, lane);
}

// ---------------------------------------------------------------------------
// Flash attention (causal, fp32). BM=BN=64, HD=128, 256 threads.
// ---------------------------------------------------------------------------
#define QK_STRIDE 68
#define V_STRIDE  132
#define S_STRIDE  68

__global__ __launch_bounds__(256) void flash_kernel()
{
    extern __shared__ float sm[];
    float* QsT = sm;
    float* KsT = QsT + 128 * QK_STRIDE;
    float* Vs  = KsT + 128 * QK_STRIDE;
    float* Ss  = Vs  + 64  * V_STRIDE;

    const int tid = threadIdx.x;
    const int qt  = blockIdx.x;
    const int h   = blockIdx.y;
    const int b   = blockIdx.z;

    const int ro  = (tid >> 4) * 4;
    const int co4 = (tid & 15) * 4;
    const int co8 = (tid & 15) * 8;

    const float* qbase = g_q + ((size_t)(b * T_ + qt * 64)) * C_ + h * HD_;
    for (int i = tid; i < 64 * 32; i += 256) {
        int r  = i >> 5;
        int c4 = (i & 31) << 2;
        float4 v = *(const float4*)(qbase + (size_t)r * C_ + c4);
        QsT[(c4 + 0) * QK_STRIDE + r] = v.x;
        QsT[(c4 + 1) * QK_STRIDE + r] = v.y;
        QsT[(c4 + 2) * QK_STRIDE + r] = v.z;
        QsT[(c4 + 3) * QK_STRIDE + r] = v.w;
    }

    float m_i[4], l_i[4], o[4][8];
    #pragma unroll
    for (int i = 0; i < 4; i++) {
        m_i[i] = -1e30f; l_i[i] = 0.f;
        #pragma unroll
        for (int c = 0; c < 8; c++) o[i][c] = 0.f;
    }

    const float scale = 0.08838834764831845f;

    for (int kb = 0; kb <= qt; kb++) {
        const float* kbase = g_k + ((size_t)(b * T_ + kb * 64)) * C_ + h * HD_;
        const float* vbase = g_v + ((size_t)(b * T_ + kb * 64)) * C_ + h * HD_;
        for (int i = tid; i < 64 * 32; i += 256) {
            int r  = i >> 5;
            int c4 = (i & 31) << 2;
            float4 kv = *(const float4*)(kbase + (size_t)r * C_ + c4);
            KsT[(c4 + 0) * QK_STRIDE + r] = kv.x;
            KsT[(c4 + 1) * QK_STRIDE + r] = kv.y;
            KsT[(c4 + 2) * QK_STRIDE + r] = kv.z;
            KsT[(c4 + 3) * QK_STRIDE + r] = kv.w;
            float4 vv = *(const float4*)(vbase + (size_t)r * C_ + c4);
            *(float4*)(Vs + r * V_STRIDE + c4) = vv;
        }
        __syncthreads();

        float s[4][4];
        #pragma unroll
        for (int i = 0; i < 4; i++)
            #pragma unroll
            for (int j = 0; j < 4; j++) s[i][j] = 0.f;

        for (int kk = 0; kk < HD_; kk++) {
            float4 af = *(float4*)(QsT + kk * QK_STRIDE + ro);
            float4 bf = *(float4*)(KsT + kk * QK_STRIDE + co4);
            float a[4] = {af.x, af.y, af.z, af.w};
            float bb[4] = {bf.x, bf.y, bf.z, bf.w};
            #pragma unroll
            for (int i = 0; i < 4; i++)
                #pragma unroll
                for (int j = 0; j < 4; j++)
                    s[i][j] += a[i] * bb[j];
        }

        if (kb == qt) {
            #pragma unroll
            for (int i = 0; i < 4; i++)
                #pragma unroll
                for (int j = 0; j < 4; j++)
                    s[i][j] = (co4 + j <= ro + i) ? s[i][j] * scale : -1e30f;
        } else {
            #pragma unroll
            for (int i = 0; i < 4; i++)
                #pragma unroll
                for (int j = 0; j < 4; j++)
                    s[i][j] *= scale;
        }

        #pragma unroll
        for (int i = 0; i < 4; i++) {
            float mx = fmaxf(fmaxf(s[i][0], s[i][1]), fmaxf(s[i][2], s[i][3]));
            #pragma unroll
            for (int d = 8; d >= 1; d >>= 1)
                mx = fmaxf(mx, __shfl_xor_sync(0xffffffffu, mx, d));
            float mn = fmaxf(m_i[i], mx);
            float alpha = __expf(m_i[i] - mn);
            float rs = 0.f;
            #pragma unroll
            for (int j = 0; j < 4; j++) {
                float p = __expf(s[i][j] - mn);
                s[i][j] = p;
                rs += p;
            }
            #pragma unroll
            for (int d = 8; d >= 1; d >>= 1)
                rs += __shfl_xor_sync(0xffffffffu, rs, d);
            l_i[i] = l_i[i] * alpha + rs;
            m_i[i] = mn;
            #pragma unroll
            for (int c = 0; c < 8; c++) o[i][c] *= alpha;
            #pragma unroll
            for (int j = 0; j < 4; j++)
                Ss[(ro + i) * S_STRIDE + co4 + j] = s[i][j];
        }
        __syncthreads();

        for (int j = 0; j < 64; j++) {
            float4 v0 = *(float4*)(Vs + j * V_STRIDE + co8);
            float4 v1 = *(float4*)(Vs + j * V_STRIDE + co8 + 4);
            float vv[8] = {v0.x, v0.y, v0.z, v0.w, v1.x, v1.y, v1.z, v1.w};
            #pragma unroll
            for (int i = 0; i < 4; i++) {
                float p = Ss[(ro + i) * S_STRIDE + j];
                #pragma unroll
                for (int c = 0; c < 8; c++)
                    o[i][c] += p * vv[c];
            }
        }
        __syncthreads();
    }

    float* ybase = g_y + ((size_t)(b * T_ + qt * 64)) * C_ + h * HD_;
    #pragma unroll
    for (int i = 0; i < 4; i++) {
        float inv = 1.f / l_i[i];
        float4 w0 = make_float4(o[i][0]*inv, o[i][1]*inv, o[i][2]*inv, o[i][3]*inv);
        float4 w1 = make_float4(o[i][4]*inv, o[i][5]*inv, o[i][6]*inv, o[i][7]*inv);
        *(float4*)(ybase + (size_t)(ro + i) * C_ + co8)     = w0;
        *(float4*)(ybase + (size_t)(ro + i) * C_ + co8 + 4) = w1;
    }
}

// ---------------------------------------------------------------------------
// Launch
// ---------------------------------------------------------------------------
extern "C" void kernel_launch(void* const* d_in, const int* in_sizes, int n_in,
                              void* d_out, int out_size)
{
    (void)in_sizes; (void)n_in; (void)out_size;
    const float* x     = (const float*)d_in[0];
    const float* ve    = (const float*)d_in[1];
    const float* cosb  = (const float*)d_in[2];
    const float* sinb  = (const float*)d_in[3];
    const float* Wq    = (const float*)d_in[4];
    const float* Wk    = (const float*)d_in[5];
    const float* Wv    = (const float*)d_in[6];
    const float* Wgate = (const float*)d_in[7];
    const float* Wproj = (const float*)d_in[8];
    float* out = (float*)d_out;

    float *q, *k, *v, *y;
    cudaGetSymbolAddress((void**)&q, g_q);
    cudaGetSymbolAddress((void**)&k, g_k);
    cudaGetSymbolAddress((void**)&v, g_v);
    cudaGetSymbolAddress((void**)&y, g_y);
    __nv_bfloat16 *xh, *xl, *yh, *yl, *wth, *wtl;
    cudaGetSymbolAddress((void**)&xh, g_xh);
    cudaGetSymbolAddress((void**)&xl, g_xl);
    cudaGetSymbolAddress((void**)&yh, g_yh);
    cudaGetSymbolAddress((void**)&yl, g_yl);
    cudaGetSymbolAddress((void**)&wth, g_wth);
    cudaGetSymbolAddress((void**)&wtl, g_wtl);
    const size_t WSZ = (size_t)C_ * C_;

    // split x
    convert_split<<<(M_*C_/4 + 255)/256, 256>>>(x, xh, xl, M_*C_/4);
    // transpose+split weights
    dim3 tgrid(C_/32, C_/32), tblk(32, 8);
    transpose_split<<<tgrid, tblk>>>(Wq,    wth + 0*WSZ, wtl + 0*WSZ, C_, C_);
    transpose_split<<<tgrid, tblk>>>(Wk,    wth + 1*WSZ, wtl + 1*WSZ, C_, C_);
    transpose_split<<<tgrid, tblk>>>(Wv,    wth + 2*WSZ, wtl + 2*WSZ, C_, C_);
    transpose_split<<<tgrid, tblk>>>(Wproj, wth + 3*WSZ, wtl + 3*WSZ, C_, C_);

    const int gemm_smem = 2 * STAGE_E * (int)sizeof(__nv_bfloat16);  // 81920 B
    cudaFuncSetAttribute(gemm_mma_bf16x3, cudaFuncAttributeMaxDynamicSharedMemorySize, gemm_smem);
    dim3 ggrid(C_/128, M_/128);  // (16, 32)
    gemm_mma_bf16x3<<<ggrid, 256, gemm_smem>>>(xh, xl, wth + 0*WSZ, wtl + 0*WSZ, q, C_, C_);
    gemm_mma_bf16x3<<<ggrid, 256, gemm_smem>>>(xh, xl, wth + 1*WSZ, wtl + 1*WSZ, k, C_, C_);
    gemm_mma_bf16x3<<<ggrid, 256, gemm_smem>>>(xh, xl, wth + 2*WSZ, wtl + 2*WSZ, v, C_, C_);

    prep_kernel<<<M_, 512>>>(x, ve, cosb, sinb, Wgate);

    const int fsmem = (128 * QK_STRIDE * 2 + 64 * V_STRIDE + 64 * S_STRIDE) * 4;
    cudaFuncSetAttribute(flash_kernel, cudaFuncAttributeMaxDynamicSharedMemorySize, fsmem);
    flash_kernel<<<dim3(T_/64, NH_, B_), 256, fsmem>>>();

    convert_split<<<(M_*C_/4 + 255)/256, 256>>>(y, yh, yl, M_*C_/4);
    gemm_mma_bf16x3<<<ggrid, 256, gemm_smem>>>(yh, yl, wth + 3*WSZ, wtl + 3*WSZ, out, C_, C_);
}

// round 4
// speedup vs baseline: 2.6343x; 1.5877x over previous
#include <cuda_runtime.h>
#include <cuda_bf16.h>
#include <math.h>

// Problem constants
#define B_       2
#define T_       2048
#define C_       2048
#define NH_      16
#define HD_      128
#define GATE_CH_ 32
#define M_       (B_*T_)   // 4096 rows

// ---------------------------------------------------------------------------
// Scratch (device globals: allocation-free per harness rules)
// ---------------------------------------------------------------------------
__device__ float g_q[(size_t)M_*C_];
__device__ float g_k[(size_t)M_*C_];
__device__ float g_v[(size_t)M_*C_];
__device__ float g_y[(size_t)M_*C_];

__device__ __nv_bfloat16 g_xh[(size_t)M_*C_];
__device__ __nv_bfloat16 g_xl[(size_t)M_*C_];
__device__ __nv_bfloat16 g_yh[(size_t)M_*C_];
__device__ __nv_bfloat16 g_yl[(size_t)M_*C_];
// attention operand splits
__device__ __nv_bfloat16 g_qh[(size_t)M_*C_];
__device__ __nv_bfloat16 g_ql[(size_t)M_*C_];
__device__ __nv_bfloat16 g_kh[(size_t)M_*C_];
__device__ __nv_bfloat16 g_kl[(size_t)M_*C_];
__device__ __nv_bfloat16 g_vh[(size_t)M_*C_];
__device__ __nv_bfloat16 g_vl[(size_t)M_*C_];
// transposed split weights [N][K] for Wq, Wk, Wv, Wproj
__device__ __nv_bfloat16 g_wth[4][(size_t)C_*C_];
__device__ __nv_bfloat16 g_wtl[4][(size_t)C_*C_];

// ---------------------------------------------------------------------------
// PTX helpers (sm_103 baseline-safe: mma.sync + ldmatrix + cp.async)
// ---------------------------------------------------------------------------
__device__ __forceinline__ unsigned smem_u32(const void* p) {
    unsigned a;
    asm("{ .reg .u64 t; cvta.to.shared.u64 t, %1; cvt.u32.u64 %0, t; }"
        : "=r"(a) : "l"(p));
    return a;
}

#define CP_ASYNC16(dst_u32, src_ptr) \
    asm volatile("cp.async.cg.shared.global [%0], [%1], 16;" \
                 :: "r"(dst_u32), "l"(src_ptr))
#define CP_COMMIT() asm volatile("cp.async.commit_group;" ::: "memory")
#define CP_WAIT0()  asm volatile("cp.async.wait_group 0;" ::: "memory")
#define CP_WAIT1()  asm volatile("cp.async.wait_group 1;" ::: "memory")

__device__ __forceinline__ void ldmatrix_x4(unsigned* r, unsigned addr) {
    asm volatile("ldmatrix.sync.aligned.m8n8.x4.shared.b16 {%0,%1,%2,%3}, [%4];"
                 : "=r"(r[0]), "=r"(r[1]), "=r"(r[2]), "=r"(r[3]) : "r"(addr));
}
__device__ __forceinline__ void ldmatrix_x4_trans(unsigned* r, unsigned addr) {
    asm volatile("ldmatrix.sync.aligned.m8n8.x4.trans.shared.b16 {%0,%1,%2,%3}, [%4];"
                 : "=r"(r[0]), "=r"(r[1]), "=r"(r[2]), "=r"(r[3]) : "r"(addr));
}
__device__ __forceinline__ void mma_bf16(float* c, const unsigned* a, const unsigned* b) {
    asm volatile(
        "mma.sync.aligned.m16n8k16.row.col.f32.bf16.bf16.f32 "
        "{%0,%1,%2,%3}, {%4,%5,%6,%7}, {%8,%9}, {%0,%1,%2,%3};"
        : "+f"(c[0]), "+f"(c[1]), "+f"(c[2]), "+f"(c[3])
        : "r"(a[0]), "r"(a[1]), "r"(a[2]), "r"(a[3]), "r"(b[0]), "r"(b[1]));
}
__device__ __forceinline__ unsigned prmt_hi(unsigned a, unsigned b) {
    unsigned d;
    asm("prmt.b32 %0, %1, %2, 0x7632;" : "=r"(d) : "r"(a), "r"(b));
    return d;
}
__device__ __forceinline__ unsigned cvt_bf16x2(float lo, float hi) {
    unsigned d;
    asm("cvt.rn.bf16x2.f32 %0, %1, %2;" : "=r"(d) : "f"(hi), "f"(lo));
    return d;
}
__device__ __forceinline__ float ex2(float x) {
    float y;
    asm("ex2.approx.f32 %0, %1;" : "=f"(y) : "f"(x));
    return y;
}

// ---------------------------------------------------------------------------
// convert_split: fp32 -> bf16 hi/lo (same layout)
// ---------------------------------------------------------------------------
__global__ __launch_bounds__(256) void convert_split(
    const float* __restrict__ in, __nv_bfloat16* __restrict__ h,
    __nv_bfloat16* __restrict__ l, int n4)
{
    int i = blockIdx.x * blockDim.x + threadIdx.x;
    if (i >= n4) return;
    float4 v = ((const float4*)in)[i];
    __nv_bfloat16 h0 = __float2bfloat16(v.x);
    __nv_bfloat16 h1 = __float2bfloat16(v.y);
    __nv_bfloat16 h2 = __float2bfloat16(v.z);
    __nv_bfloat16 h3 = __float2bfloat16(v.w);
    __nv_bfloat16 l0 = __float2bfloat16(v.x - __bfloat162float(h0));
    __nv_bfloat16 l1 = __float2bfloat16(v.y - __bfloat162float(h1));
    __nv_bfloat16 l2 = __float2bfloat16(v.z - __bfloat162float(h2));
    __nv_bfloat16 l3 = __float2bfloat16(v.w - __bfloat162float(h3));
    __nv_bfloat162* hp = (__nv_bfloat162*)(h + (size_t)i * 4);
    __nv_bfloat162* lp = (__nv_bfloat162*)(l + (size_t)i * 4);
    hp[0] = __nv_bfloat162(h0, h1); hp[1] = __nv_bfloat162(h2, h3);
    lp[0] = __nv_bfloat162(l0, l1); lp[1] = __nv_bfloat162(l2, l3);
}

// ---------------------------------------------------------------------------
// transpose_split: W[K][N] fp32 -> Wt_h/Wt_l[N][K] bf16
// ---------------------------------------------------------------------------
__global__ __launch_bounds__(256) void transpose_split(
    const float* __restrict__ W, __nv_bfloat16* __restrict__ th,
    __nv_bfloat16* __restrict__ tl, int K, int N)
{
    __shared__ float tile[32][33];
    int k0 = blockIdx.y * 32, n0 = blockIdx.x * 32;
    int tx = threadIdx.x, ty = threadIdx.y;  // block (32, 8)
    #pragma unroll
    for (int r = 0; r < 4; r++)
        tile[ty + 8 * r][tx] = W[(size_t)(k0 + ty + 8 * r) * N + n0 + tx];
    __syncthreads();
    #pragma unroll
    for (int r = 0; r < 4; r++) {
        float v = tile[tx][ty + 8 * r];
        __nv_bfloat16 h = __float2bfloat16(v);
        __nv_bfloat16 l = __float2bfloat16(v - __bfloat162float(h));
        size_t o = (size_t)(n0 + ty + 8 * r) * K + k0 + tx;
        th[o] = h; tl[o] = l;
    }
}

// ---------------------------------------------------------------------------
// HMMA split-bf16 GEMM: C[M][N] = A[M][K] * B[K][N]
// ---------------------------------------------------------------------------
#define KC        32
#define AS_STRIDE 40                        // bf16 elems per smem row (80B)
#define TILE_E    (128 * AS_STRIDE)         // elems per matrix tile
#define STAGE_E   (4 * TILE_E)              // Ah | Al | Bh | Bl

__global__ __launch_bounds__(256) void gemm_mma_bf16x3(
    const __nv_bfloat16* __restrict__ Ah, const __nv_bfloat16* __restrict__ Al,
    const __nv_bfloat16* __restrict__ Bh, const __nv_bfloat16* __restrict__ Bl,
    float* __restrict__ Cm, int Ncols, int K)
{
    extern __shared__ __nv_bfloat16 smb[];
    const int tid = threadIdx.x, wid = tid >> 5, lane = tid & 31;
    const int m0 = blockIdx.y * 128, n0 = blockIdx.x * 128;
    const int NCH = K / KC;
    const int wm = wid & 3;
    const int wn = wid >> 2;

    auto load_stage = [&](int c, int s) {
        const int k0 = c * KC;
        __nv_bfloat16* base = smb + s * STAGE_E;
        #pragma unroll
        for (int i = 0; i < 2; i++) {
            int cidx = tid + i * 256;
            int row  = cidx >> 2;
            int col8 = (cidx & 3) * 8;
            unsigned so = smem_u32(base + row * AS_STRIDE + col8);
            size_t ga = (size_t)(m0 + row) * K + k0 + col8;
            size_t gb = (size_t)(n0 + row) * K + k0 + col8;
            CP_ASYNC16(so,              Ah + ga);
            CP_ASYNC16(so + TILE_E * 2, Al + ga);
            CP_ASYNC16(so + TILE_E * 4, Bh + gb);
            CP_ASYNC16(so + TILE_E * 6, Bl + gb);
        }
    };

    float acc[2][8][4];
    #pragma unroll
    for (int mt = 0; mt < 2; mt++)
        #pragma unroll
        for (int nt = 0; nt < 8; nt++)
            #pragma unroll
            for (int r = 0; r < 4; r++) acc[mt][nt][r] = 0.f;

    load_stage(0, 0);
    CP_COMMIT();

    const int a_row = wm * 32 + (lane & 15);
    const int a_k8  = (lane >> 4) * 8;
    const int b_r   = lane & 7;
    const int b_grp = lane >> 3;
    const int b_row = wn * 64 + (b_grp >> 1) * 8 + b_r;
    const int b_k8  = (b_grp & 1) * 8;

    for (int c = 0; c < NCH; c++) {
        if (c + 1 < NCH) {
            load_stage(c + 1, (c + 1) & 1);
            CP_COMMIT();
            CP_WAIT1();
        } else {
            CP_WAIT0();
        }
        __syncthreads();

        const __nv_bfloat16* st = smb + (c & 1) * STAGE_E;
        const __nv_bfloat16* sAh = st;
        const __nv_bfloat16* sAl = st + TILE_E;
        const __nv_bfloat16* sBh = st + 2 * TILE_E;
        const __nv_bfloat16* sBl = st + 3 * TILE_E;

        #pragma unroll
        for (int k16 = 0; k16 < 2; k16++) {
            const int kb = k16 * 16;
            unsigned ah[2][4], al[2][4];
            #pragma unroll
            for (int mt = 0; mt < 2; mt++) {
                ldmatrix_x4(ah[mt], smem_u32(sAh + (a_row + mt * 16) * AS_STRIDE + kb + a_k8));
                ldmatrix_x4(al[mt], smem_u32(sAl + (a_row + mt * 16) * AS_STRIDE + kb + a_k8));
            }
            #pragma unroll
            for (int j = 0; j < 4; j++) {
                unsigned bh[4], bl[4];
                ldmatrix_x4(bh, smem_u32(sBh + (b_row + j * 16) * AS_STRIDE + kb + b_k8));
                ldmatrix_x4(bl, smem_u32(sBl + (b_row + j * 16) * AS_STRIDE + kb + b_k8));
                #pragma unroll
                for (int t = 0; t < 2; t++) {
                    const int nt = j * 2 + t;
                    #pragma unroll
                    for (int mt = 0; mt < 2; mt++) {
                        mma_bf16(acc[mt][nt], ah[mt], bh + t * 2);
                        mma_bf16(acc[mt][nt], ah[mt], bl + t * 2);
                        mma_bf16(acc[mt][nt], al[mt], bh + t * 2);
                    }
                }
            }
        }
        __syncthreads();
    }

    const int cg = lane >> 2, ct = lane & 3;
    #pragma unroll
    for (int mt = 0; mt < 2; mt++) {
        const int row = m0 + wm * 32 + mt * 16 + cg;
        #pragma unroll
        for (int nt = 0; nt < 8; nt++) {
            const int col = n0 + wn * 64 + nt * 8 + ct * 2;
            float2 w0 = make_float2(acc[mt][nt][0], acc[mt][nt][1]);
            float2 w1 = make_float2(acc[mt][nt][2], acc[mt][nt][3]);
            *(float2*)(Cm + (size_t)row * Ncols + col)       = w0;
            *(float2*)(Cm + (size_t)(row + 8) * Ncols + col) = w1;
        }
    }
}

// ---------------------------------------------------------------------------
// Prep: v += gate*ve ; q,k <- rmsnorm(rotary(.)), emit bf16 hi/lo splits
// ---------------------------------------------------------------------------
__device__ __forceinline__ float warp_sum(float v) {
    #pragma unroll
    for (int d = 16; d >= 1; d >>= 1) v += __shfl_xor_sync(0xffffffffu, v, d);
    return v;
}

__device__ __forceinline__ void split_store(
    float v, __nv_bfloat16* __restrict__ h, __nv_bfloat16* __restrict__ l, size_t idx)
{
    __nv_bfloat16 hh = __float2bfloat16(v);
    h[idx] = hh;
    l[idx] = __float2bfloat16(v - __bfloat162float(hh));
}

__device__ __forceinline__ void rope_rms_split(
    const float* __restrict__ src, const float* cr, const float* sr, int lane,
    __nv_bfloat16* __restrict__ dh, __nv_bfloat16* __restrict__ dl, size_t base)
{
    const int d0 = lane, d1 = lane + 32;
    float x1a = src[d0],      x2a = src[d0 + 64];
    float x1b = src[d1],      x2b = src[d1 + 64];
    float ca = cr[d0], sa = sr[d0], cb = cr[d1], sb = sr[d1];
    float o1a =  x1a * ca + x2a * sa;
    float o2a = -x1a * sa + x2a * ca;
    float o1b =  x1b * cb + x2b * sb;
    float o2b = -x1b * sb + x2b * cb;
    float ss = warp_sum(o1a*o1a + o2a*o2a + o1b*o1b + o2b*o2b);
    float r = rsqrtf(ss * (1.f / 128.f) + 1e-6f);
    split_store(o1a * r, dh, dl, base + d0);
    split_store(o2a * r, dh, dl, base + d0 + 64);
    split_store(o1b * r, dh, dl, base + d1);
    split_store(o2b * r, dh, dl, base + d1 + 64);
}

__global__ __launch_bounds__(512) void prep_kernel(
    const float* __restrict__ x, const float* __restrict__ ve,
    const float* __restrict__ cosb, const float* __restrict__ sinb,
    const float* __restrict__ Wgate)
{
    const int bt   = blockIdx.x;
    const int t    = bt & (T_ - 1);
    const int h    = threadIdx.x >> 5;
    const int lane = threadIdx.x & 31;

    const float* xr = x + (size_t)bt * C_;
    float sacc = warp_sum(xr[lane] * Wgate[lane * NH_ + h]);
    float g = 2.f / (1.f + __expf(-sacc));

    const size_t base = (size_t)bt * C_ + h * HD_;
    #pragma unroll
    for (int i = 0; i < 4; i++) {
        int d = lane + i * 32;
        float vv = g_v[base + d] + g * ve[base + d];
        split_store(vv, g_vh, g_vl, base + d);
    }

    const float* cr = cosb + (size_t)t * 64;
    const float* sr = sinb + (size_t)t * 64;
    rope_rms_split(g_q + base, cr, sr, lane, g_qh, g_ql, base);
    rope_rms_split(g_k + base, cr, sr, lane, g_kh, g_kl, base);
}

// ---------------------------------------------------------------------------
// HMMA flash attention (causal, split-bf16). BM=128, BN=64, HD=128.
// 256 threads = 8 warps, each warp owns 16 query rows.
// ---------------------------------------------------------------------------
#define FST    136                 // smem row stride (bf16 elems), 272B
#define FKV    (64 * FST)          // one 64-row tile
#define FQ     (128 * FST)         // one 128-row tile

__global__ __launch_bounds__(256) void flash_mma()
{
    extern __shared__ __nv_bfloat16 fsm[];
    __nv_bfloat16* sQh = fsm;              // [128][FST]
    __nv_bfloat16* sQl = sQh + FQ;
    __nv_bfloat16* sKV = sQl + FQ;         // 2 stages x (Kh|Kl|Vh|Vl)[64][FST]

    const int tid = threadIdx.x, wid = tid >> 5, lane = tid & 31;
    const int qb = gridDim.x - 1 - blockIdx.x;   // big tiles first
    const int h  = blockIdx.y;
    const int b  = blockIdx.z;

    const size_t qrow0 = (size_t)(b * T_ + qb * 128) * C_ + h * HD_;
    const size_t krow0 = (size_t)(b * T_) * C_ + h * HD_;

    // --- load Q (hi+lo) + KV tile 0 ---
    for (int i = tid; i < 2048; i += 256) {
        int r = i >> 4, c8 = (i & 15) * 8;
        size_t go = qrow0 + (size_t)r * C_ + c8;
        CP_ASYNC16(smem_u32(sQh + r * FST + c8), g_qh + go);
        CP_ASYNC16(smem_u32(sQl + r * FST + c8), g_ql + go);
    }
    auto load_kv = [&](int kt, int s) {
        __nv_bfloat16* base = sKV + s * (4 * FKV);
        const size_t kb0 = krow0 + (size_t)(kt * 64) * C_;
        for (int i = tid; i < 1024; i += 256) {
            int r = i >> 4, c8 = (i & 15) * 8;
            size_t go = kb0 + (size_t)r * C_ + c8;
            unsigned off = r * FST + c8;
            CP_ASYNC16(smem_u32(base + off),           g_kh + go);
            CP_ASYNC16(smem_u32(base + FKV + off),     g_kl + go);
            CP_ASYNC16(smem_u32(base + 2 * FKV + off), g_vh + go);
            CP_ASYNC16(smem_u32(base + 3 * FKV + off), g_vl + go);
        }
    };
    load_kv(0, 0);
    CP_COMMIT();
    CP_WAIT0();
    __syncthreads();

    // fragment addressing
    const int g  = lane >> 2;        // row group
    const int t4 = lane & 3;
    const int a_row = wid * 16 + (lane & 15);
    const int a_c8  = (lane >> 4) * 8;
    const int b_row = (lane & 7) + ((lane >> 4) << 3);
    const int b_c8  = ((lane >> 3) & 1) * 8;
    const int v_row = lane & 15;
    const int v_c8  = (lane >> 4) * 8;

    float m0 = -1e30f, m1 = -1e30f, l0 = 0.f, l1 = 0.f;
    float oacc[16][4];
    #pragma unroll
    for (int dt = 0; dt < 16; dt++)
        #pragma unroll
        for (int r = 0; r < 4; r++) oacc[dt][r] = 0.f;

    const float sc2 = 0.08838834764831845f * 1.4426950408889634f;  // scale*log2(e)
    const int nkt = 2 * qb + 2;

    for (int kt = 0; kt < nkt; kt++) {
        const int s = kt & 1;
        if (kt + 1 < nkt) { load_kv(kt + 1, s ^ 1); CP_COMMIT(); }

        __nv_bfloat16* Kh = sKV + s * (4 * FKV);
        __nv_bfloat16* Kl = Kh + FKV;
        __nv_bfloat16* Vh = Kh + 2 * FKV;
        __nv_bfloat16* Vl = Kh + 3 * FKV;

        // --- S = Q K^T (split x3) ---
        float sacc[8][4];
        #pragma unroll
        for (int nt = 0; nt < 8; nt++)
            #pragma unroll
            for (int r = 0; r < 4; r++) sacc[nt][r] = 0.f;

        #pragma unroll
        for (int k16 = 0; k16 < 8; k16++) {
            unsigned ah[4], al[4];
            ldmatrix_x4(ah, smem_u32(sQh + a_row * FST + k16 * 16 + a_c8));
            ldmatrix_x4(al, smem_u32(sQl + a_row * FST + k16 * 16 + a_c8));
            #pragma unroll
            for (int nt2 = 0; nt2 < 4; nt2++) {
                unsigned bh[4], bl[4];
                ldmatrix_x4(bh, smem_u32(Kh + (nt2 * 16 + b_row) * FST + k16 * 16 + b_c8));
                ldmatrix_x4(bl, smem_u32(Kl + (nt2 * 16 + b_row) * FST + k16 * 16 + b_c8));
                #pragma unroll
                for (int t = 0; t < 2; t++) {
                    mma_bf16(sacc[nt2 * 2 + t], ah, bh + 2 * t);
                    mma_bf16(sacc[nt2 * 2 + t], ah, bl + 2 * t);
                    mma_bf16(sacc[nt2 * 2 + t], al, bh + 2 * t);
                }
            }
        }

        // scale (base-2) + causal mask
        #pragma unroll
        for (int nt = 0; nt < 8; nt++)
            #pragma unroll
            for (int r = 0; r < 4; r++) sacc[nt][r] *= sc2;

        if (kt >= 2 * qb) {
            const int row0 = qb * 128 + wid * 16 + g;
            #pragma unroll
            for (int nt = 0; nt < 8; nt++) {
                const int col = kt * 64 + nt * 8 + 2 * t4;
                if (col     > row0)     sacc[nt][0] = -1e30f;
                if (col + 1 > row0)     sacc[nt][1] = -1e30f;
                if (col     > row0 + 8) sacc[nt][2] = -1e30f;
                if (col + 1 > row0 + 8) sacc[nt][3] = -1e30f;
            }
        }

        // --- online softmax (rows g, g+8; reduce over t4 lanes) ---
        float mx0 = -1e30f, mx1 = -1e30f;
        #pragma unroll
        for (int nt = 0; nt < 8; nt++) {
            mx0 = fmaxf(mx0, fmaxf(sacc[nt][0], sacc[nt][1]));
            mx1 = fmaxf(mx1, fmaxf(sacc[nt][2], sacc[nt][3]));
        }
        mx0 = fmaxf(mx0, __shfl_xor_sync(0xffffffffu, mx0, 1));
        mx0 = fmaxf(mx0, __shfl_xor_sync(0xffffffffu, mx0, 2));
        mx1 = fmaxf(mx1, __shfl_xor_sync(0xffffffffu, mx1, 1));
        mx1 = fmaxf(mx1, __shfl_xor_sync(0xffffffffu, mx1, 2));

        float mn0 = fmaxf(m0, mx0), mn1 = fmaxf(m1, mx1);
        float al0 = ex2(m0 - mn0), al1 = ex2(m1 - mn1);
        m0 = mn0; m1 = mn1;

        float rs0 = 0.f, rs1 = 0.f;
        #pragma unroll
        for (int nt = 0; nt < 8; nt++) {
            sacc[nt][0] = ex2(sacc[nt][0] - mn0);
            sacc[nt][1] = ex2(sacc[nt][1] - mn0);
            sacc[nt][2] = ex2(sacc[nt][2] - mn1);
            sacc[nt][3] = ex2(sacc[nt][3] - mn1);
            rs0 += sacc[nt][0] + sacc[nt][1];
            rs1 += sacc[nt][2] + sacc[nt][3];
        }
        rs0 += __shfl_xor_sync(0xffffffffu, rs0, 1);
        rs0 += __shfl_xor_sync(0xffffffffu, rs0, 2);
        rs1 += __shfl_xor_sync(0xffffffffu, rs1, 1);
        rs1 += __shfl_xor_sync(0xffffffffu, rs1, 2);
        l0 = l0 * al0 + rs0;
        l1 = l1 * al1 + rs1;

        #pragma unroll
        for (int dt = 0; dt < 16; dt++) {
            oacc[dt][0] *= al0; oacc[dt][1] *= al0;
            oacc[dt][2] *= al1; oacc[dt][3] *= al1;
        }

        // --- O += P V (split x3); P frags straight from S accumulators ---
        #pragma unroll
        for (int kt2 = 0; kt2 < 4; kt2++) {
            unsigned ph[4], pl[4];
            #pragma unroll
            for (int half = 0; half < 2; half++) {       // n-tiles 2kt2, 2kt2+1
                const float* sp = sacc[2 * kt2 + half];
                #pragma unroll
                for (int rr = 0; rr < 2; rr++) {         // (c0,c1) then (c2,c3)
                    float p0 = sp[2 * rr], p1 = sp[2 * rr + 1];
                    unsigned u0 = __float_as_uint(p0), u1 = __float_as_uint(p1);
                    ph[half * 2 + rr] = prmt_hi(u0, u1);
                    float r0 = p0 - __uint_as_float(u0 & 0xFFFF0000u);
                    float r1 = p1 - __uint_as_float(u1 & 0xFFFF0000u);
                    pl[half * 2 + rr] = cvt_bf16x2(r0, r1);
                }
            }
            #pragma unroll
            for (int dt2 = 0; dt2 < 8; dt2++) {
                unsigned vh[4], vl[4];
                ldmatrix_x4_trans(vh, smem_u32(Vh + (kt2 * 16 + v_row) * FST + dt2 * 16 + v_c8));
                ldmatrix_x4_trans(vl, smem_u32(Vl + (kt2 * 16 + v_row) * FST + dt2 * 16 + v_c8));
                mma_bf16(oacc[dt2 * 2],     ph, vh);
                mma_bf16(oacc[dt2 * 2],     ph, vl);
                mma_bf16(oacc[dt2 * 2],     pl, vh);
                mma_bf16(oacc[dt2 * 2 + 1], ph, vh + 2);
                mma_bf16(oacc[dt2 * 2 + 1], ph, vl + 2);
                mma_bf16(oacc[dt2 * 2 + 1], pl, vh + 2);
            }
        }

        if (kt + 1 < nkt) CP_WAIT0();
        __syncthreads();
    }

    // --- epilogue: O / l -> g_y (fp32) ---
    const float inv0 = 1.f / l0, inv1 = 1.f / l1;
    float* yb = g_y + (size_t)(b * T_ + qb * 128 + wid * 16) * C_ + h * HD_;
    #pragma unroll
    for (int dt = 0; dt < 16; dt++) {
        const int col = dt * 8 + 2 * t4;
        *(float2*)(yb + (size_t)g * C_ + col) =
            make_float2(oacc[dt][0] * inv0, oacc[dt][1] * inv0);
        *(float2*)(yb + (size_t)(g + 8) * C_ + col) =
            make_float2(oacc[dt][2] * inv1, oacc[dt][3] * inv1);
    }
}

// ---------------------------------------------------------------------------
// Launch
// ---------------------------------------------------------------------------
extern "C" void kernel_launch(void* const* d_in, const int* in_sizes, int n_in,
                              void* d_out, int out_size)
{
    (void)in_sizes; (void)n_in; (void)out_size;
    const float* x     = (const float*)d_in[0];
    const float* ve    = (const float*)d_in[1];
    const float* cosb  = (const float*)d_in[2];
    const float* sinb  = (const float*)d_in[3];
    const float* Wq    = (const float*)d_in[4];
    const float* Wk    = (const float*)d_in[5];
    const float* Wv    = (const float*)d_in[6];
    const float* Wgate = (const float*)d_in[7];
    const float* Wproj = (const float*)d_in[8];
    float* out = (float*)d_out;

    float *q, *k, *v, *y;
    cudaGetSymbolAddress((void**)&q, g_q);
    cudaGetSymbolAddress((void**)&k, g_k);
    cudaGetSymbolAddress((void**)&v, g_v);
    cudaGetSymbolAddress((void**)&y, g_y);
    __nv_bfloat16 *xh, *xl, *yh, *yl, *wth, *wtl;
    cudaGetSymbolAddress((void**)&xh, g_xh);
    cudaGetSymbolAddress((void**)&xl, g_xl);
    cudaGetSymbolAddress((void**)&yh, g_yh);
    cudaGetSymbolAddress((void**)&yl, g_yl);
    cudaGetSymbolAddress((void**)&wth, g_wth);
    cudaGetSymbolAddress((void**)&wtl, g_wtl);
    const size_t WSZ = (size_t)C_ * C_;

    convert_split<<<(M_*C_/4 + 255)/256, 256>>>(x, xh, xl, M_*C_/4);
    dim3 tgrid(C_/32, C_/32), tblk(32, 8);
    transpose_split<<<tgrid, tblk>>>(Wq,    wth + 0*WSZ, wtl + 0*WSZ, C_, C_);
    transpose_split<<<tgrid, tblk>>>(Wk,    wth + 1*WSZ, wtl + 1*WSZ, C_, C_);
    transpose_split<<<tgrid, tblk>>>(Wv,    wth + 2*WSZ, wtl + 2*WSZ, C_, C_);
    transpose_split<<<tgrid, tblk>>>(Wproj, wth + 3*WSZ, wtl + 3*WSZ, C_, C_);

    const int gemm_smem = 2 * STAGE_E * (int)sizeof(__nv_bfloat16);
    cudaFuncSetAttribute(gemm_mma_bf16x3, cudaFuncAttributeMaxDynamicSharedMemorySize, gemm_smem);
    dim3 ggrid(C_/128, M_/128);
    gemm_mma_bf16x3<<<ggrid, 256, gemm_smem>>>(xh, xl, wth + 0*WSZ, wtl + 0*WSZ, q, C_, C_);
    gemm_mma_bf16x3<<<ggrid, 256, gemm_smem>>>(xh, xl, wth + 1*WSZ, wtl + 1*WSZ, k, C_, C_);
    gemm_mma_bf16x3<<<ggrid, 256, gemm_smem>>>(xh, xl, wth + 2*WSZ, wtl + 2*WSZ, v, C_, C_);

    prep_kernel<<<M_, 512>>>(x, ve, cosb, sinb, Wgate);

    const int fsmem = (2 * FQ + 8 * FKV) * (int)sizeof(__nv_bfloat16);  // 208,896 B
    cudaFuncSetAttribute(flash_mma, cudaFuncAttributeMaxDynamicSharedMemorySize, fsmem);
    flash_mma<<<dim3(T_/128, NH_, B_), 256, fsmem>>>();

    convert_split<<<(M_*C_/4 + 255)/256, 256>>>(y, yh, yl, M_*C_/4);
    gemm_mma_bf16x3<<<ggrid, 256, gemm_smem>>>(yh, yl, wth + 3*WSZ, wtl + 3*WSZ, out, C_, C_);
}

// round 5
// speedup vs baseline: 2.9955x; 1.1371x over previous
#include <cuda_runtime.h>
#include <cuda_bf16.h>
#include <math.h>

// Problem constants
#define B_       2
#define T_       2048
#define C_       2048
#define NH_      16
#define HD_      128
#define GATE_CH_ 32
#define M_       (B_*T_)   // 4096 rows

// ---------------------------------------------------------------------------
// Scratch (device globals: allocation-free per harness rules)
// ---------------------------------------------------------------------------
__device__ float g_q[(size_t)M_*C_];
__device__ float g_k[(size_t)M_*C_];
__device__ float g_v[(size_t)M_*C_];
__device__ float g_y[(size_t)M_*C_];

__device__ __nv_bfloat16 g_xh[(size_t)M_*C_];
__device__ __nv_bfloat16 g_xl[(size_t)M_*C_];
__device__ __nv_bfloat16 g_yh[(size_t)M_*C_];
__device__ __nv_bfloat16 g_yl[(size_t)M_*C_];
// attention operand splits
__device__ __nv_bfloat16 g_qh[(size_t)M_*C_];
__device__ __nv_bfloat16 g_ql[(size_t)M_*C_];
__device__ __nv_bfloat16 g_kh[(size_t)M_*C_];
__device__ __nv_bfloat16 g_kl[(size_t)M_*C_];
__device__ __nv_bfloat16 g_vh[(size_t)M_*C_];
__device__ __nv_bfloat16 g_vl[(size_t)M_*C_];
// transposed split weights [N][K] for Wq, Wk, Wv, Wproj
__device__ __nv_bfloat16 g_wth[4][(size_t)C_*C_];
__device__ __nv_bfloat16 g_wtl[4][(size_t)C_*C_];

// ---------------------------------------------------------------------------
// PTX helpers (sm_103 baseline-safe: mma.sync + ldmatrix + cp.async)
// ---------------------------------------------------------------------------
__device__ __forceinline__ unsigned smem_u32(const void* p) {
    unsigned a;
    asm("{ .reg .u64 t; cvta.to.shared.u64 t, %1; cvt.u32.u64 %0, t; }"
        : "=r"(a) : "l"(p));
    return a;
}

#define CP_ASYNC16(dst_u32, src_ptr) \
    asm volatile("cp.async.cg.shared.global [%0], [%1], 16;" \
                 :: "r"(dst_u32), "l"(src_ptr))
#define CP_COMMIT() asm volatile("cp.async.commit_group;" ::: "memory")
#define CP_WAIT0()  asm volatile("cp.async.wait_group 0;" ::: "memory")
#define CP_WAIT1()  asm volatile("cp.async.wait_group 1;" ::: "memory")

__device__ __forceinline__ void ldmatrix_x4(unsigned* r, unsigned addr) {
    asm volatile("ldmatrix.sync.aligned.m8n8.x4.shared.b16 {%0,%1,%2,%3}, [%4];"
                 : "=r"(r[0]), "=r"(r[1]), "=r"(r[2]), "=r"(r[3]) : "r"(addr));
}
__device__ __forceinline__ void ldmatrix_x4_trans(unsigned* r, unsigned addr) {
    asm volatile("ldmatrix.sync.aligned.m8n8.x4.trans.shared.b16 {%0,%1,%2,%3}, [%4];"
                 : "=r"(r[0]), "=r"(r[1]), "=r"(r[2]), "=r"(r[3]) : "r"(addr));
}
__device__ __forceinline__ void mma_bf16(float* c, const unsigned* a, const unsigned* b) {
    asm volatile(
        "mma.sync.aligned.m16n8k16.row.col.f32.bf16.bf16.f32 "
        "{%0,%1,%2,%3}, {%4,%5,%6,%7}, {%8,%9}, {%0,%1,%2,%3};"
        : "+f"(c[0]), "+f"(c[1]), "+f"(c[2]), "+f"(c[3])
        : "r"(a[0]), "r"(a[1]), "r"(a[2]), "r"(a[3]), "r"(b[0]), "r"(b[1]));
}
__device__ __forceinline__ unsigned prmt_hi(unsigned a, unsigned b) {
    unsigned d;
    asm("prmt.b32 %0, %1, %2, 0x7632;" : "=r"(d) : "r"(a), "r"(b));
    return d;
}
__device__ __forceinline__ unsigned cvt_bf16x2(float lo, float hi) {
    unsigned d;
    asm("cvt.rn.bf16x2.f32 %0, %1, %2;" : "=r"(d) : "f"(hi), "f"(lo));
    return d;
}
__device__ __forceinline__ float ex2(float x) {
    float y;
    asm("ex2.approx.f32 %0, %1;" : "=f"(y) : "f"(x));
    return y;
}

// ---------------------------------------------------------------------------
// convert_split: fp32 -> bf16 hi/lo (same layout)
// ---------------------------------------------------------------------------
__global__ __launch_bounds__(256) void convert_split(
    const float* __restrict__ in, __nv_bfloat16* __restrict__ h,
    __nv_bfloat16* __restrict__ l, int n4)
{
    int i = blockIdx.x * blockDim.x + threadIdx.x;
    if (i >= n4) return;
    float4 v = ((const float4*)in)[i];
    __nv_bfloat16 h0 = __float2bfloat16(v.x);
    __nv_bfloat16 h1 = __float2bfloat16(v.y);
    __nv_bfloat16 h2 = __float2bfloat16(v.z);
    __nv_bfloat16 h3 = __float2bfloat16(v.w);
    __nv_bfloat16 l0 = __float2bfloat16(v.x - __bfloat162float(h0));
    __nv_bfloat16 l1 = __float2bfloat16(v.y - __bfloat162float(h1));
    __nv_bfloat16 l2 = __float2bfloat16(v.z - __bfloat162float(h2));
    __nv_bfloat16 l3 = __float2bfloat16(v.w - __bfloat162float(h3));
    __nv_bfloat162* hp = (__nv_bfloat162*)(h + (size_t)i * 4);
    __nv_bfloat162* lp = (__nv_bfloat162*)(l + (size_t)i * 4);
    hp[0] = __nv_bfloat162(h0, h1); hp[1] = __nv_bfloat162(h2, h3);
    lp[0] = __nv_bfloat162(l0, l1); lp[1] = __nv_bfloat162(l2, l3);
}

// ---------------------------------------------------------------------------
// transpose_split: W[K][N] fp32 -> Wt_h/Wt_l[N][K] bf16
// ---------------------------------------------------------------------------
__global__ __launch_bounds__(256) void transpose_split(
    const float* __restrict__ W, __nv_bfloat16* __restrict__ th,
    __nv_bfloat16* __restrict__ tl, int K, int N)
{
    __shared__ float tile[32][33];
    int k0 = blockIdx.y * 32, n0 = blockIdx.x * 32;
    int tx = threadIdx.x, ty = threadIdx.y;  // block (32, 8)
    #pragma unroll
    for (int r = 0; r < 4; r++)
        tile[ty + 8 * r][tx] = W[(size_t)(k0 + ty + 8 * r) * N + n0 + tx];
    __syncthreads();
    #pragma unroll
    for (int r = 0; r < 4; r++) {
        float v = tile[tx][ty + 8 * r];
        __nv_bfloat16 h = __float2bfloat16(v);
        __nv_bfloat16 l = __float2bfloat16(v - __bfloat162float(h));
        size_t o = (size_t)(n0 + ty + 8 * r) * K + k0 + tx;
        th[o] = h; tl[o] = l;
    }
}

// ---------------------------------------------------------------------------
// HMMA split-bf16 GEMM body: C[M][N] = A[M][K] * B[K][N]
// 128x128 CTA tile, 8 warps (4x2), k-chunk 32, cp.async double-buffered.
// Term-major MMA ordering for ILP. Target 2 CTAs/SM.
// ---------------------------------------------------------------------------
#define KC        32
#define AS_STRIDE 40                        // bf16 elems per smem row (80B)
#define TILE_E    (128 * AS_STRIDE)         // elems per matrix tile
#define STAGE_E   (4 * TILE_E)              // Ah | Al | Bh | Bl

__device__ __forceinline__ void gemm_body(
    const __nv_bfloat16* __restrict__ Ah, const __nv_bfloat16* __restrict__ Al,
    const __nv_bfloat16* __restrict__ Bh, const __nv_bfloat16* __restrict__ Bl,
    float* __restrict__ Cm, int Ncols, int K, __nv_bfloat16* smb)
{
    const int tid = threadIdx.x, wid = tid >> 5, lane = tid & 31;
    const int m0 = blockIdx.y * 128, n0 = blockIdx.x * 128;
    const int NCH = K / KC;
    const int wm = wid & 3;
    const int wn = wid >> 2;

    auto load_stage = [&](int c, int s) {
        const int k0 = c * KC;
        __nv_bfloat16* base = smb + s * STAGE_E;
        #pragma unroll
        for (int i = 0; i < 2; i++) {
            int cidx = tid + i * 256;
            int row  = cidx >> 2;
            int col8 = (cidx & 3) * 8;
            unsigned so = smem_u32(base + row * AS_STRIDE + col8);
            size_t ga = (size_t)(m0 + row) * K + k0 + col8;
            size_t gb = (size_t)(n0 + row) * K + k0 + col8;
            CP_ASYNC16(so,              Ah + ga);
            CP_ASYNC16(so + TILE_E * 2, Al + ga);
            CP_ASYNC16(so + TILE_E * 4, Bh + gb);
            CP_ASYNC16(so + TILE_E * 6, Bl + gb);
        }
    };

    float acc[2][8][4];
    #pragma unroll
    for (int mt = 0; mt < 2; mt++)
        #pragma unroll
        for (int nt = 0; nt < 8; nt++)
            #pragma unroll
            for (int r = 0; r < 4; r++) acc[mt][nt][r] = 0.f;

    load_stage(0, 0);
    CP_COMMIT();

    const int a_row = wm * 32 + (lane & 15);
    const int a_k8  = (lane >> 4) * 8;
    const int b_r   = lane & 7;
    const int b_grp = lane >> 3;
    const int b_row = wn * 64 + (b_grp >> 1) * 8 + b_r;
    const int b_k8  = (b_grp & 1) * 8;

    for (int c = 0; c < NCH; c++) {
        if (c + 1 < NCH) {
            load_stage(c + 1, (c + 1) & 1);
            CP_COMMIT();
            CP_WAIT1();
        } else {
            CP_WAIT0();
        }
        __syncthreads();

        const __nv_bfloat16* st = smb + (c & 1) * STAGE_E;
        const __nv_bfloat16* sAh = st;
        const __nv_bfloat16* sAl = st + TILE_E;
        const __nv_bfloat16* sBh = st + 2 * TILE_E;
        const __nv_bfloat16* sBl = st + 3 * TILE_E;

        #pragma unroll
        for (int k16 = 0; k16 < 2; k16++) {
            const int kb = k16 * 16;
            unsigned ah[2][4], al[2][4];
            #pragma unroll
            for (int mt = 0; mt < 2; mt++) {
                ldmatrix_x4(ah[mt], smem_u32(sAh + (a_row + mt * 16) * AS_STRIDE + kb + a_k8));
                ldmatrix_x4(al[mt], smem_u32(sAl + (a_row + mt * 16) * AS_STRIDE + kb + a_k8));
            }
            #pragma unroll
            for (int j = 0; j < 4; j++) {
                unsigned bh[4], bl[4];
                ldmatrix_x4(bh, smem_u32(sBh + (b_row + j * 16) * AS_STRIDE + kb + b_k8));
                ldmatrix_x4(bl, smem_u32(sBl + (b_row + j * 16) * AS_STRIDE + kb + b_k8));
                // term-major: 4 independent MMAs per term
                #pragma unroll
                for (int t = 0; t < 2; t++)
                    #pragma unroll
                    for (int mt = 0; mt < 2; mt++)
                        mma_bf16(acc[mt][j * 2 + t], ah[mt], bh + t * 2);
                #pragma unroll
                for (int t = 0; t < 2; t++)
                    #pragma unroll
                    for (int mt = 0; mt < 2; mt++)
                        mma_bf16(acc[mt][j * 2 + t], ah[mt], bl + t * 2);
                #pragma unroll
                for (int t = 0; t < 2; t++)
                    #pragma unroll
                    for (int mt = 0; mt < 2; mt++)
                        mma_bf16(acc[mt][j * 2 + t], al[mt], bh + t * 2);
            }
        }
        __syncthreads();
    }

    const int cg = lane >> 2, ct = lane & 3;
    #pragma unroll
    for (int mt = 0; mt < 2; mt++) {
        const int row = m0 + wm * 32 + mt * 16 + cg;
        #pragma unroll
        for (int nt = 0; nt < 8; nt++) {
            const int col = n0 + wn * 64 + nt * 8 + ct * 2;
            float2 w0 = make_float2(acc[mt][nt][0], acc[mt][nt][1]);
            float2 w1 = make_float2(acc[mt][nt][2], acc[mt][nt][3]);
            *(float2*)(Cm + (size_t)row * Ncols + col)       = w0;
            *(float2*)(Cm + (size_t)(row + 8) * Ncols + col) = w1;
        }
    }
}

// fused QKV GEMM: blockIdx.z selects weight/output
__global__ __launch_bounds__(256, 2) void gemm_qkv(
    const __nv_bfloat16* __restrict__ Ah, const __nv_bfloat16* __restrict__ Al,
    float* __restrict__ q, float* __restrict__ k, float* __restrict__ v)
{
    extern __shared__ __nv_bfloat16 smb[];
    const int z = blockIdx.z;
    const size_t WSZ = (size_t)C_ * C_;
    const __nv_bfloat16* Bh = g_wth[0] + z * WSZ;
    const __nv_bfloat16* Bl = g_wtl[0] + z * WSZ;
    float* Cm = (z == 0) ? q : (z == 1) ? k : v;
    gemm_body(Ah, Al, Bh, Bl, Cm, C_, C_, smb);
}

__global__ __launch_bounds__(256, 2) void gemm_one(
    const __nv_bfloat16* __restrict__ Ah, const __nv_bfloat16* __restrict__ Al,
    const __nv_bfloat16* __restrict__ Bh, const __nv_bfloat16* __restrict__ Bl,
    float* __restrict__ Cm)
{
    extern __shared__ __nv_bfloat16 smb[];
    gemm_body(Ah, Al, Bh, Bl, Cm, C_, C_, smb);
}

// ---------------------------------------------------------------------------
// Prep: v += gate*ve ; q,k <- rmsnorm(rotary(.)), emit bf16 hi/lo splits
// ---------------------------------------------------------------------------
__device__ __forceinline__ float warp_sum(float v) {
    #pragma unroll
    for (int d = 16; d >= 1; d >>= 1) v += __shfl_xor_sync(0xffffffffu, v, d);
    return v;
}

__device__ __forceinline__ void split_store(
    float v, __nv_bfloat16* __restrict__ h, __nv_bfloat16* __restrict__ l, size_t idx)
{
    __nv_bfloat16 hh = __float2bfloat16(v);
    h[idx] = hh;
    l[idx] = __float2bfloat16(v - __bfloat162float(hh));
}

__device__ __forceinline__ void rope_rms_split(
    const float* __restrict__ src, const float* cr, const float* sr, int lane,
    __nv_bfloat16* __restrict__ dh, __nv_bfloat16* __restrict__ dl, size_t base)
{
    const int d0 = lane, d1 = lane + 32;
    float x1a = src[d0],      x2a = src[d0 + 64];
    float x1b = src[d1],      x2b = src[d1 + 64];
    float ca = cr[d0], sa = sr[d0], cb = cr[d1], sb = sr[d1];
    float o1a =  x1a * ca + x2a * sa;
    float o2a = -x1a * sa + x2a * ca;
    float o1b =  x1b * cb + x2b * sb;
    float o2b = -x1b * sb + x2b * cb;
    float ss = warp_sum(o1a*o1a + o2a*o2a + o1b*o1b + o2b*o2b);
    float r = rsqrtf(ss * (1.f / 128.f) + 1e-6f);
    split_store(o1a * r, dh, dl, base + d0);
    split_store(o2a * r, dh, dl, base + d0 + 64);
    split_store(o1b * r, dh, dl, base + d1);
    split_store(o2b * r, dh, dl, base + d1 + 64);
}

__global__ __launch_bounds__(512) void prep_kernel(
    const float* __restrict__ x, const float* __restrict__ ve,
    const float* __restrict__ cosb, const float* __restrict__ sinb,
    const float* __restrict__ Wgate)
{
    const int bt   = blockIdx.x;
    const int t    = bt & (T_ - 1);
    const int h    = threadIdx.x >> 5;
    const int lane = threadIdx.x & 31;

    const float* xr = x + (size_t)bt * C_;
    float sacc = warp_sum(xr[lane] * Wgate[lane * NH_ + h]);
    float g = 2.f / (1.f + __expf(-sacc));

    const size_t base = (size_t)bt * C_ + h * HD_;
    #pragma unroll
    for (int i = 0; i < 4; i++) {
        int d = lane + i * 32;
        float vv = g_v[base + d] + g * ve[base + d];
        split_store(vv, g_vh, g_vl, base + d);
    }

    const float* cr = cosb + (size_t)t * 64;
    const float* sr = sinb + (size_t)t * 64;
    rope_rms_split(g_q + base, cr, sr, lane, g_qh, g_ql, base);
    rope_rms_split(g_k + base, cr, sr, lane, g_kh, g_kl, base);
}

// ---------------------------------------------------------------------------
// HMMA flash attention (causal, split-bf16). BM=128, BN=64, HD=128.
// 256 threads = 8 warps, each warp owns 16 query rows. Term-major MMA order.
// ---------------------------------------------------------------------------
#define FST    136                 // smem row stride (bf16 elems), 272B
#define FKV    (64 * FST)          // one 64-row tile
#define FQ     (128 * FST)         // one 128-row tile

__global__ __launch_bounds__(256) void flash_mma()
{
    extern __shared__ __nv_bfloat16 fsm[];
    __nv_bfloat16* sQh = fsm;              // [128][FST]
    __nv_bfloat16* sQl = sQh + FQ;
    __nv_bfloat16* sKV = sQl + FQ;         // 2 stages x (Kh|Kl|Vh|Vl)[64][FST]

    const int tid = threadIdx.x, wid = tid >> 5, lane = tid & 31;
    const int qb = gridDim.x - 1 - blockIdx.x;   // big tiles first
    const int h  = blockIdx.y;
    const int b  = blockIdx.z;

    const size_t qrow0 = (size_t)(b * T_ + qb * 128) * C_ + h * HD_;
    const size_t krow0 = (size_t)(b * T_) * C_ + h * HD_;

    for (int i = tid; i < 2048; i += 256) {
        int r = i >> 4, c8 = (i & 15) * 8;
        size_t go = qrow0 + (size_t)r * C_ + c8;
        CP_ASYNC16(smem_u32(sQh + r * FST + c8), g_qh + go);
        CP_ASYNC16(smem_u32(sQl + r * FST + c8), g_ql + go);
    }
    auto load_kv = [&](int kt, int s) {
        __nv_bfloat16* base = sKV + s * (4 * FKV);
        const size_t kb0 = krow0 + (size_t)(kt * 64) * C_;
        for (int i = tid; i < 1024; i += 256) {
            int r = i >> 4, c8 = (i & 15) * 8;
            size_t go = kb0 + (size_t)r * C_ + c8;
            unsigned off = r * FST + c8;
            CP_ASYNC16(smem_u32(base + off),           g_kh + go);
            CP_ASYNC16(smem_u32(base + FKV + off),     g_kl + go);
            CP_ASYNC16(smem_u32(base + 2 * FKV + off), g_vh + go);
            CP_ASYNC16(smem_u32(base + 3 * FKV + off), g_vl + go);
        }
    };
    load_kv(0, 0);
    CP_COMMIT();
    CP_WAIT0();
    __syncthreads();

    const int g  = lane >> 2;
    const int t4 = lane & 3;
    const int a_row = wid * 16 + (lane & 15);
    const int a_c8  = (lane >> 4) * 8;
    const int b_row = (lane & 7) + ((lane >> 4) << 3);
    const int b_c8  = ((lane >> 3) & 1) * 8;
    const int v_row = lane & 15;
    const int v_c8  = (lane >> 4) * 8;

    float m0 = -1e30f, m1 = -1e30f, l0 = 0.f, l1 = 0.f;
    float oacc[16][4];
    #pragma unroll
    for (int dt = 0; dt < 16; dt++)
        #pragma unroll
        for (int r = 0; r < 4; r++) oacc[dt][r] = 0.f;

    const float sc2 = 0.08838834764831845f * 1.4426950408889634f;  // scale*log2(e)
    const int nkt = 2 * qb + 2;

    for (int kt = 0; kt < nkt; kt++) {
        const int s = kt & 1;
        if (kt + 1 < nkt) { load_kv(kt + 1, s ^ 1); CP_COMMIT(); }

        __nv_bfloat16* Kh = sKV + s * (4 * FKV);
        __nv_bfloat16* Kl = Kh + FKV;
        __nv_bfloat16* Vh = Kh + 2 * FKV;
        __nv_bfloat16* Vl = Kh + 3 * FKV;

        // --- S = Q K^T (split x3, term-major: 8 independent accs/term) ---
        float sacc[8][4];
        #pragma unroll
        for (int nt = 0; nt < 8; nt++)
            #pragma unroll
            for (int r = 0; r < 4; r++) sacc[nt][r] = 0.f;

        #pragma unroll
        for (int k16 = 0; k16 < 8; k16++) {
            unsigned ah[4], al[4];
            ldmatrix_x4(ah, smem_u32(sQh + a_row * FST + k16 * 16 + a_c8));
            ldmatrix_x4(al, smem_u32(sQl + a_row * FST + k16 * 16 + a_c8));
            unsigned bh[4][4], bl[4][4];
            #pragma unroll
            for (int nt2 = 0; nt2 < 4; nt2++) {
                ldmatrix_x4(bh[nt2], smem_u32(Kh + (nt2 * 16 + b_row) * FST + k16 * 16 + b_c8));
                ldmatrix_x4(bl[nt2], smem_u32(Kl + (nt2 * 16 + b_row) * FST + k16 * 16 + b_c8));
            }
            #pragma unroll
            for (int nt2 = 0; nt2 < 4; nt2++)
                #pragma unroll
                for (int t = 0; t < 2; t++)
                    mma_bf16(sacc[nt2 * 2 + t], ah, bh[nt2] + 2 * t);
            #pragma unroll
            for (int nt2 = 0; nt2 < 4; nt2++)
                #pragma unroll
                for (int t = 0; t < 2; t++)
                    mma_bf16(sacc[nt2 * 2 + t], ah, bl[nt2] + 2 * t);
            #pragma unroll
            for (int nt2 = 0; nt2 < 4; nt2++)
                #pragma unroll
                for (int t = 0; t < 2; t++)
                    mma_bf16(sacc[nt2 * 2 + t], al, bh[nt2] + 2 * t);
        }

        #pragma unroll
        for (int nt = 0; nt < 8; nt++)
            #pragma unroll
            for (int r = 0; r < 4; r++) sacc[nt][r] *= sc2;

        if (kt >= 2 * qb) {
            const int row0 = qb * 128 + wid * 16 + g;
            #pragma unroll
            for (int nt = 0; nt < 8; nt++) {
                const int col = kt * 64 + nt * 8 + 2 * t4;
                if (col     > row0)     sacc[nt][0] = -1e30f;
                if (col + 1 > row0)     sacc[nt][1] = -1e30f;
                if (col     > row0 + 8) sacc[nt][2] = -1e30f;
                if (col + 1 > row0 + 8) sacc[nt][3] = -1e30f;
            }
        }

        // --- online softmax ---
        float mx0 = -1e30f, mx1 = -1e30f;
        #pragma unroll
        for (int nt = 0; nt < 8; nt++) {
            mx0 = fmaxf(mx0, fmaxf(sacc[nt][0], sacc[nt][1]));
            mx1 = fmaxf(mx1, fmaxf(sacc[nt][2], sacc[nt][3]));
        }
        mx0 = fmaxf(mx0, __shfl_xor_sync(0xffffffffu, mx0, 1));
        mx0 = fmaxf(mx0, __shfl_xor_sync(0xffffffffu, mx0, 2));
        mx1 = fmaxf(mx1, __shfl_xor_sync(0xffffffffu, mx1, 1));
        mx1 = fmaxf(mx1, __shfl_xor_sync(0xffffffffu, mx1, 2));

        float mn0 = fmaxf(m0, mx0), mn1 = fmaxf(m1, mx1);
        float al0 = ex2(m0 - mn0), al1 = ex2(m1 - mn1);
        m0 = mn0; m1 = mn1;

        float rs0 = 0.f, rs1 = 0.f;
        #pragma unroll
        for (int nt = 0; nt < 8; nt++) {
            sacc[nt][0] = ex2(sacc[nt][0] - mn0);
            sacc[nt][1] = ex2(sacc[nt][1] - mn0);
            sacc[nt][2] = ex2(sacc[nt][2] - mn1);
            sacc[nt][3] = ex2(sacc[nt][3] - mn1);
            rs0 += sacc[nt][0] + sacc[nt][1];
            rs1 += sacc[nt][2] + sacc[nt][3];
        }
        rs0 += __shfl_xor_sync(0xffffffffu, rs0, 1);
        rs0 += __shfl_xor_sync(0xffffffffu, rs0, 2);
        rs1 += __shfl_xor_sync(0xffffffffu, rs1, 1);
        rs1 += __shfl_xor_sync(0xffffffffu, rs1, 2);
        l0 = l0 * al0 + rs0;
        l1 = l1 * al1 + rs1;

        #pragma unroll
        for (int dt = 0; dt < 16; dt++) {
            oacc[dt][0] *= al0; oacc[dt][1] *= al0;
            oacc[dt][2] *= al1; oacc[dt][3] *= al1;
        }

        // --- O += P V (split x3, term-major over dt2 pairs) ---
        #pragma unroll
        for (int kt2 = 0; kt2 < 4; kt2++) {
            unsigned ph[4], pl[4];
            #pragma unroll
            for (int half = 0; half < 2; half++) {
                const float* sp = sacc[2 * kt2 + half];
                #pragma unroll
                for (int rr = 0; rr < 2; rr++) {
                    float p0 = sp[2 * rr], p1 = sp[2 * rr + 1];
                    unsigned u0 = __float_as_uint(p0), u1 = __float_as_uint(p1);
                    ph[half * 2 + rr] = prmt_hi(u0, u1);
                    float r0 = p0 - __uint_as_float(u0 & 0xFFFF0000u);
                    float r1 = p1 - __uint_as_float(u1 & 0xFFFF0000u);
                    pl[half * 2 + rr] = cvt_bf16x2(r0, r1);
                }
            }
            #pragma unroll
            for (int dp = 0; dp < 4; dp++) {         // pairs of dt2
                unsigned vh[2][4], vl[2][4];
                #pragma unroll
                for (int d = 0; d < 2; d++) {
                    const int dt2 = dp * 2 + d;
                    ldmatrix_x4_trans(vh[d], smem_u32(Vh + (kt2 * 16 + v_row) * FST + dt2 * 16 + v_c8));
                    ldmatrix_x4_trans(vl[d], smem_u32(Vl + (kt2 * 16 + v_row) * FST + dt2 * 16 + v_c8));
                }
                // term-major: 4 independent accs per term
                #pragma unroll
                for (int d = 0; d < 2; d++)
                    #pragma unroll
                    for (int n = 0; n < 2; n++)
                        mma_bf16(oacc[(dp * 2 + d) * 2 + n], ph, vh[d] + 2 * n);
                #pragma unroll
                for (int d = 0; d < 2; d++)
                    #pragma unroll
                    for (int n = 0; n < 2; n++)
                        mma_bf16(oacc[(dp * 2 + d) * 2 + n], ph, vl[d] + 2 * n);
                #pragma unroll
                for (int d = 0; d < 2; d++)
                    #pragma unroll
                    for (int n = 0; n < 2; n++)
                        mma_bf16(oacc[(dp * 2 + d) * 2 + n], pl, vh[d] + 2 * n);
            }
        }

        if (kt + 1 < nkt) CP_WAIT0();
        __syncthreads();
    }

    const float inv0 = 1.f / l0, inv1 = 1.f / l1;
    float* yb = g_y + (size_t)(b * T_ + qb * 128 + wid * 16) * C_ + h * HD_;
    #pragma unroll
    for (int dt = 0; dt < 16; dt++) {
        const int col = dt * 8 + 2 * t4;
        *(float2*)(yb + (size_t)g * C_ + col) =
            make_float2(oacc[dt][0] * inv0, oacc[dt][1] * inv0);
        *(float2*)(yb + (size_t)(g + 8) * C_ + col) =
            make_float2(oacc[dt][2] * inv1, oacc[dt][3] * inv1);
    }
}

// ---------------------------------------------------------------------------
// Launch
// ---------------------------------------------------------------------------
extern "C" void kernel_launch(void* const* d_in, const int* in_sizes, int n_in,
                              void* d_out, int out_size)
{
    (void)in_sizes; (void)n_in; (void)out_size;
    const float* x     = (const float*)d_in[0];
    const float* ve    = (const float*)d_in[1];
    const float* cosb  = (const float*)d_in[2];
    const float* sinb  = (const float*)d_in[3];
    const float* Wq    = (const float*)d_in[4];
    const float* Wk    = (const float*)d_in[5];
    const float* Wv    = (const float*)d_in[6];
    const float* Wgate = (const float*)d_in[7];
    const float* Wproj = (const float*)d_in[8];
    float* out = (float*)d_out;

    float *q, *k, *v, *y;
    cudaGetSymbolAddress((void**)&q, g_q);
    cudaGetSymbolAddress((void**)&k, g_k);
    cudaGetSymbolAddress((void**)&v, g_v);
    cudaGetSymbolAddress((void**)&y, g_y);
    __nv_bfloat16 *xh, *xl, *yh, *yl, *wth, *wtl;
    cudaGetSymbolAddress((void**)&xh, g_xh);
    cudaGetSymbolAddress((void**)&xl, g_xl);
    cudaGetSymbolAddress((void**)&yh, g_yh);
    cudaGetSymbolAddress((void**)&yl, g_yl);
    cudaGetSymbolAddress((void**)&wth, g_wth);
    cudaGetSymbolAddress((void**)&wtl, g_wtl);
    const size_t WSZ = (size_t)C_ * C_;

    convert_split<<<(M_*C_/4 + 255)/256, 256>>>(x, xh, xl, M_*C_/4);
    dim3 tgrid(C_/32, C_/32), tblk(32, 8);
    transpose_split<<<tgrid, tblk>>>(Wq,    wth + 0*WSZ, wtl + 0*WSZ, C_, C_);
    transpose_split<<<tgrid, tblk>>>(Wk,    wth + 1*WSZ, wtl + 1*WSZ, C_, C_);
    transpose_split<<<tgrid, tblk>>>(Wv,    wth + 2*WSZ, wtl + 2*WSZ, C_, C_);
    transpose_split<<<tgrid, tblk>>>(Wproj, wth + 3*WSZ, wtl + 3*WSZ, C_, C_);

    const int gemm_smem = 2 * STAGE_E * (int)sizeof(__nv_bfloat16);  // 81920 B
    cudaFuncSetAttribute(gemm_qkv, cudaFuncAttributeMaxDynamicSharedMemorySize, gemm_smem);
    cudaFuncSetAttribute(gemm_one, cudaFuncAttributeMaxDynamicSharedMemorySize, gemm_smem);
    gemm_qkv<<<dim3(C_/128, M_/128, 3), 256, gemm_smem>>>(xh, xl, q, k, v);

    prep_kernel<<<M_, 512>>>(x, ve, cosb, sinb, Wgate);

    const int fsmem = (2 * FQ + 8 * FKV) * (int)sizeof(__nv_bfloat16);  // 208,896 B
    cudaFuncSetAttribute(flash_mma, cudaFuncAttributeMaxDynamicSharedMemorySize, fsmem);
    flash_mma<<<dim3(T_/128, NH_, B_), 256, fsmem>>>();

    convert_split<<<(M_*C_/4 + 255)/256, 256>>>(y, yh, yl, M_*C_/4);
    gemm_one<<<dim3(C_/128, M_/128), 256, gemm_smem>>>(yh, yl, wth + 3*WSZ, wtl + 3*WSZ, out);
}

// round 7
// speedup vs baseline: 7.0489x; 2.3532x over previous
#include <cuda_runtime.h>
#include <cuda_fp16.h>
#include <math.h>

// Problem constants
#define B_       2
#define T_       2048
#define C_       2048
#define NH_      16
#define HD_      128
#define GATE_CH_ 32
#define M_       (B_*T_)   // 4096 rows

// ---------------------------------------------------------------------------
// Scratch (device globals: allocation-free per harness rules)
// ---------------------------------------------------------------------------
__device__ float g_q[(size_t)M_*C_];
__device__ float g_k[(size_t)M_*C_];
__device__ float g_v[(size_t)M_*C_];

__device__ __half g_xf[(size_t)M_*C_];
__device__ __half g_yf[(size_t)M_*C_];
__device__ __half g_qf[(size_t)M_*C_];
__device__ __half g_kf[(size_t)M_*C_];
__device__ __half g_vf[(size_t)M_*C_];
__device__ __half g_wt[4][(size_t)C_*C_];   // transposed [N][K] Wq,Wk,Wv,Wproj

// ---------------------------------------------------------------------------
// PTX helpers
// ---------------------------------------------------------------------------
__device__ __forceinline__ unsigned smem_u32(const void* p) {
    unsigned a;
    asm("{ .reg .u64 t; cvta.to.shared.u64 t, %1; cvt.u32.u64 %0, t; }"
        : "=r"(a) : "l"(p));
    return a;
}

#define CP_ASYNC16(dst_u32, src_ptr) \
    asm volatile("cp.async.cg.shared.global [%0], [%1], 16;" \
                 :: "r"(dst_u32), "l"(src_ptr))
#define CP_COMMIT() asm volatile("cp.async.commit_group;" ::: "memory")
#define CP_WAIT0()  asm volatile("cp.async.wait_group 0;" ::: "memory")
#define CP_WAIT1()  asm volatile("cp.async.wait_group 1;" ::: "memory")

__device__ __forceinline__ void ldmatrix_x4(unsigned* r, unsigned addr) {
    asm volatile("ldmatrix.sync.aligned.m8n8.x4.shared.b16 {%0,%1,%2,%3}, [%4];"
                 : "=r"(r[0]), "=r"(r[1]), "=r"(r[2]), "=r"(r[3]) : "r"(addr));
}
__device__ __forceinline__ void ldmatrix_x4_trans(unsigned* r, unsigned addr) {
    asm volatile("ldmatrix.sync.aligned.m8n8.x4.trans.shared.b16 {%0,%1,%2,%3}, [%4];"
                 : "=r"(r[0]), "=r"(r[1]), "=r"(r[2]), "=r"(r[3]) : "r"(addr));
}
__device__ __forceinline__ void mma_f16(float* c, const unsigned* a, const unsigned* b) {
    asm volatile(
        "mma.sync.aligned.m16n8k16.row.col.f32.f16.f16.f32 "
        "{%0,%1,%2,%3}, {%4,%5,%6,%7}, {%8,%9}, {%0,%1,%2,%3};"
        : "+f"(c[0]), "+f"(c[1]), "+f"(c[2]), "+f"(c[3])
        : "r"(a[0]), "r"(a[1]), "r"(a[2]), "r"(a[3]), "r"(b[0]), "r"(b[1]));
}
__device__ __forceinline__ unsigned pack_h2(float lo, float hi) {
    __half2 h = __float22half2_rn(make_float2(lo, hi));
    return *reinterpret_cast<unsigned*>(&h);
}
__device__ __forceinline__ float ex2(float x) {
    float y;
    asm("ex2.approx.f32 %0, %1;" : "=f"(y) : "f"(x));
    return y;
}

// ---------------------------------------------------------------------------
// convert_h: fp32 -> fp16
// ---------------------------------------------------------------------------
__global__ __launch_bounds__(256) void convert_h(
    const float* __restrict__ in, __half* __restrict__ out, int n4)
{
    int i = blockIdx.x * blockDim.x + threadIdx.x;
    if (i >= n4) return;
    float4 v = ((const float4*)in)[i];
    __half2* op = (__half2*)(out + (size_t)i * 4);
    op[0] = __float22half2_rn(make_float2(v.x, v.y));
    op[1] = __float22half2_rn(make_float2(v.z, v.w));
}

// ---------------------------------------------------------------------------
// transpose_all: W[K][N] fp32 -> g_wt[z][N][K] fp16 (z = blockIdx.z)
// ---------------------------------------------------------------------------
__global__ __launch_bounds__(256) void transpose_all(
    const float* __restrict__ Wq, const float* __restrict__ Wk,
    const float* __restrict__ Wv, const float* __restrict__ Wproj)
{
    __shared__ float tile[32][33];
    const int z = blockIdx.z;
    const float* W = (z == 0) ? Wq : (z == 1) ? Wk : (z == 2) ? Wv : Wproj;
    __half* out = g_wt[z];
    int k0 = blockIdx.y * 32, n0 = blockIdx.x * 32;
    int tx = threadIdx.x, ty = threadIdx.y;  // block (32, 8)
    #pragma unroll
    for (int r = 0; r < 4; r++)
        tile[ty + 8 * r][tx] = W[(size_t)(k0 + ty + 8 * r) * C_ + n0 + tx];
    __syncthreads();
    #pragma unroll
    for (int r = 0; r < 4; r++) {
        float v = tile[tx][ty + 8 * r];
        out[(size_t)(n0 + ty + 8 * r) * C_ + k0 + tx] = __float2half(v);
    }
}

// ---------------------------------------------------------------------------
// HMMA fp16 GEMM body: C[M][N] = A[M][K] * B[K][N], B transposed [N][K].
// 128x128 CTA tile, 8 warps (4x2), k-chunk 64, cp.async double-buffered.
// ---------------------------------------------------------------------------
#define KC        64
#define AS_STRIDE 72                        // fp16 elems per smem row (144B)
#define TILE_E    (128 * AS_STRIDE)         // 9216 elems
#define STAGE_E   (2 * TILE_E)              // A | B

__device__ __forceinline__ void gemm_body(
    const __half* __restrict__ A, const __half* __restrict__ Bm,
    float* __restrict__ Cm, int Ncols, int K, __half* smb)
{
    const int tid = threadIdx.x, wid = tid >> 5, lane = tid & 31;
    const int m0 = blockIdx.y * 128, n0 = blockIdx.x * 128;
    const int NCH = K / KC;
    const int wm = wid & 3;
    const int wn = wid >> 2;

    auto load_stage = [&](int c, int s) {
        const int k0 = c * KC;
        __half* base = smb + s * STAGE_E;
        #pragma unroll
        for (int i = 0; i < 4; i++) {
            int cidx = tid + i * 256;          // 0..1023
            int row  = cidx >> 3;
            int col8 = (cidx & 7) * 8;
            unsigned so = smem_u32(base + row * AS_STRIDE + col8);
            CP_ASYNC16(so,              A  + (size_t)(m0 + row) * K + k0 + col8);
            CP_ASYNC16(so + TILE_E * 2, Bm + (size_t)(n0 + row) * K + k0 + col8);
        }
    };

    float acc[2][8][4];
    #pragma unroll
    for (int mt = 0; mt < 2; mt++)
        #pragma unroll
        for (int nt = 0; nt < 8; nt++)
            #pragma unroll
            for (int r = 0; r < 4; r++) acc[mt][nt][r] = 0.f;

    load_stage(0, 0);
    CP_COMMIT();

    const int a_row = wm * 32 + (lane & 15);
    const int a_k8  = (lane >> 4) * 8;
    const int b_r   = lane & 7;
    const int b_grp = lane >> 3;
    const int b_row = wn * 64 + (b_grp >> 1) * 8 + b_r;
    const int b_k8  = (b_grp & 1) * 8;

    for (int c = 0; c < NCH; c++) {
        if (c + 1 < NCH) {
            load_stage(c + 1, (c + 1) & 1);
            CP_COMMIT();
            CP_WAIT1();
        } else {
            CP_WAIT0();
        }
        __syncthreads();

        const __half* st = smb + (c & 1) * STAGE_E;
        const __half* sA = st;
        const __half* sB = st + TILE_E;

        #pragma unroll
        for (int k16 = 0; k16 < 4; k16++) {
            const int kb = k16 * 16;
            unsigned ah[2][4];
            #pragma unroll
            for (int mt = 0; mt < 2; mt++)
                ldmatrix_x4(ah[mt], smem_u32(sA + (a_row + mt * 16) * AS_STRIDE + kb + a_k8));
            #pragma unroll
            for (int j = 0; j < 4; j++) {
                unsigned bh[4];
                ldmatrix_x4(bh, smem_u32(sB + (b_row + j * 16) * AS_STRIDE + kb + b_k8));
                #pragma unroll
                for (int t = 0; t < 2; t++)
                    #pragma unroll
                    for (int mt = 0; mt < 2; mt++)
                        mma_f16(acc[mt][j * 2 + t], ah[mt], bh + t * 2);
            }
        }
        __syncthreads();
    }

    const int cg = lane >> 2, ct = lane & 3;
    #pragma unroll
    for (int mt = 0; mt < 2; mt++) {
        const int row = m0 + wm * 32 + mt * 16 + cg;
        #pragma unroll
        for (int nt = 0; nt < 8; nt++) {
            const int col = n0 + wn * 64 + nt * 8 + ct * 2;
            float2 w0 = make_float2(acc[mt][nt][0], acc[mt][nt][1]);
            float2 w1 = make_float2(acc[mt][nt][2], acc[mt][nt][3]);
            *(float2*)(Cm + (size_t)row * Ncols + col)       = w0;
            *(float2*)(Cm + (size_t)(row + 8) * Ncols + col) = w1;
        }
    }
}

// fused QKV GEMM: blockIdx.z selects weight/output
__global__ __launch_bounds__(256, 2) void gemm_qkv(
    const __half* __restrict__ A,
    float* __restrict__ q, float* __restrict__ k, float* __restrict__ v)
{
    extern __shared__ __half smb[];
    const int z = blockIdx.z;
    float* Cm = (z == 0) ? q : (z == 1) ? k : v;
    gemm_body(A, g_wt[z], Cm, C_, C_, smb);
}

__global__ __launch_bounds__(256, 2) void gemm_proj(
    const __half* __restrict__ A, float* __restrict__ Cm)
{
    extern __shared__ __half smb[];
    gemm_body(A, g_wt[3], Cm, C_, C_, smb);
}

// ---------------------------------------------------------------------------
// Prep: v += gate*ve ; q,k <- rmsnorm(rotary(.)), emit fp16
// ---------------------------------------------------------------------------
__device__ __forceinline__ float warp_sum(float v) {
    #pragma unroll
    for (int d = 16; d >= 1; d >>= 1) v += __shfl_xor_sync(0xffffffffu, v, d);
    return v;
}

__device__ __forceinline__ void rope_rms_h(
    const float* __restrict__ src, const float* cr, const float* sr, int lane,
    __half* __restrict__ dst, size_t base)
{
    const int d0 = lane, d1 = lane + 32;
    float x1a = src[d0],      x2a = src[d0 + 64];
    float x1b = src[d1],      x2b = src[d1 + 64];
    float ca = cr[d0], sa = sr[d0], cb = cr[d1], sb = sr[d1];
    float o1a =  x1a * ca + x2a * sa;
    float o2a = -x1a * sa + x2a * ca;
    float o1b =  x1b * cb + x2b * sb;
    float o2b = -x1b * sb + x2b * cb;
    float ss = warp_sum(o1a*o1a + o2a*o2a + o1b*o1b + o2b*o2b);
    float r = rsqrtf(ss * (1.f / 128.f) + 1e-6f);
    dst[base + d0]      = __float2half(o1a * r);
    dst[base + d0 + 64] = __float2half(o2a * r);
    dst[base + d1]      = __float2half(o1b * r);
    dst[base + d1 + 64] = __float2half(o2b * r);
}

__global__ __launch_bounds__(512) void prep_kernel(
    const float* __restrict__ x, const float* __restrict__ ve,
    const float* __restrict__ cosb, const float* __restrict__ sinb,
    const float* __restrict__ Wgate)
{
    const int bt   = blockIdx.x;
    const int t    = bt & (T_ - 1);
    const int h    = threadIdx.x >> 5;
    const int lane = threadIdx.x & 31;

    const float* xr = x + (size_t)bt * C_;
    float sacc = warp_sum(xr[lane] * Wgate[lane * NH_ + h]);
    float g = 2.f / (1.f + __expf(-sacc));

    const size_t base = (size_t)bt * C_ + h * HD_;
    #pragma unroll
    for (int i = 0; i < 4; i++) {
        int d = lane + i * 32;
        float vv = g_v[base + d] + g * ve[base + d];
        g_vf[base + d] = __float2half(vv);
    }

    const float* cr = cosb + (size_t)t * 64;
    const float* sr = sinb + (size_t)t * 64;
    rope_rms_h(g_q + base, cr, sr, lane, g_qf, base);
    rope_rms_h(g_k + base, cr, sr, lane, g_kf, base);
}

// ---------------------------------------------------------------------------
// HMMA fp16 flash attention (causal). BM=128, BN=64, HD=128.
// 256 threads = 8 warps, each warp owns 16 query rows. Output fp16 -> g_yf.
// ---------------------------------------------------------------------------
#define FST    136                 // smem row stride (fp16 elems), 272B
#define FKV    (64 * FST)
#define FQ     (128 * FST)

__global__ __launch_bounds__(256, 2) void flash_mma()
{
    extern __shared__ __half fsm[];
    __half* sQ  = fsm;                      // [128][FST]
    __half* sKV = sQ + FQ;                  // 2 stages x (K|V)[64][FST]

    const int tid = threadIdx.x, wid = tid >> 5, lane = tid & 31;
    const int qb = gridDim.x - 1 - blockIdx.x;   // big tiles first
    const int h  = blockIdx.y;
    const int b  = blockIdx.z;

    const size_t qrow0 = (size_t)(b * T_ + qb * 128) * C_ + h * HD_;
    const size_t krow0 = (size_t)(b * T_) * C_ + h * HD_;

    for (int i = tid; i < 2048; i += 256) {
        int r = i >> 4, c8 = (i & 15) * 8;
        CP_ASYNC16(smem_u32(sQ + r * FST + c8), g_qf + qrow0 + (size_t)r * C_ + c8);
    }
    auto load_kv = [&](int kt, int s) {
        __half* base = sKV + s * (2 * FKV);
        const size_t kb0 = krow0 + (size_t)(kt * 64) * C_;
        for (int i = tid; i < 1024; i += 256) {
            int r = i >> 4, c8 = (i & 15) * 8;
            size_t go = kb0 + (size_t)r * C_ + c8;
            unsigned off = r * FST + c8;
            CP_ASYNC16(smem_u32(base + off),       g_kf + go);
            CP_ASYNC16(smem_u32(base + FKV + off), g_vf + go);
        }
    };
    load_kv(0, 0);
    CP_COMMIT();
    CP_WAIT0();
    __syncthreads();

    const int g  = lane >> 2;
    const int t4 = lane & 3;
    const int a_row = wid * 16 + (lane & 15);
    const int a_c8  = (lane >> 4) * 8;
    const int b_row = (lane & 7) + ((lane >> 4) << 3);
    const int b_c8  = ((lane >> 3) & 1) * 8;
    const int v_row = lane & 15;
    const int v_c8  = (lane >> 4) * 8;

    float m0 = -1e30f, m1 = -1e30f, l0 = 0.f, l1 = 0.f;
    float oacc[16][4];
    #pragma unroll
    for (int dt = 0; dt < 16; dt++)
        #pragma unroll
        for (int r = 0; r < 4; r++) oacc[dt][r] = 0.f;

    const float sc2 = 0.08838834764831845f * 1.4426950408889634f;  // scale*log2(e)
    const int nkt = 2 * qb + 2;

    for (int kt = 0; kt < nkt; kt++) {
        const int s = kt & 1;
        if (kt + 1 < nkt) { load_kv(kt + 1, s ^ 1); CP_COMMIT(); }

        __half* Kh = sKV + s * (2 * FKV);
        __half* Vh = Kh + FKV;

        // --- S = Q K^T ---
        float sacc[8][4];
        #pragma unroll
        for (int nt = 0; nt < 8; nt++)
            #pragma unroll
            for (int r = 0; r < 4; r++) sacc[nt][r] = 0.f;

        #pragma unroll
        for (int k16 = 0; k16 < 8; k16++) {
            unsigned ah[4];
            ldmatrix_x4(ah, smem_u32(sQ + a_row * FST + k16 * 16 + a_c8));
            #pragma unroll
            for (int nt2 = 0; nt2 < 4; nt2++) {
                unsigned bh[4];
                ldmatrix_x4(bh, smem_u32(Kh + (nt2 * 16 + b_row) * FST + k16 * 16 + b_c8));
                #pragma unroll
                for (int t = 0; t < 2; t++)
                    mma_f16(sacc[nt2 * 2 + t], ah, bh + 2 * t);
            }
        }

        #pragma unroll
        for (int nt = 0; nt < 8; nt++)
            #pragma unroll
            for (int r = 0; r < 4; r++) sacc[nt][r] *= sc2;

        if (kt >= 2 * qb) {
            const int row0 = qb * 128 + wid * 16 + g;
            #pragma unroll
            for (int nt = 0; nt < 8; nt++) {
                const int col = kt * 64 + nt * 8 + 2 * t4;
                if (col     > row0)     sacc[nt][0] = -1e30f;
                if (col + 1 > row0)     sacc[nt][1] = -1e30f;
                if (col     > row0 + 8) sacc[nt][2] = -1e30f;
                if (col + 1 > row0 + 8) sacc[nt][3] = -1e30f;
            }
        }

        // --- online softmax ---
        float mx0 = -1e30f, mx1 = -1e30f;
        #pragma unroll
        for (int nt = 0; nt < 8; nt++) {
            mx0 = fmaxf(mx0, fmaxf(sacc[nt][0], sacc[nt][1]));
            mx1 = fmaxf(mx1, fmaxf(sacc[nt][2], sacc[nt][3]));
        }
        mx0 = fmaxf(mx0, __shfl_xor_sync(0xffffffffu, mx0, 1));
        mx0 = fmaxf(mx0, __shfl_xor_sync(0xffffffffu, mx0, 2));
        mx1 = fmaxf(mx1, __shfl_xor_sync(0xffffffffu, mx1, 1));
        mx1 = fmaxf(mx1, __shfl_xor_sync(0xffffffffu, mx1, 2));

        float mn0 = fmaxf(m0, mx0), mn1 = fmaxf(m1, mx1);
        float al0 = ex2(m0 - mn0), al1 = ex2(m1 - mn1);
        m0 = mn0; m1 = mn1;

        float rs0 = 0.f, rs1 = 0.f;
        #pragma unroll
        for (int nt = 0; nt < 8; nt++) {
            sacc[nt][0] = ex2(sacc[nt][0] - mn0);
            sacc[nt][1] = ex2(sacc[nt][1] - mn0);
            sacc[nt][2] = ex2(sacc[nt][2] - mn1);
            sacc[nt][3] = ex2(sacc[nt][3] - mn1);
            rs0 += sacc[nt][0] + sacc[nt][1];
            rs1 += sacc[nt][2] + sacc[nt][3];
        }
        rs0 += __shfl_xor_sync(0xffffffffu, rs0, 1);
        rs0 += __shfl_xor_sync(0xffffffffu, rs0, 2);
        rs1 += __shfl_xor_sync(0xffffffffu, rs1, 1);
        rs1 += __shfl_xor_sync(0xffffffffu, rs1, 2);
        l0 = l0 * al0 + rs0;
        l1 = l1 * al1 + rs1;

        #pragma unroll
        for (int dt = 0; dt < 16; dt++) {
            oacc[dt][0] *= al0; oacc[dt][1] *= al0;
            oacc[dt][2] *= al1; oacc[dt][3] *= al1;
        }

        // --- O += P V ---
        #pragma unroll
        for (int kt2 = 0; kt2 < 4; kt2++) {
            unsigned ph[4];
            #pragma unroll
            for (int half = 0; half < 2; half++) {
                const float* sp = sacc[2 * kt2 + half];
                ph[half * 2 + 0] = pack_h2(sp[0], sp[1]);
                ph[half * 2 + 1] = pack_h2(sp[2], sp[3]);
            }
            #pragma unroll
            for (int dp = 0; dp < 4; dp++) {
                unsigned vh[2][4];
                #pragma unroll
                for (int d = 0; d < 2; d++) {
                    const int dt2 = dp * 2 + d;
                    ldmatrix_x4_trans(vh[d], smem_u32(Vh + (kt2 * 16 + v_row) * FST + dt2 * 16 + v_c8));
                }
                #pragma unroll
                for (int d = 0; d < 2; d++)
                    #pragma unroll
                    for (int n = 0; n < 2; n++)
                        mma_f16(oacc[(dp * 2 + d) * 2 + n], ph, vh[d] + 2 * n);
            }
        }

        if (kt + 1 < nkt) CP_WAIT0();
        __syncthreads();
    }

    // epilogue -> fp16 g_yf
    const float inv0 = 1.f / l0, inv1 = 1.f / l1;
    __half* yb = g_yf + (size_t)(b * T_ + qb * 128 + wid * 16) * C_ + h * HD_;
    #pragma unroll
    for (int dt = 0; dt < 16; dt++) {
        const int col = dt * 8 + 2 * t4;
        *(__half2*)(yb + (size_t)g * C_ + col) =
            __float22half2_rn(make_float2(oacc[dt][0] * inv0, oacc[dt][1] * inv0));
        *(__half2*)(yb + (size_t)(g + 8) * C_ + col) =
            __float22half2_rn(make_float2(oacc[dt][2] * inv1, oacc[dt][3] * inv1));
    }
}

// ---------------------------------------------------------------------------
// Launch
// ---------------------------------------------------------------------------
extern "C" void kernel_launch(void* const* d_in, const int* in_sizes, int n_in,
                              void* d_out, int out_size)
{
    (void)in_sizes; (void)n_in; (void)out_size;
    const float* x     = (const float*)d_in[0];
    const float* ve    = (const float*)d_in[1];
    const float* cosb  = (const float*)d_in[2];
    const float* sinb  = (const float*)d_in[3];
    const float* Wq    = (const float*)d_in[4];
    const float* Wk    = (const float*)d_in[5];
    const float* Wv    = (const float*)d_in[6];
    const float* Wgate = (const float*)d_in[7];
    const float* Wproj = (const float*)d_in[8];
    float* out = (float*)d_out;

    float *q, *k, *v;
    cudaGetSymbolAddress((void**)&q, g_q);
    cudaGetSymbolAddress((void**)&k, g_k);
    cudaGetSymbolAddress((void**)&v, g_v);
    __half *xf, *yf;
    cudaGetSymbolAddress((void**)&xf, g_xf);
    cudaGetSymbolAddress((void**)&yf, g_yf);

    convert_h<<<(M_*C_/4 + 255)/256, 256>>>(x, xf, M_*C_/4);
    transpose_all<<<dim3(C_/32, C_/32, 4), dim3(32, 8)>>>(Wq, Wk, Wv, Wproj);

    const int gemm_smem = 2 * STAGE_E * (int)sizeof(__half);  // 73728 B
    cudaFuncSetAttribute(gemm_qkv,  cudaFuncAttributeMaxDynamicSharedMemorySize, gemm_smem);
    cudaFuncSetAttribute(gemm_proj, cudaFuncAttributeMaxDynamicSharedMemorySize, gemm_smem);
    gemm_qkv<<<dim3(C_/128, M_/128, 3), 256, gemm_smem>>>(xf, q, k, v);

    prep_kernel<<<M_, 512>>>(x, ve, cosb, sinb, Wgate);

    const int fsmem = (FQ + 4 * FKV) * (int)sizeof(__half);  // 104448 B
    cudaFuncSetAttribute(flash_mma, cudaFuncAttributeMaxDynamicSharedMemorySize, fsmem);
    flash_mma<<<dim3(T_/128, NH_, B_), 256, fsmem>>>();

    gemm_proj<<<dim3(C_/128, M_/128), 256, gemm_smem>>>(yf, out);
}

// round 8
// speedup vs baseline: 7.1468x; 1.0139x over previous
#include <cuda_runtime.h>
#include <cuda_fp16.h>
#include <math.h>

// Problem constants
#define B_       2
#define T_       2048
#define C_       2048
#define NH_      16
#define HD_      128
#define GATE_CH_ 32
#define M_       (B_*T_)   // 4096 rows

// ---------------------------------------------------------------------------
// Scratch (device globals: allocation-free per harness rules)
// ---------------------------------------------------------------------------
__device__ __half g_xf[(size_t)M_*C_];
__device__ __half g_yf[(size_t)M_*C_];
__device__ __half g_qf[(size_t)M_*C_];
__device__ __half g_kf[(size_t)M_*C_];
__device__ __half g_vf[(size_t)M_*C_];
__device__ __half g_wt[4][(size_t)C_*C_];   // transposed [N][K] Wq,Wk,Wv,Wproj

// ---------------------------------------------------------------------------
// PTX helpers
// ---------------------------------------------------------------------------
__device__ __forceinline__ unsigned smem_u32(const void* p) {
    unsigned a;
    asm("{ .reg .u64 t; cvta.to.shared.u64 t, %1; cvt.u32.u64 %0, t; }"
        : "=r"(a) : "l"(p));
    return a;
}

#define CP_ASYNC16(dst_u32, src_ptr) \
    asm volatile("cp.async.cg.shared.global [%0], [%1], 16;" \
                 :: "r"(dst_u32), "l"(src_ptr))
#define CP_COMMIT() asm volatile("cp.async.commit_group;" ::: "memory")
#define CP_WAIT0()  asm volatile("cp.async.wait_group 0;" ::: "memory")
#define CP_WAIT1()  asm volatile("cp.async.wait_group 1;" ::: "memory")

__device__ __forceinline__ void ldmatrix_x4(unsigned* r, unsigned addr) {
    asm volatile("ldmatrix.sync.aligned.m8n8.x4.shared.b16 {%0,%1,%2,%3}, [%4];"
                 : "=r"(r[0]), "=r"(r[1]), "=r"(r[2]), "=r"(r[3]) : "r"(addr));
}
__device__ __forceinline__ void ldmatrix_x4_trans(unsigned* r, unsigned addr) {
    asm volatile("ldmatrix.sync.aligned.m8n8.x4.trans.shared.b16 {%0,%1,%2,%3}, [%4];"
                 : "=r"(r[0]), "=r"(r[1]), "=r"(r[2]), "=r"(r[3]) : "r"(addr));
}
__device__ __forceinline__ void mma_f16(float* c, const unsigned* a, const unsigned* b) {
    asm volatile(
        "mma.sync.aligned.m16n8k16.row.col.f32.f16.f16.f32 "
        "{%0,%1,%2,%3}, {%4,%5,%6,%7}, {%8,%9}, {%0,%1,%2,%3};"
        : "+f"(c[0]), "+f"(c[1]), "+f"(c[2]), "+f"(c[3])
        : "r"(a[0]), "r"(a[1]), "r"(a[2]), "r"(a[3]), "r"(b[0]), "r"(b[1]));
}
__device__ __forceinline__ unsigned pack_h2(float lo, float hi) {
    __half2 h = __float22half2_rn(make_float2(lo, hi));
    return *reinterpret_cast<unsigned*>(&h);
}
__device__ __forceinline__ float ex2(float x) {
    float y;
    asm("ex2.approx.f32 %0, %1;" : "=f"(y) : "f"(x));
    return y;
}
__device__ __forceinline__ float warp_sum(float v) {
    #pragma unroll
    for (int d = 16; d >= 1; d >>= 1) v += __shfl_xor_sync(0xffffffffu, v, d);
    return v;
}

// ---------------------------------------------------------------------------
// convert_h: fp32 -> fp16
// ---------------------------------------------------------------------------
__global__ __launch_bounds__(256) void convert_h(
    const float* __restrict__ in, __half* __restrict__ out, int n4)
{
    int i = blockIdx.x * blockDim.x + threadIdx.x;
    if (i >= n4) return;
    float4 v = ((const float4*)in)[i];
    __half2* op = (__half2*)(out + (size_t)i * 4);
    op[0] = __float22half2_rn(make_float2(v.x, v.y));
    op[1] = __float22half2_rn(make_float2(v.z, v.w));
}

// ---------------------------------------------------------------------------
// transpose_all: W[K][N] fp32 -> g_wt[z][N][K] fp16 (z = blockIdx.z)
// ---------------------------------------------------------------------------
__global__ __launch_bounds__(256) void transpose_all(
    const float* __restrict__ Wq, const float* __restrict__ Wk,
    const float* __restrict__ Wv, const float* __restrict__ Wproj)
{
    __shared__ float tile[32][33];
    const int z = blockIdx.z;
    const float* W = (z == 0) ? Wq : (z == 1) ? Wk : (z == 2) ? Wv : Wproj;
    __half* out = g_wt[z];
    int k0 = blockIdx.y * 32, n0 = blockIdx.x * 32;
    int tx = threadIdx.x, ty = threadIdx.y;  // block (32, 8)
    #pragma unroll
    for (int r = 0; r < 4; r++)
        tile[ty + 8 * r][tx] = W[(size_t)(k0 + ty + 8 * r) * C_ + n0 + tx];
    __syncthreads();
    #pragma unroll
    for (int r = 0; r < 4; r++) {
        float v = tile[tx][ty + 8 * r];
        out[(size_t)(n0 + ty + 8 * r) * C_ + k0 + tx] = __float2half(v);
    }
}

// ---------------------------------------------------------------------------
// HMMA fp16 GEMM mainloop (shared by qkv-fused and proj kernels).
// 128x128 CTA tile, 8 warps (4x2), k-chunk 64, cp.async double-buffered.
// ---------------------------------------------------------------------------
#define KC        64
#define AS_STRIDE 72                        // fp16 elems per smem row (144B)
#define TILE_E    (128 * AS_STRIDE)         // 9216 elems
#define STAGE_E   (2 * TILE_E)              // A | B

__device__ __forceinline__ void gemm_mainloop(
    const __half* __restrict__ A, const __half* __restrict__ Bm,
    int m0, int n0, int K, __half* smb, float acc[2][8][4])
{
    const int tid = threadIdx.x, wid = tid >> 5, lane = tid & 31;
    const int NCH = K / KC;
    const int wm = wid & 3;
    const int wn = wid >> 2;

    auto load_stage = [&](int c, int s) {
        const int k0 = c * KC;
        __half* base = smb + s * STAGE_E;
        #pragma unroll
        for (int i = 0; i < 4; i++) {
            int cidx = tid + i * 256;          // 0..1023
            int row  = cidx >> 3;
            int col8 = (cidx & 7) * 8;
            unsigned so = smem_u32(base + row * AS_STRIDE + col8);
            CP_ASYNC16(so,              A  + (size_t)(m0 + row) * K + k0 + col8);
            CP_ASYNC16(so + TILE_E * 2, Bm + (size_t)(n0 + row) * K + k0 + col8);
        }
    };

    #pragma unroll
    for (int mt = 0; mt < 2; mt++)
        #pragma unroll
        for (int nt = 0; nt < 8; nt++)
            #pragma unroll
            for (int r = 0; r < 4; r++) acc[mt][nt][r] = 0.f;

    load_stage(0, 0);
    CP_COMMIT();

    const int a_row = wm * 32 + (lane & 15);
    const int a_k8  = (lane >> 4) * 8;
    const int b_r   = lane & 7;
    const int b_grp = lane >> 3;
    const int b_row = wn * 64 + (b_grp >> 1) * 8 + b_r;
    const int b_k8  = (b_grp & 1) * 8;

    for (int c = 0; c < NCH; c++) {
        if (c + 1 < NCH) {
            load_stage(c + 1, (c + 1) & 1);
            CP_COMMIT();
            CP_WAIT1();
        } else {
            CP_WAIT0();
        }
        __syncthreads();

        const __half* st = smb + (c & 1) * STAGE_E;
        const __half* sA = st;
        const __half* sB = st + TILE_E;

        #pragma unroll
        for (int k16 = 0; k16 < 4; k16++) {
            const int kb = k16 * 16;
            unsigned ah[2][4];
            #pragma unroll
            for (int mt = 0; mt < 2; mt++)
                ldmatrix_x4(ah[mt], smem_u32(sA + (a_row + mt * 16) * AS_STRIDE + kb + a_k8));
            #pragma unroll
            for (int j = 0; j < 4; j++) {
                unsigned bh[4];
                ldmatrix_x4(bh, smem_u32(sB + (b_row + j * 16) * AS_STRIDE + kb + b_k8));
                #pragma unroll
                for (int t = 0; t < 2; t++)
                    #pragma unroll
                    for (int mt = 0; mt < 2; mt++)
                        mma_f16(acc[mt][j * 2 + t], ah[mt], bh + t * 2);
            }
        }
        __syncthreads();
    }
}

// ---------------------------------------------------------------------------
// Fused QKV GEMM + prep epilogue.
// z=0: q -> rope+rms -> g_qf ; z=1: k -> rope+rms -> g_kf ;
// z=2: v -> + gate*ve -> g_vf. 128 cols per tile = one full head.
// ---------------------------------------------------------------------------
#define EST 130   // fp32 epilogue smem row stride

__global__ __launch_bounds__(256, 2) void gemm_qkv_fused(
    const __half* __restrict__ A,
    const float* __restrict__ x, const float* __restrict__ ve,
    const float* __restrict__ cosb, const float* __restrict__ sinb,
    const float* __restrict__ Wgate)
{
    extern __shared__ __half smb[];
    const int z = blockIdx.z;
    const int m0 = blockIdx.y * 128, n0 = blockIdx.x * 128;

    float acc[2][8][4];
    gemm_mainloop(A, g_wt[z], m0, n0, C_, smb, acc);

    // spill fp32 tile to smem (stage buffers are free now)
    const int tid = threadIdx.x, wid = tid >> 5, lane = tid & 31;
    const int wm = wid & 3, wn = wid >> 2;
    const int cg = lane >> 2, ct = lane & 3;
    float* ft = (float*)smb;
    #pragma unroll
    for (int mt = 0; mt < 2; mt++) {
        const int r = wm * 32 + mt * 16 + cg;
        #pragma unroll
        for (int nt = 0; nt < 8; nt++) {
            const int cc = wn * 64 + nt * 8 + ct * 2;
            ft[r * EST + cc]           = acc[mt][nt][0];
            ft[r * EST + cc + 1]       = acc[mt][nt][1];
            ft[(r + 8) * EST + cc]     = acc[mt][nt][2];
            ft[(r + 8) * EST + cc + 1] = acc[mt][nt][3];
        }
    }
    __syncthreads();

    const int h = n0 >> 7;   // head index
    if (z < 2) {
        __half* gout = (z == 0) ? g_qf : g_kf;
        for (int rr = 0; rr < 16; rr++) {
            const int r = wid * 16 + rr;
            const int row = m0 + r;
            const int t = row & (T_ - 1);
            const float* fr = ft + r * EST;
            const float* cr = cosb + (size_t)t * 64;
            const float* sr = sinb + (size_t)t * 64;
            const int d0 = lane, d1 = lane + 32;
            float x1a = fr[d0], x2a = fr[d0 + 64];
            float x1b = fr[d1], x2b = fr[d1 + 64];
            float ca = cr[d0], sa = sr[d0], cb = cr[d1], sb = sr[d1];
            float o1a =  x1a * ca + x2a * sa;
            float o2a = -x1a * sa + x2a * ca;
            float o1b =  x1b * cb + x2b * sb;
            float o2b = -x1b * sb + x2b * cb;
            float ss = warp_sum(o1a*o1a + o2a*o2a + o1b*o1b + o2b*o2b);
            float rn = rsqrtf(ss * (1.f / 128.f) + 1e-6f);
            __half* dst = gout + (size_t)row * C_ + n0;
            dst[d0]      = __float2half(o1a * rn);
            dst[d0 + 64] = __float2half(o2a * rn);
            dst[d1]      = __float2half(o1b * rn);
            dst[d1 + 64] = __float2half(o2b * rn);
        }
    } else {
        for (int rr = 0; rr < 16; rr++) {
            const int r = wid * 16 + rr;
            const int row = m0 + r;
            const float* fr = ft + r * EST;
            float sg = warp_sum(x[(size_t)row * C_ + lane] * Wgate[lane * NH_ + h]);
            float gt = 2.f / (1.f + __expf(-sg));
            __half* dst = g_vf + (size_t)row * C_ + n0;
            const float* vep = ve + (size_t)row * C_ + n0;
            #pragma unroll
            for (int i2 = 0; i2 < 4; i2++) {
                const int d = lane + i2 * 32;
                dst[d] = __float2half(fr[d] + gt * vep[d]);
            }
        }
    }
}

// proj GEMM: plain fp32 epilogue to out
__global__ __launch_bounds__(256, 2) void gemm_proj(
    const __half* __restrict__ A, float* __restrict__ Cm)
{
    extern __shared__ __half smb[];
    const int m0 = blockIdx.y * 128, n0 = blockIdx.x * 128;
    float acc[2][8][4];
    gemm_mainloop(A, g_wt[3], m0, n0, C_, smb, acc);

    const int tid = threadIdx.x, wid = tid >> 5, lane = tid & 31;
    const int wm = wid & 3, wn = wid >> 2;
    const int cg = lane >> 2, ct = lane & 3;
    #pragma unroll
    for (int mt = 0; mt < 2; mt++) {
        const int row = m0 + wm * 32 + mt * 16 + cg;
        #pragma unroll
        for (int nt = 0; nt < 8; nt++) {
            const int col = n0 + wn * 64 + nt * 8 + ct * 2;
            *(float2*)(Cm + (size_t)row * C_ + col)       = make_float2(acc[mt][nt][0], acc[mt][nt][1]);
            *(float2*)(Cm + (size_t)(row + 8) * C_ + col) = make_float2(acc[mt][nt][2], acc[mt][nt][3]);
        }
    }
}

// ---------------------------------------------------------------------------
// HMMA fp16 flash attention (causal). BM=128, BN=64, HD=128.
// 256 threads = 8 warps, each warp owns 16 query rows. Output fp16 -> g_yf.
// ---------------------------------------------------------------------------
#define FST    136                 // smem row stride (fp16 elems), 272B
#define FKV    (64 * FST)
#define FQ     (128 * FST)

__global__ __launch_bounds__(256, 2) void flash_mma()
{
    extern __shared__ __half fsm[];
    __half* sQ  = fsm;                      // [128][FST]
    __half* sKV = sQ + FQ;                  // 2 stages x (K|V)[64][FST]

    const int tid = threadIdx.x, wid = tid >> 5, lane = tid & 31;
    const int qb = gridDim.x - 1 - blockIdx.x;   // big tiles first
    const int h  = blockIdx.y;
    const int b  = blockIdx.z;

    const size_t qrow0 = (size_t)(b * T_ + qb * 128) * C_ + h * HD_;
    const size_t krow0 = (size_t)(b * T_) * C_ + h * HD_;

    for (int i = tid; i < 2048; i += 256) {
        int r = i >> 4, c8 = (i & 15) * 8;
        CP_ASYNC16(smem_u32(sQ + r * FST + c8), g_qf + qrow0 + (size_t)r * C_ + c8);
    }
    auto load_kv = [&](int kt, int s) {
        __half* base = sKV + s * (2 * FKV);
        const size_t kb0 = krow0 + (size_t)(kt * 64) * C_;
        for (int i = tid; i < 1024; i += 256) {
            int r = i >> 4, c8 = (i & 15) * 8;
            size_t go = kb0 + (size_t)r * C_ + c8;
            unsigned off = r * FST + c8;
            CP_ASYNC16(smem_u32(base + off),       g_kf + go);
            CP_ASYNC16(smem_u32(base + FKV + off), g_vf + go);
        }
    };
    load_kv(0, 0);
    CP_COMMIT();
    CP_WAIT0();
    __syncthreads();

    const int g  = lane >> 2;
    const int t4 = lane & 3;
    const int a_row = wid * 16 + (lane & 15);
    const int a_c8  = (lane >> 4) * 8;
    const int b_row = (lane & 7) + ((lane >> 4) << 3);
    const int b_c8  = ((lane >> 3) & 1) * 8;
    const int v_row = lane & 15;
    const int v_c8  = (lane >> 4) * 8;

    float m0 = -1e30f, m1 = -1e30f, l0 = 0.f, l1 = 0.f;
    float oacc[16][4];
    #pragma unroll
    for (int dt = 0; dt < 16; dt++)
        #pragma unroll
        for (int r = 0; r < 4; r++) oacc[dt][r] = 0.f;

    const float sc2 = 0.08838834764831845f * 1.4426950408889634f;  // scale*log2(e)
    const int nkt = 2 * qb + 2;

    for (int kt = 0; kt < nkt; kt++) {
        const int s = kt & 1;
        if (kt + 1 < nkt) { load_kv(kt + 1, s ^ 1); CP_COMMIT(); }

        __half* Kh = sKV + s * (2 * FKV);
        __half* Vh = Kh + FKV;

        // --- S = Q K^T ---
        float sacc[8][4];
        #pragma unroll
        for (int nt = 0; nt < 8; nt++)
            #pragma unroll
            for (int r = 0; r < 4; r++) sacc[nt][r] = 0.f;

        #pragma unroll
        for (int k16 = 0; k16 < 8; k16++) {
            unsigned ah[4];
            ldmatrix_x4(ah, smem_u32(sQ + a_row * FST + k16 * 16 + a_c8));
            #pragma unroll
            for (int nt2 = 0; nt2 < 4; nt2++) {
                unsigned bh[4];
                ldmatrix_x4(bh, smem_u32(Kh + (nt2 * 16 + b_row) * FST + k16 * 16 + b_c8));
                #pragma unroll
                for (int t = 0; t < 2; t++)
                    mma_f16(sacc[nt2 * 2 + t], ah, bh + 2 * t);
            }
        }

        #pragma unroll
        for (int nt = 0; nt < 8; nt++)
            #pragma unroll
            for (int r = 0; r < 4; r++) sacc[nt][r] *= sc2;

        if (kt >= 2 * qb) {
            const int row0 = qb * 128 + wid * 16 + g;
            #pragma unroll
            for (int nt = 0; nt < 8; nt++) {
                const int col = kt * 64 + nt * 8 + 2 * t4;
                if (col     > row0)     sacc[nt][0] = -1e30f;
                if (col + 1 > row0)     sacc[nt][1] = -1e30f;
                if (col     > row0 + 8) sacc[nt][2] = -1e30f;
                if (col + 1 > row0 + 8) sacc[nt][3] = -1e30f;
            }
        }

        // --- online softmax ---
        float mx0 = -1e30f, mx1 = -1e30f;
        #pragma unroll
        for (int nt = 0; nt < 8; nt++) {
            mx0 = fmaxf(mx0, fmaxf(sacc[nt][0], sacc[nt][1]));
            mx1 = fmaxf(mx1, fmaxf(sacc[nt][2], sacc[nt][3]));
        }
        mx0 = fmaxf(mx0, __shfl_xor_sync(0xffffffffu, mx0, 1));
        mx0 = fmaxf(mx0, __shfl_xor_sync(0xffffffffu, mx0, 2));
        mx1 = fmaxf(mx1, __shfl_xor_sync(0xffffffffu, mx1, 1));
        mx1 = fmaxf(mx1, __shfl_xor_sync(0xffffffffu, mx1, 2));

        float mn0 = fmaxf(m0, mx0), mn1 = fmaxf(m1, mx1);
        float al0 = ex2(m0 - mn0), al1 = ex2(m1 - mn1);
        m0 = mn0; m1 = mn1;

        float rs0 = 0.f, rs1 = 0.f;
        #pragma unroll
        for (int nt = 0; nt < 8; nt++) {
            sacc[nt][0] = ex2(sacc[nt][0] - mn0);
            sacc[nt][1] = ex2(sacc[nt][1] - mn0);
            sacc[nt][2] = ex2(sacc[nt][2] - mn1);
            sacc[nt][3] = ex2(sacc[nt][3] - mn1);
            rs0 += sacc[nt][0] + sacc[nt][1];
            rs1 += sacc[nt][2] + sacc[nt][3];
        }
        rs0 += __shfl_xor_sync(0xffffffffu, rs0, 1);
        rs0 += __shfl_xor_sync(0xffffffffu, rs0, 2);
        rs1 += __shfl_xor_sync(0xffffffffu, rs1, 1);
        rs1 += __shfl_xor_sync(0xffffffffu, rs1, 2);
        l0 = l0 * al0 + rs0;
        l1 = l1 * al1 + rs1;

        #pragma unroll
        for (int dt = 0; dt < 16; dt++) {
            oacc[dt][0] *= al0; oacc[dt][1] *= al0;
            oacc[dt][2] *= al1; oacc[dt][3] *= al1;
        }

        // --- O += P V ---
        #pragma unroll
        for (int kt2 = 0; kt2 < 4; kt2++) {
            unsigned ph[4];
            #pragma unroll
            for (int half = 0; half < 2; half++) {
                const float* sp = sacc[2 * kt2 + half];
                ph[half * 2 + 0] = pack_h2(sp[0], sp[1]);
                ph[half * 2 + 1] = pack_h2(sp[2], sp[3]);
            }
            #pragma unroll
            for (int dp = 0; dp < 4; dp++) {
                unsigned vh[2][4];
                #pragma unroll
                for (int d = 0; d < 2; d++) {
                    const int dt2 = dp * 2 + d;
                    ldmatrix_x4_trans(vh[d], smem_u32(Vh + (kt2 * 16 + v_row) * FST + dt2 * 16 + v_c8));
                }
                #pragma unroll
                for (int d = 0; d < 2; d++)
                    #pragma unroll
                    for (int n = 0; n < 2; n++)
                        mma_f16(oacc[(dp * 2 + d) * 2 + n], ph, vh[d] + 2 * n);
            }
        }

        if (kt + 1 < nkt) CP_WAIT0();
        __syncthreads();
    }

    // epilogue -> fp16 g_yf
    const float inv0 = 1.f / l0, inv1 = 1.f / l1;
    __half* yb = g_yf + (size_t)(b * T_ + qb * 128 + wid * 16) * C_ + h * HD_;
    #pragma unroll
    for (int dt = 0; dt < 16; dt++) {
        const int col = dt * 8 + 2 * t4;
        *(__half2*)(yb + (size_t)g * C_ + col) =
            __float22half2_rn(make_float2(oacc[dt][0] * inv0, oacc[dt][1] * inv0));
        *(__half2*)(yb + (size_t)(g + 8) * C_ + col) =
            __float22half2_rn(make_float2(oacc[dt][2] * inv1, oacc[dt][3] * inv1));
    }
}

// ---------------------------------------------------------------------------
// Launch
// ---------------------------------------------------------------------------
extern "C" void kernel_launch(void* const* d_in, const int* in_sizes, int n_in,
                              void* d_out, int out_size)
{
    (void)in_sizes; (void)n_in; (void)out_size;
    const float* x     = (const float*)d_in[0];
    const float* ve    = (const float*)d_in[1];
    const float* cosb  = (const float*)d_in[2];
    const float* sinb  = (const float*)d_in[3];
    const float* Wq    = (const float*)d_in[4];
    const float* Wk    = (const float*)d_in[5];
    const float* Wv    = (const float*)d_in[6];
    const float* Wgate = (const float*)d_in[7];
    const float* Wproj = (const float*)d_in[8];
    float* out = (float*)d_out;

    __half *xf, *yf;
    cudaGetSymbolAddress((void**)&xf, g_xf);
    cudaGetSymbolAddress((void**)&yf, g_yf);

    convert_h<<<(M_*C_/4 + 255)/256, 256>>>(x, xf, M_*C_/4);
    transpose_all<<<dim3(C_/32, C_/32, 4), dim3(32, 8)>>>(Wq, Wk, Wv, Wproj);

    const int gemm_smem = 2 * STAGE_E * (int)sizeof(__half);  // 73728 B
    cudaFuncSetAttribute(gemm_qkv_fused, cudaFuncAttributeMaxDynamicSharedMemorySize, gemm_smem);
    cudaFuncSetAttribute(gemm_proj,      cudaFuncAttributeMaxDynamicSharedMemorySize, gemm_smem);
    gemm_qkv_fused<<<dim3(C_/128, M_/128, 3), 256, gemm_smem>>>(xf, x, ve, cosb, sinb, Wgate);

    const int fsmem = (FQ + 4 * FKV) * (int)sizeof(__half);  // 104448 B
    cudaFuncSetAttribute(flash_mma, cudaFuncAttributeMaxDynamicSharedMemorySize, fsmem);
    flash_mma<<<dim3(T_/128, NH_, B_), 256, fsmem>>>();

    gemm_proj<<<dim3(C_/128, M_/128), 256, gemm_smem>>>(yf, out);
}

// round 9
// speedup vs baseline: 7.2311x; 1.0118x over previous
#include <cuda_runtime.h>
#include <cuda_fp16.h>
#include <math.h>

// Problem constants
#define B_       2
#define T_       2048
#define C_       2048
#define NH_      16
#define HD_      128
#define GATE_CH_ 32
#define M_       (B_*T_)   // 4096 rows

// ---------------------------------------------------------------------------
// Scratch (device globals: allocation-free per harness rules)
// ---------------------------------------------------------------------------
__device__ __half g_xf[(size_t)M_*C_];
__device__ __half g_yf[(size_t)M_*C_];
__device__ __half g_qf[(size_t)M_*C_];
__device__ __half g_kf[(size_t)M_*C_];
__device__ __half g_vf[(size_t)M_*C_];
__device__ __half g_wt[4][(size_t)C_*C_];   // transposed [N][K] Wq,Wk,Wv,Wproj

// ---------------------------------------------------------------------------
// PTX helpers
// ---------------------------------------------------------------------------
__device__ __forceinline__ unsigned smem_u32(const void* p) {
    unsigned a;
    asm("{ .reg .u64 t; cvta.to.shared.u64 t, %1; cvt.u32.u64 %0, t; }"
        : "=r"(a) : "l"(p));
    return a;
}

#define CP_ASYNC16(dst_u32, src_ptr) \
    asm volatile("cp.async.cg.shared.global [%0], [%1], 16;" \
                 :: "r"(dst_u32), "l"(src_ptr))
#define CP_COMMIT() asm volatile("cp.async.commit_group;" ::: "memory")
#define CP_WAIT0()  asm volatile("cp.async.wait_group 0;" ::: "memory")
#define CP_WAIT1()  asm volatile("cp.async.wait_group 1;" ::: "memory")
#define CP_WAIT2()  asm volatile("cp.async.wait_group 2;" ::: "memory")

__device__ __forceinline__ void ldmatrix_x4(unsigned* r, unsigned addr) {
    asm volatile("ldmatrix.sync.aligned.m8n8.x4.shared.b16 {%0,%1,%2,%3}, [%4];"
                 : "=r"(r[0]), "=r"(r[1]), "=r"(r[2]), "=r"(r[3]) : "r"(addr));
}
__device__ __forceinline__ void ldmatrix_x4_trans(unsigned* r, unsigned addr) {
    asm volatile("ldmatrix.sync.aligned.m8n8.x4.trans.shared.b16 {%0,%1,%2,%3}, [%4];"
                 : "=r"(r[0]), "=r"(r[1]), "=r"(r[2]), "=r"(r[3]) : "r"(addr));
}
__device__ __forceinline__ void mma_f16(float* c, const unsigned* a, const unsigned* b) {
    asm volatile(
        "mma.sync.aligned.m16n8k16.row.col.f32.f16.f16.f32 "
        "{%0,%1,%2,%3}, {%4,%5,%6,%7}, {%8,%9}, {%0,%1,%2,%3};"
        : "+f"(c[0]), "+f"(c[1]), "+f"(c[2]), "+f"(c[3])
        : "r"(a[0]), "r"(a[1]), "r"(a[2]), "r"(a[3]), "r"(b[0]), "r"(b[1]));
}
__device__ __forceinline__ unsigned pack_h2(float lo, float hi) {
    __half2 h = __float22half2_rn(make_float2(lo, hi));
    return *reinterpret_cast<unsigned*>(&h);
}
__device__ __forceinline__ float ex2(float x) {
    float y;
    asm("ex2.approx.f32 %0, %1;" : "=f"(y) : "f"(x));
    return y;
}
__device__ __forceinline__ float warp_sum(float v) {
    #pragma unroll
    for (int d = 16; d >= 1; d >>= 1) v += __shfl_xor_sync(0xffffffffu, v, d);
    return v;
}

// scale * log2(e), folded into q at QKV epilogue
#define QSC (0.08838834764831845f * 1.4426950408889634f)

// ---------------------------------------------------------------------------
// convert_h: fp32 -> fp16
// ---------------------------------------------------------------------------
__global__ __launch_bounds__(256) void convert_h(
    const float* __restrict__ in, __half* __restrict__ out, int n4)
{
    int i = blockIdx.x * blockDim.x + threadIdx.x;
    if (i >= n4) return;
    float4 v = ((const float4*)in)[i];
    __half2* op = (__half2*)(out + (size_t)i * 4);
    op[0] = __float22half2_rn(make_float2(v.x, v.y));
    op[1] = __float22half2_rn(make_float2(v.z, v.w));
}

// ---------------------------------------------------------------------------
// transpose_all: W[K][N] fp32 -> g_wt[z][N][K] fp16 (z = blockIdx.z)
// ---------------------------------------------------------------------------
__global__ __launch_bounds__(256) void transpose_all(
    const float* __restrict__ Wq, const float* __restrict__ Wk,
    const float* __restrict__ Wv, const float* __restrict__ Wproj)
{
    __shared__ float tile[32][33];
    const int z = blockIdx.z;
    const float* W = (z == 0) ? Wq : (z == 1) ? Wk : (z == 2) ? Wv : Wproj;
    __half* out = g_wt[z];
    int k0 = blockIdx.y * 32, n0 = blockIdx.x * 32;
    int tx = threadIdx.x, ty = threadIdx.y;  // block (32, 8)
    #pragma unroll
    for (int r = 0; r < 4; r++)
        tile[ty + 8 * r][tx] = W[(size_t)(k0 + ty + 8 * r) * C_ + n0 + tx];
    __syncthreads();
    #pragma unroll
    for (int r = 0; r < 4; r++) {
        float v = tile[tx][ty + 8 * r];
        out[(size_t)(n0 + ty + 8 * r) * C_ + k0 + tx] = __float2half(v);
    }
}

// ---------------------------------------------------------------------------
// HMMA fp16 GEMM mainloop. 128x128 CTA tile, 8 warps (4x2), k-chunk 64,
// cp.async 3-stage pipeline, batched B fragments.
// ---------------------------------------------------------------------------
#define KC        64
#define AS_STRIDE 72                        // fp16 elems per smem row (144B)
#define TILE_E    (128 * AS_STRIDE)         // 9216 elems
#define STAGE_E   (2 * TILE_E)              // A | B
#define NSTAGE    3

__device__ __forceinline__ void gemm_mainloop(
    const __half* __restrict__ A, const __half* __restrict__ Bm,
    int m0, int n0, int K, __half* smb, float acc[2][8][4])
{
    const int tid = threadIdx.x, wid = tid >> 5, lane = tid & 31;
    const int NCH = K / KC;
    const int wm = wid & 3;
    const int wn = wid >> 2;

    auto load_stage = [&](int c, int s) {
        const int k0 = c * KC;
        __half* base = smb + s * STAGE_E;
        #pragma unroll
        for (int i = 0; i < 4; i++) {
            int cidx = tid + i * 256;          // 0..1023
            int row  = cidx >> 3;
            int col8 = (cidx & 7) * 8;
            unsigned so = smem_u32(base + row * AS_STRIDE + col8);
            CP_ASYNC16(so,              A  + (size_t)(m0 + row) * K + k0 + col8);
            CP_ASYNC16(so + TILE_E * 2, Bm + (size_t)(n0 + row) * K + k0 + col8);
        }
    };

    #pragma unroll
    for (int mt = 0; mt < 2; mt++)
        #pragma unroll
        for (int nt = 0; nt < 8; nt++)
            #pragma unroll
            for (int r = 0; r < 4; r++) acc[mt][nt][r] = 0.f;

    load_stage(0, 0);
    CP_COMMIT();
    load_stage(1, 1);
    CP_COMMIT();

    const int a_row = wm * 32 + (lane & 15);
    const int a_k8  = (lane >> 4) * 8;
    const int b_r   = lane & 7;
    const int b_grp = lane >> 3;
    const int b_row = wn * 64 + (b_grp >> 1) * 8 + b_r;
    const int b_k8  = (b_grp & 1) * 8;

    for (int c = 0; c < NCH; c++) {
        if (c + 2 < NCH) {
            load_stage(c + 2, (c + 2) % NSTAGE);
            CP_COMMIT();
            CP_WAIT2();
        } else if (c + 1 < NCH) {
            CP_WAIT1();
        } else {
            CP_WAIT0();
        }
        __syncthreads();

        const __half* st = smb + (c % NSTAGE) * STAGE_E;
        const __half* sA = st;
        const __half* sB = st + TILE_E;

        #pragma unroll
        for (int k16 = 0; k16 < 4; k16++) {
            const int kb = k16 * 16;
            unsigned ah[2][4];
            #pragma unroll
            for (int mt = 0; mt < 2; mt++)
                ldmatrix_x4(ah[mt], smem_u32(sA + (a_row + mt * 16) * AS_STRIDE + kb + a_k8));
            unsigned bh[4][4];
            #pragma unroll
            for (int j = 0; j < 4; j++)
                ldmatrix_x4(bh[j], smem_u32(sB + (b_row + j * 16) * AS_STRIDE + kb + b_k8));
            #pragma unroll
            for (int j = 0; j < 4; j++)
                #pragma unroll
                for (int t = 0; t < 2; t++)
                    #pragma unroll
                    for (int mt = 0; mt < 2; mt++)
                        mma_f16(acc[mt][j * 2 + t], ah[mt], bh[j] + t * 2);
        }
        __syncthreads();
    }
}

// ---------------------------------------------------------------------------
// Fused QKV GEMM + prep epilogue. z=0: q (rope+rms, pre-scaled by QSC);
// z=1: k (rope+rms); z=2: v + gate*ve. 128 cols per tile = one full head.
// ---------------------------------------------------------------------------
#define EST 130   // fp32 epilogue smem row stride

__global__ __launch_bounds__(256, 2) void gemm_qkv_fused(
    const __half* __restrict__ A,
    const float* __restrict__ x, const float* __restrict__ ve,
    const float* __restrict__ cosb, const float* __restrict__ sinb,
    const float* __restrict__ Wgate)
{
    extern __shared__ __half smb[];
    const int z = blockIdx.z;
    const int m0 = blockIdx.y * 128, n0 = blockIdx.x * 128;

    float acc[2][8][4];
    gemm_mainloop(A, g_wt[z], m0, n0, C_, smb, acc);

    // spill fp32 tile to smem (stage buffers are free now)
    const int tid = threadIdx.x, wid = tid >> 5, lane = tid & 31;
    const int wm = wid & 3, wn = wid >> 2;
    const int cg = lane >> 2, ct = lane & 3;
    float* ft = (float*)smb;
    #pragma unroll
    for (int mt = 0; mt < 2; mt++) {
        const int r = wm * 32 + mt * 16 + cg;
        #pragma unroll
        for (int nt = 0; nt < 8; nt++) {
            const int cc = wn * 64 + nt * 8 + ct * 2;
            ft[r * EST + cc]           = acc[mt][nt][0];
            ft[r * EST + cc + 1]       = acc[mt][nt][1];
            ft[(r + 8) * EST + cc]     = acc[mt][nt][2];
            ft[(r + 8) * EST + cc + 1] = acc[mt][nt][3];
        }
    }
    __syncthreads();

    const int h = n0 >> 7;   // head index
    if (z < 2) {
        __half* gout = (z == 0) ? g_qf : g_kf;
        const float post = (z == 0) ? QSC : 1.f;
        for (int rr = 0; rr < 16; rr++) {
            const int r = wid * 16 + rr;
            const int row = m0 + r;
            const int t = row & (T_ - 1);
            const float* fr = ft + r * EST;
            const float* cr = cosb + (size_t)t * 64;
            const float* sr = sinb + (size_t)t * 64;
            const int d0 = lane, d1 = lane + 32;
            float x1a = fr[d0], x2a = fr[d0 + 64];
            float x1b = fr[d1], x2b = fr[d1 + 64];
            float ca = cr[d0], sa = sr[d0], cb = cr[d1], sb = sr[d1];
            float o1a =  x1a * ca + x2a * sa;
            float o2a = -x1a * sa + x2a * ca;
            float o1b =  x1b * cb + x2b * sb;
            float o2b = -x1b * sb + x2b * cb;
            float ss = warp_sum(o1a*o1a + o2a*o2a + o1b*o1b + o2b*o2b);
            float rn = rsqrtf(ss * (1.f / 128.f) + 1e-6f) * post;
            __half* dst = gout + (size_t)row * C_ + n0;
            dst[d0]      = __float2half(o1a * rn);
            dst[d0 + 64] = __float2half(o2a * rn);
            dst[d1]      = __float2half(o1b * rn);
            dst[d1 + 64] = __float2half(o2b * rn);
        }
    } else {
        for (int rr = 0; rr < 16; rr++) {
            const int r = wid * 16 + rr;
            const int row = m0 + r;
            const float* fr = ft + r * EST;
            float sg = warp_sum(x[(size_t)row * C_ + lane] * Wgate[lane * NH_ + h]);
            float gt = 2.f / (1.f + __expf(-sg));
            __half* dst = g_vf + (size_t)row * C_ + n0;
            const float* vep = ve + (size_t)row * C_ + n0;
            #pragma unroll
            for (int i2 = 0; i2 < 4; i2++) {
                const int d = lane + i2 * 32;
                dst[d] = __float2half(fr[d] + gt * vep[d]);
            }
        }
    }
}

// proj GEMM: plain fp32 epilogue to out
__global__ __launch_bounds__(256, 2) void gemm_proj(
    const __half* __restrict__ A, float* __restrict__ Cm)
{
    extern __shared__ __half smb[];
    const int m0 = blockIdx.y * 128, n0 = blockIdx.x * 128;
    float acc[2][8][4];
    gemm_mainloop(A, g_wt[3], m0, n0, C_, smb, acc);

    const int tid = threadIdx.x, wid = tid >> 5, lane = tid & 31;
    const int wm = wid & 3, wn = wid >> 2;
    const int cg = lane >> 2, ct = lane & 3;
    #pragma unroll
    for (int mt = 0; mt < 2; mt++) {
        const int row = m0 + wm * 32 + mt * 16 + cg;
        #pragma unroll
        for (int nt = 0; nt < 8; nt++) {
            const int col = n0 + wn * 64 + nt * 8 + ct * 2;
            *(float2*)(Cm + (size_t)row * C_ + col)       = make_float2(acc[mt][nt][0], acc[mt][nt][1]);
            *(float2*)(Cm + (size_t)(row + 8) * C_ + col) = make_float2(acc[mt][nt][2], acc[mt][nt][3]);
        }
    }
}

// ---------------------------------------------------------------------------
// HMMA fp16 flash attention (causal). BM=128, BN=64, HD=128.
// 256 threads = 8 warps, each warp owns 16 query rows. Q pre-scaled by QSC.
// l computed via ones-column MMA (lacc). Output fp16 -> g_yf.
// ---------------------------------------------------------------------------
#define FST    136                 // smem row stride (fp16 elems), 272B
#define FKV    (64 * FST)
#define FQ     (128 * FST)

__global__ __launch_bounds__(256, 2) void flash_mma()
{
    extern __shared__ __half fsm[];
    __half* sQ  = fsm;                      // [128][FST]
    __half* sKV = sQ + FQ;                  // 2 stages x (K|V)[64][FST]

    const int tid = threadIdx.x, wid = tid >> 5, lane = tid & 31;
    const int qb = gridDim.x - 1 - blockIdx.x;   // big tiles first
    const int h  = blockIdx.y;
    const int b  = blockIdx.z;

    const size_t qrow0 = (size_t)(b * T_ + qb * 128) * C_ + h * HD_;
    const size_t krow0 = (size_t)(b * T_) * C_ + h * HD_;

    for (int i = tid; i < 2048; i += 256) {
        int r = i >> 4, c8 = (i & 15) * 8;
        CP_ASYNC16(smem_u32(sQ + r * FST + c8), g_qf + qrow0 + (size_t)r * C_ + c8);
    }
    auto load_kv = [&](int kt, int s) {
        __half* base = sKV + s * (2 * FKV);
        const size_t kb0 = krow0 + (size_t)(kt * 64) * C_;
        for (int i = tid; i < 1024; i += 256) {
            int r = i >> 4, c8 = (i & 15) * 8;
            size_t go = kb0 + (size_t)r * C_ + c8;
            unsigned off = r * FST + c8;
            CP_ASYNC16(smem_u32(base + off),       g_kf + go);
            CP_ASYNC16(smem_u32(base + FKV + off), g_vf + go);
        }
    };
    load_kv(0, 0);
    CP_COMMIT();
    CP_WAIT0();
    __syncthreads();

    const int g  = lane >> 2;
    const int t4 = lane & 3;
    const int a_row = wid * 16 + (lane & 15);
    const int a_c8  = (lane >> 4) * 8;
    const int b_row = (lane & 7) + ((lane >> 4) << 3);
    const int b_c8  = ((lane >> 3) & 1) * 8;
    const int v_row = lane & 15;
    const int v_c8  = (lane >> 4) * 8;

    // ones B-fragment: column n=0 of an m16n8k16 B tile is all 1.0 (fp16).
    // Lanes 0-3 own (n=0, k=0..15) in both regs; all other lanes hold 0.
    unsigned bones[2];
    bones[0] = bones[1] = (lane < 4) ? 0x3C003C00u : 0u;

    float m0 = -1e30f, m1 = -1e30f;
    float lacc[4] = {0.f, 0.f, 0.f, 0.f};
    float oacc[16][4];
    #pragma unroll
    for (int dt = 0; dt < 16; dt++)
        #pragma unroll
        for (int r = 0; r < 4; r++) oacc[dt][r] = 0.f;

    const int nkt = 2 * qb + 2;

    for (int kt = 0; kt < nkt; kt++) {
        const int s = kt & 1;
        if (kt + 1 < nkt) { load_kv(kt + 1, s ^ 1); CP_COMMIT(); }

        __half* Kh = sKV + s * (2 * FKV);
        __half* Vh = Kh + FKV;

        // --- S = Q K^T (Q pre-scaled by QSC) ---
        float sacc[8][4];
        #pragma unroll
        for (int nt = 0; nt < 8; nt++)
            #pragma unroll
            for (int r = 0; r < 4; r++) sacc[nt][r] = 0.f;

        #pragma unroll
        for (int k16 = 0; k16 < 8; k16++) {
            unsigned ah[4];
            ldmatrix_x4(ah, smem_u32(sQ + a_row * FST + k16 * 16 + a_c8));
            #pragma unroll
            for (int nt2 = 0; nt2 < 4; nt2++) {
                unsigned bh[4];
                ldmatrix_x4(bh, smem_u32(Kh + (nt2 * 16 + b_row) * FST + k16 * 16 + b_c8));
                #pragma unroll
                for (int t = 0; t < 2; t++)
                    mma_f16(sacc[nt2 * 2 + t], ah, bh + 2 * t);
            }
        }

        if (kt >= 2 * qb) {
            const int row0 = qb * 128 + wid * 16 + g;
            #pragma unroll
            for (int nt = 0; nt < 8; nt++) {
                const int col = kt * 64 + nt * 8 + 2 * t4;
                if (col     > row0)     sacc[nt][0] = -1e30f;
                if (col + 1 > row0)     sacc[nt][1] = -1e30f;
                if (col     > row0 + 8) sacc[nt][2] = -1e30f;
                if (col + 1 > row0 + 8) sacc[nt][3] = -1e30f;
            }
        }

        // --- online softmax (max only; l comes from ones-MMA) ---
        float mx0 = -1e30f, mx1 = -1e30f;
        #pragma unroll
        for (int nt = 0; nt < 8; nt++) {
            mx0 = fmaxf(mx0, fmaxf(sacc[nt][0], sacc[nt][1]));
            mx1 = fmaxf(mx1, fmaxf(sacc[nt][2], sacc[nt][3]));
        }
        mx0 = fmaxf(mx0, __shfl_xor_sync(0xffffffffu, mx0, 1));
        mx0 = fmaxf(mx0, __shfl_xor_sync(0xffffffffu, mx0, 2));
        mx1 = fmaxf(mx1, __shfl_xor_sync(0xffffffffu, mx1, 1));
        mx1 = fmaxf(mx1, __shfl_xor_sync(0xffffffffu, mx1, 2));

        float mn0 = fmaxf(m0, mx0), mn1 = fmaxf(m1, mx1);
        float al0 = ex2(m0 - mn0), al1 = ex2(m1 - mn1);
        m0 = mn0; m1 = mn1;

        #pragma unroll
        for (int nt = 0; nt < 8; nt++) {
            sacc[nt][0] = ex2(sacc[nt][0] - mn0);
            sacc[nt][1] = ex2(sacc[nt][1] - mn0);
            sacc[nt][2] = ex2(sacc[nt][2] - mn1);
            sacc[nt][3] = ex2(sacc[nt][3] - mn1);
        }

        lacc[0] *= al0; lacc[2] *= al1;
        #pragma unroll
        for (int dt = 0; dt < 16; dt++) {
            oacc[dt][0] *= al0; oacc[dt][1] *= al0;
            oacc[dt][2] *= al1; oacc[dt][3] *= al1;
        }

        // --- O += P V ; lacc += P * ones ---
        #pragma unroll
        for (int kt2 = 0; kt2 < 4; kt2++) {
            unsigned ph[4];
            #pragma unroll
            for (int half = 0; half < 2; half++) {
                const float* sp = sacc[2 * kt2 + half];
                ph[half * 2 + 0] = pack_h2(sp[0], sp[1]);
                ph[half * 2 + 1] = pack_h2(sp[2], sp[3]);
            }
            mma_f16(lacc, ph, bones);
            #pragma unroll
            for (int dp = 0; dp < 4; dp++) {
                unsigned vh[2][4];
                #pragma unroll
                for (int d = 0; d < 2; d++) {
                    const int dt2 = dp * 2 + d;
                    ldmatrix_x4_trans(vh[d], smem_u32(Vh + (kt2 * 16 + v_row) * FST + dt2 * 16 + v_c8));
                }
                #pragma unroll
                for (int d = 0; d < 2; d++)
                    #pragma unroll
                    for (int n = 0; n < 2; n++)
                        mma_f16(oacc[(dp * 2 + d) * 2 + n], ph, vh[d] + 2 * n);
            }
        }

        if (kt + 1 < nkt) CP_WAIT0();
        __syncthreads();
    }

    // epilogue: broadcast l from ct==0 lanes, normalize, store fp16
    float l0 = __shfl_sync(0xffffffffu, lacc[0], lane & 28);
    float l1 = __shfl_sync(0xffffffffu, lacc[2], lane & 28);
    const float inv0 = 1.f / l0, inv1 = 1.f / l1;
    __half* yb = g_yf + (size_t)(b * T_ + qb * 128 + wid * 16) * C_ + h * HD_;
    #pragma unroll
    for (int dt = 0; dt < 16; dt++) {
        const int col = dt * 8 + 2 * t4;
        *(__half2*)(yb + (size_t)g * C_ + col) =
            __float22half2_rn(make_float2(oacc[dt][0] * inv0, oacc[dt][1] * inv0));
        *(__half2*)(yb + (size_t)(g + 8) * C_ + col) =
            __float22half2_rn(make_float2(oacc[dt][2] * inv1, oacc[dt][3] * inv1));
    }
}

// ---------------------------------------------------------------------------
// Launch
// ---------------------------------------------------------------------------
extern "C" void kernel_launch(void* const* d_in, const int* in_sizes, int n_in,
                              void* d_out, int out_size)
{
    (void)in_sizes; (void)n_in; (void)out_size;
    const float* x     = (const float*)d_in[0];
    const float* ve    = (const float*)d_in[1];
    const float* cosb  = (const float*)d_in[2];
    const float* sinb  = (const float*)d_in[3];
    const float* Wq    = (const float*)d_in[4];
    const float* Wk    = (const float*)d_in[5];
    const float* Wv    = (const float*)d_in[6];
    const float* Wgate = (const float*)d_in[7];
    const float* Wproj = (const float*)d_in[8];
    float* out = (float*)d_out;

    __half *xf, *yf;
    cudaGetSymbolAddress((void**)&xf, g_xf);
    cudaGetSymbolAddress((void**)&yf, g_yf);

    convert_h<<<(M_*C_/4 + 255)/256, 256>>>(x, xf, M_*C_/4);
    transpose_all<<<dim3(C_/32, C_/32, 4), dim3(32, 8)>>>(Wq, Wk, Wv, Wproj);

    const int gemm_smem = NSTAGE * STAGE_E * (int)sizeof(__half);  // 110592 B
    cudaFuncSetAttribute(gemm_qkv_fused, cudaFuncAttributeMaxDynamicSharedMemorySize, gemm_smem);
    cudaFuncSetAttribute(gemm_proj,      cudaFuncAttributeMaxDynamicSharedMemorySize, gemm_smem);
    gemm_qkv_fused<<<dim3(C_/128, M_/128, 3), 256, gemm_smem>>>(xf, x, ve, cosb, sinb, Wgate);

    const int fsmem = (FQ + 4 * FKV) * (int)sizeof(__half);  // 104448 B
    cudaFuncSetAttribute(flash_mma, cudaFuncAttributeMaxDynamicSharedMemorySize, fsmem);
    flash_mma<<<dim3(T_/128, NH_, B_), 256, fsmem>>>();

    gemm_proj<<<dim3(C_/128, M_/128), 256, gemm_smem>>>(yf, out);
}

// round 10
// speedup vs baseline: 7.3651x; 1.0185x over previous
#include <cuda_runtime.h>
#include <cuda_fp16.h>
#include <math.h>

// Problem constants
#define B_       2
#define T_       2048
#define C_       2048
#define NH_      16
#define HD_      128
#define GATE_CH_ 32
#define M_       (B_*T_)   // 4096 rows

// ---------------------------------------------------------------------------
// Scratch (device globals: allocation-free per harness rules)
// ---------------------------------------------------------------------------
__device__ __half g_xf[(size_t)M_*C_];
__device__ __half g_yf[(size_t)M_*C_];
__device__ __half g_qf[(size_t)M_*C_];
__device__ __half g_kf[(size_t)M_*C_];
__device__ __half g_vf[(size_t)M_*C_];
__device__ __half g_wt[4][(size_t)C_*C_];   // transposed [N][K] Wq,Wk,Wv,Wproj

// ---------------------------------------------------------------------------
// PTX helpers
// ---------------------------------------------------------------------------
__device__ __forceinline__ unsigned smem_u32(const void* p) {
    unsigned a;
    asm("{ .reg .u64 t; cvta.to.shared.u64 t, %1; cvt.u32.u64 %0, t; }"
        : "=r"(a) : "l"(p));
    return a;
}

#define CP_ASYNC16(dst_u32, src_ptr) \
    asm volatile("cp.async.cg.shared.global [%0], [%1], 16;" \
                 :: "r"(dst_u32), "l"(src_ptr))
#define CP_COMMIT() asm volatile("cp.async.commit_group;" ::: "memory")
#define CP_WAIT0()  asm volatile("cp.async.wait_group 0;" ::: "memory")
#define CP_WAIT1()  asm volatile("cp.async.wait_group 1;" ::: "memory")
#define CP_WAIT2()  asm volatile("cp.async.wait_group 2;" ::: "memory")

__device__ __forceinline__ void ldmatrix_x4(unsigned* r, unsigned addr) {
    asm volatile("ldmatrix.sync.aligned.m8n8.x4.shared.b16 {%0,%1,%2,%3}, [%4];"
                 : "=r"(r[0]), "=r"(r[1]), "=r"(r[2]), "=r"(r[3]) : "r"(addr));
}
__device__ __forceinline__ void ldmatrix_x4_trans(unsigned* r, unsigned addr) {
    asm volatile("ldmatrix.sync.aligned.m8n8.x4.trans.shared.b16 {%0,%1,%2,%3}, [%4];"
                 : "=r"(r[0]), "=r"(r[1]), "=r"(r[2]), "=r"(r[3]) : "r"(addr));
}
__device__ __forceinline__ void mma_f16(float* c, const unsigned* a, const unsigned* b) {
    asm volatile(
        "mma.sync.aligned.m16n8k16.row.col.f32.f16.f16.f32 "
        "{%0,%1,%2,%3}, {%4,%5,%6,%7}, {%8,%9}, {%0,%1,%2,%3};"
        : "+f"(c[0]), "+f"(c[1]), "+f"(c[2]), "+f"(c[3])
        : "r"(a[0]), "r"(a[1]), "r"(a[2]), "r"(a[3]), "r"(b[0]), "r"(b[1]));
}
__device__ __forceinline__ unsigned pack_h2(float lo, float hi) {
    __half2 h = __float22half2_rn(make_float2(lo, hi));
    return *reinterpret_cast<unsigned*>(&h);
}
__device__ __forceinline__ float ex2(float x) {
    float y;
    asm("ex2.approx.f32 %0, %1;" : "=f"(y) : "f"(x));
    return y;
}
__device__ __forceinline__ float warp_sum(float v) {
    #pragma unroll
    for (int d = 16; d >= 1; d >>= 1) v += __shfl_xor_sync(0xffffffffu, v, d);
    return v;
}

// scale * log2(e), folded into q at QKV epilogue
#define QSC (0.08838834764831845f * 1.4426950408889634f)
// fixed softmax reference (log2 units). |t| <= 16.33 by Cauchy-Schwarz on
// RMS-normed q,k, so p = 2^(t-5) in [2^-21.3, 2^11.3]: provably no fp16
// overflow and no subnormal flush-to-zero of any term.
#define FMAX_REF 5.0f

// ---------------------------------------------------------------------------
// convert_h: fp32 -> fp16
// ---------------------------------------------------------------------------
__global__ __launch_bounds__(256) void convert_h(
    const float* __restrict__ in, __half* __restrict__ out, int n4)
{
    int i = blockIdx.x * blockDim.x + threadIdx.x;
    if (i >= n4) return;
    float4 v = ((const float4*)in)[i];
    __half2* op = (__half2*)(out + (size_t)i * 4);
    op[0] = __float22half2_rn(make_float2(v.x, v.y));
    op[1] = __float22half2_rn(make_float2(v.z, v.w));
}

// ---------------------------------------------------------------------------
// transpose_all: W[K][N] fp32 -> g_wt[z][N][K] fp16 (z = blockIdx.z)
// ---------------------------------------------------------------------------
__global__ __launch_bounds__(256) void transpose_all(
    const float* __restrict__ Wq, const float* __restrict__ Wk,
    const float* __restrict__ Wv, const float* __restrict__ Wproj)
{
    __shared__ float tile[32][33];
    const int z = blockIdx.z;
    const float* W = (z == 0) ? Wq : (z == 1) ? Wk : (z == 2) ? Wv : Wproj;
    __half* out = g_wt[z];
    int k0 = blockIdx.y * 32, n0 = blockIdx.x * 32;
    int tx = threadIdx.x, ty = threadIdx.y;  // block (32, 8)
    #pragma unroll
    for (int r = 0; r < 4; r++)
        tile[ty + 8 * r][tx] = W[(size_t)(k0 + ty + 8 * r) * C_ + n0 + tx];
    __syncthreads();
    #pragma unroll
    for (int r = 0; r < 4; r++) {
        float v = tile[tx][ty + 8 * r];
        out[(size_t)(n0 + ty + 8 * r) * C_ + k0 + tx] = __float2half(v);
    }
}

// ---------------------------------------------------------------------------
// HMMA fp16 GEMM mainloop. 128x128 CTA tile, 8 warps (4x2), k-chunk 64,
// cp.async 3-stage pipeline, batched B fragments.
// ---------------------------------------------------------------------------
#define KC        64
#define AS_STRIDE 72                        // fp16 elems per smem row (144B)
#define TILE_E    (128 * AS_STRIDE)         // 9216 elems
#define STAGE_E   (2 * TILE_E)              // A | B
#define NSTAGE    3

__device__ __forceinline__ void gemm_mainloop(
    const __half* __restrict__ A, const __half* __restrict__ Bm,
    int m0, int n0, int K, __half* smb, float acc[2][8][4])
{
    const int tid = threadIdx.x, wid = tid >> 5, lane = tid & 31;
    const int NCH = K / KC;
    const int wm = wid & 3;
    const int wn = wid >> 2;

    auto load_stage = [&](int c, int s) {
        const int k0 = c * KC;
        __half* base = smb + s * STAGE_E;
        #pragma unroll
        for (int i = 0; i < 4; i++) {
            int cidx = tid + i * 256;          // 0..1023
            int row  = cidx >> 3;
            int col8 = (cidx & 7) * 8;
            unsigned so = smem_u32(base + row * AS_STRIDE + col8);
            CP_ASYNC16(so,              A  + (size_t)(m0 + row) * K + k0 + col8);
            CP_ASYNC16(so + TILE_E * 2, Bm + (size_t)(n0 + row) * K + k0 + col8);
        }
    };

    #pragma unroll
    for (int mt = 0; mt < 2; mt++)
        #pragma unroll
        for (int nt = 0; nt < 8; nt++)
            #pragma unroll
            for (int r = 0; r < 4; r++) acc[mt][nt][r] = 0.f;

    load_stage(0, 0);
    CP_COMMIT();
    load_stage(1, 1);
    CP_COMMIT();

    const int a_row = wm * 32 + (lane & 15);
    const int a_k8  = (lane >> 4) * 8;
    const int b_r   = lane & 7;
    const int b_grp = lane >> 3;
    const int b_row = wn * 64 + (b_grp >> 1) * 8 + b_r;
    const int b_k8  = (b_grp & 1) * 8;

    for (int c = 0; c < NCH; c++) {
        if (c + 2 < NCH) {
            load_stage(c + 2, (c + 2) % NSTAGE);
            CP_COMMIT();
            CP_WAIT2();
        } else if (c + 1 < NCH) {
            CP_WAIT1();
        } else {
            CP_WAIT0();
        }
        __syncthreads();

        const __half* st = smb + (c % NSTAGE) * STAGE_E;
        const __half* sA = st;
        const __half* sB = st + TILE_E;

        #pragma unroll
        for (int k16 = 0; k16 < 4; k16++) {
            const int kb = k16 * 16;
            unsigned ah[2][4];
            #pragma unroll
            for (int mt = 0; mt < 2; mt++)
                ldmatrix_x4(ah[mt], smem_u32(sA + (a_row + mt * 16) * AS_STRIDE + kb + a_k8));
            unsigned bh[4][4];
            #pragma unroll
            for (int j = 0; j < 4; j++)
                ldmatrix_x4(bh[j], smem_u32(sB + (b_row + j * 16) * AS_STRIDE + kb + b_k8));
            #pragma unroll
            for (int j = 0; j < 4; j++)
                #pragma unroll
                for (int t = 0; t < 2; t++)
                    #pragma unroll
                    for (int mt = 0; mt < 2; mt++)
                        mma_f16(acc[mt][j * 2 + t], ah[mt], bh[j] + t * 2);
        }
        __syncthreads();
    }
}

// ---------------------------------------------------------------------------
// Fused QKV GEMM + prep epilogue. z=0: q (rope+rms, pre-scaled by QSC);
// z=1: k (rope+rms); z=2: v + gate*ve. 128 cols per tile = one full head.
// ---------------------------------------------------------------------------
#define EST 130   // fp32 epilogue smem row stride

__global__ __launch_bounds__(256, 2) void gemm_qkv_fused(
    const __half* __restrict__ A,
    const float* __restrict__ x, const float* __restrict__ ve,
    const float* __restrict__ cosb, const float* __restrict__ sinb,
    const float* __restrict__ Wgate)
{
    extern __shared__ __half smb[];
    const int z = blockIdx.z;
    const int m0 = blockIdx.y * 128, n0 = blockIdx.x * 128;

    float acc[2][8][4];
    gemm_mainloop(A, g_wt[z], m0, n0, C_, smb, acc);

    // spill fp32 tile to smem (stage buffers are free now)
    const int tid = threadIdx.x, wid = tid >> 5, lane = tid & 31;
    const int wm = wid & 3, wn = wid >> 2;
    const int cg = lane >> 2, ct = lane & 3;
    float* ft = (float*)smb;
    #pragma unroll
    for (int mt = 0; mt < 2; mt++) {
        const int r = wm * 32 + mt * 16 + cg;
        #pragma unroll
        for (int nt = 0; nt < 8; nt++) {
            const int cc = wn * 64 + nt * 8 + ct * 2;
            ft[r * EST + cc]           = acc[mt][nt][0];
            ft[r * EST + cc + 1]       = acc[mt][nt][1];
            ft[(r + 8) * EST + cc]     = acc[mt][nt][2];
            ft[(r + 8) * EST + cc + 1] = acc[mt][nt][3];
        }
    }
    __syncthreads();

    const int h = n0 >> 7;   // head index
    if (z < 2) {
        __half* gout = (z == 0) ? g_qf : g_kf;
        const float post = (z == 0) ? QSC : 1.f;
        for (int rr = 0; rr < 16; rr++) {
            const int r = wid * 16 + rr;
            const int row = m0 + r;
            const int t = row & (T_ - 1);
            const float* fr = ft + r * EST;
            const float* cr = cosb + (size_t)t * 64;
            const float* sr = sinb + (size_t)t * 64;
            const int d0 = lane, d1 = lane + 32;
            float x1a = fr[d0], x2a = fr[d0 + 64];
            float x1b = fr[d1], x2b = fr[d1 + 64];
            float ca = cr[d0], sa = sr[d0], cb = cr[d1], sb = sr[d1];
            float o1a =  x1a * ca + x2a * sa;
            float o2a = -x1a * sa + x2a * ca;
            float o1b =  x1b * cb + x2b * sb;
            float o2b = -x1b * sb + x2b * cb;
            float ss = warp_sum(o1a*o1a + o2a*o2a + o1b*o1b + o2b*o2b);
            float rn = rsqrtf(ss * (1.f / 128.f) + 1e-6f) * post;
            __half* dst = gout + (size_t)row * C_ + n0;
            dst[d0]      = __float2half(o1a * rn);
            dst[d0 + 64] = __float2half(o2a * rn);
            dst[d1]      = __float2half(o1b * rn);
            dst[d1 + 64] = __float2half(o2b * rn);
        }
    } else {
        for (int rr = 0; rr < 16; rr++) {
            const int r = wid * 16 + rr;
            const int row = m0 + r;
            const float* fr = ft + r * EST;
            float sg = warp_sum(x[(size_t)row * C_ + lane] * Wgate[lane * NH_ + h]);
            float gt = 2.f / (1.f + __expf(-sg));
            __half* dst = g_vf + (size_t)row * C_ + n0;
            const float* vep = ve + (size_t)row * C_ + n0;
            #pragma unroll
            for (int i2 = 0; i2 < 4; i2++) {
                const int d = lane + i2 * 32;
                dst[d] = __float2half(fr[d] + gt * vep[d]);
            }
        }
    }
}

// proj GEMM: plain fp32 epilogue to out
__global__ __launch_bounds__(256, 2) void gemm_proj(
    const __half* __restrict__ A, float* __restrict__ Cm)
{
    extern __shared__ __half smb[];
    const int m0 = blockIdx.y * 128, n0 = blockIdx.x * 128;
    float acc[2][8][4];
    gemm_mainloop(A, g_wt[3], m0, n0, C_, smb, acc);

    const int tid = threadIdx.x, wid = tid >> 5, lane = tid & 31;
    const int wm = wid & 3, wn = wid >> 2;
    const int cg = lane >> 2, ct = lane & 3;
    #pragma unroll
    for (int mt = 0; mt < 2; mt++) {
        const int row = m0 + wm * 32 + mt * 16 + cg;
        #pragma unroll
        for (int nt = 0; nt < 8; nt++) {
            const int col = n0 + wn * 64 + nt * 8 + ct * 2;
            *(float2*)(Cm + (size_t)row * C_ + col)       = make_float2(acc[mt][nt][0], acc[mt][nt][1]);
            *(float2*)(Cm + (size_t)(row + 8) * C_ + col) = make_float2(acc[mt][nt][2], acc[mt][nt][3]);
        }
    }
}

// ---------------------------------------------------------------------------
// HMMA fp16 flash attention (causal). BM=128, BN=64, HD=128.
// Fixed-reference softmax (no online max/rescale): p = 2^(t - FMAX_REF),
// provably safe in fp16 because q,k are RMS-normalized (|t| <= 16.33).
// l via ones-column MMA. Output fp16 -> g_yf.
// ---------------------------------------------------------------------------
#define FST    136                 // smem row stride (fp16 elems), 272B
#define FKV    (64 * FST)
#define FQ     (128 * FST)

__global__ __launch_bounds__(256, 2) void flash_mma()
{
    extern __shared__ __half fsm[];
    __half* sQ  = fsm;                      // [128][FST]
    __half* sKV = sQ + FQ;                  // 2 stages x (K|V)[64][FST]

    const int tid = threadIdx.x, wid = tid >> 5, lane = tid & 31;
    const int qb = gridDim.x - 1 - blockIdx.x;   // big tiles first
    const int h  = blockIdx.y;
    const int b  = blockIdx.z;

    const size_t qrow0 = (size_t)(b * T_ + qb * 128) * C_ + h * HD_;
    const size_t krow0 = (size_t)(b * T_) * C_ + h * HD_;

    for (int i = tid; i < 2048; i += 256) {
        int r = i >> 4, c8 = (i & 15) * 8;
        CP_ASYNC16(smem_u32(sQ + r * FST + c8), g_qf + qrow0 + (size_t)r * C_ + c8);
    }
    auto load_kv = [&](int kt, int s) {
        __half* base = sKV + s * (2 * FKV);
        const size_t kb0 = krow0 + (size_t)(kt * 64) * C_;
        for (int i = tid; i < 1024; i += 256) {
            int r = i >> 4, c8 = (i & 15) * 8;
            size_t go = kb0 + (size_t)r * C_ + c8;
            unsigned off = r * FST + c8;
            CP_ASYNC16(smem_u32(base + off),       g_kf + go);
            CP_ASYNC16(smem_u32(base + FKV + off), g_vf + go);
        }
    };
    load_kv(0, 0);
    CP_COMMIT();
    CP_WAIT0();
    __syncthreads();

    const int g  = lane >> 2;
    const int t4 = lane & 3;
    const int a_row = wid * 16 + (lane & 15);
    const int a_c8  = (lane >> 4) * 8;
    const int b_row = (lane & 7) + ((lane >> 4) << 3);
    const int b_c8  = ((lane >> 3) & 1) * 8;
    const int v_row = lane & 15;
    const int v_c8  = (lane >> 4) * 8;

    // ones B-fragment: column n=0 of an m16n8k16 B tile is all 1.0 (fp16).
    unsigned bones[2];
    bones[0] = bones[1] = (lane < 4) ? 0x3C003C00u : 0u;

    float lacc[4] = {0.f, 0.f, 0.f, 0.f};
    float oacc[16][4];
    #pragma unroll
    for (int dt = 0; dt < 16; dt++)
        #pragma unroll
        for (int r = 0; r < 4; r++) oacc[dt][r] = 0.f;

    const int nkt = 2 * qb + 2;

    for (int kt = 0; kt < nkt; kt++) {
        const int s = kt & 1;
        if (kt + 1 < nkt) { load_kv(kt + 1, s ^ 1); CP_COMMIT(); }

        __half* Kh = sKV + s * (2 * FKV);
        __half* Vh = Kh + FKV;

        // --- S = Q K^T (Q pre-scaled by QSC) ---
        float sacc[8][4];
        #pragma unroll
        for (int nt = 0; nt < 8; nt++)
            #pragma unroll
            for (int r = 0; r < 4; r++) sacc[nt][r] = 0.f;

        #pragma unroll
        for (int k16 = 0; k16 < 8; k16++) {
            unsigned ah[4];
            ldmatrix_x4(ah, smem_u32(sQ + a_row * FST + k16 * 16 + a_c8));
            #pragma unroll
            for (int nt2 = 0; nt2 < 4; nt2++) {
                unsigned bh[4];
                ldmatrix_x4(bh, smem_u32(Kh + (nt2 * 16 + b_row) * FST + k16 * 16 + b_c8));
                #pragma unroll
                for (int t = 0; t < 2; t++)
                    mma_f16(sacc[nt2 * 2 + t], ah, bh + 2 * t);
            }
        }

        if (kt >= 2 * qb) {
            const int row0 = qb * 128 + wid * 16 + g;
            #pragma unroll
            for (int nt = 0; nt < 8; nt++) {
                const int col = kt * 64 + nt * 8 + 2 * t4;
                if (col     > row0)     sacc[nt][0] = -1e30f;
                if (col + 1 > row0)     sacc[nt][1] = -1e30f;
                if (col     > row0 + 8) sacc[nt][2] = -1e30f;
                if (col + 1 > row0 + 8) sacc[nt][3] = -1e30f;
            }
        }

        // --- p = 2^(t - FMAX_REF); no max reduce, no rescale ---
        #pragma unroll
        for (int nt = 0; nt < 8; nt++) {
            sacc[nt][0] = ex2(sacc[nt][0] - FMAX_REF);
            sacc[nt][1] = ex2(sacc[nt][1] - FMAX_REF);
            sacc[nt][2] = ex2(sacc[nt][2] - FMAX_REF);
            sacc[nt][3] = ex2(sacc[nt][3] - FMAX_REF);
        }

        // --- O += P V ; lacc += P * ones ---
        #pragma unroll
        for (int kt2 = 0; kt2 < 4; kt2++) {
            unsigned ph[4];
            #pragma unroll
            for (int half = 0; half < 2; half++) {
                const float* sp = sacc[2 * kt2 + half];
                ph[half * 2 + 0] = pack_h2(sp[0], sp[1]);
                ph[half * 2 + 1] = pack_h2(sp[2], sp[3]);
            }
            mma_f16(lacc, ph, bones);
            #pragma unroll
            for (int dp = 0; dp < 4; dp++) {
                unsigned vh[2][4];
                #pragma unroll
                for (int d = 0; d < 2; d++) {
                    const int dt2 = dp * 2 + d;
                    ldmatrix_x4_trans(vh[d], smem_u32(Vh + (kt2 * 16 + v_row) * FST + dt2 * 16 + v_c8));
                }
                #pragma unroll
                for (int d = 0; d < 2; d++)
                    #pragma unroll
                    for (int n = 0; n < 2; n++)
                        mma_f16(oacc[(dp * 2 + d) * 2 + n], ph, vh[d] + 2 * n);
            }
        }

        if (kt + 1 < nkt) CP_WAIT0();
        __syncthreads();
    }

    // epilogue: broadcast l from ct==0 lanes, normalize, store fp16
    float l0 = __shfl_sync(0xffffffffu, lacc[0], lane & 28);
    float l1 = __shfl_sync(0xffffffffu, lacc[2], lane & 28);
    const float inv0 = 1.f / l0, inv1 = 1.f / l1;
    __half* yb = g_yf + (size_t)(b * T_ + qb * 128 + wid * 16) * C_ + h * HD_;
    #pragma unroll
    for (int dt = 0; dt < 16; dt++) {
        const int col = dt * 8 + 2 * t4;
        *(__half2*)(yb + (size_t)g * C_ + col) =
            __float22half2_rn(make_float2(oacc[dt][0] * inv0, oacc[dt][1] * inv0));
        *(__half2*)(yb + (size_t)(g + 8) * C_ + col) =
            __float22half2_rn(make_float2(oacc[dt][2] * inv1, oacc[dt][3] * inv1));
    }
}

// ---------------------------------------------------------------------------
// Launch
// ---------------------------------------------------------------------------
extern "C" void kernel_launch(void* const* d_in, const int* in_sizes, int n_in,
                              void* d_out, int out_size)
{
    (void)in_sizes; (void)n_in; (void)out_size;
    const float* x     = (const float*)d_in[0];
    const float* ve    = (const float*)d_in[1];
    const float* cosb  = (const float*)d_in[2];
    const float* sinb  = (const float*)d_in[3];
    const float* Wq    = (const float*)d_in[4];
    const float* Wk    = (const float*)d_in[5];
    const float* Wv    = (const float*)d_in[6];
    const float* Wgate = (const float*)d_in[7];
    const float* Wproj = (const float*)d_in[8];
    float* out = (float*)d_out;

    __half *xf, *yf;
    cudaGetSymbolAddress((void**)&xf, g_xf);
    cudaGetSymbolAddress((void**)&yf, g_yf);

    convert_h<<<(M_*C_/4 + 255)/256, 256>>>(x, xf, M_*C_/4);
    transpose_all<<<dim3(C_/32, C_/32, 4), dim3(32, 8)>>>(Wq, Wk, Wv, Wproj);

    const int gemm_smem = NSTAGE * STAGE_E * (int)sizeof(__half);  // 110592 B
    cudaFuncSetAttribute(gemm_qkv_fused, cudaFuncAttributeMaxDynamicSharedMemorySize, gemm_smem);
    cudaFuncSetAttribute(gemm_proj,      cudaFuncAttributeMaxDynamicSharedMemorySize, gemm_smem);
    gemm_qkv_fused<<<dim3(C_/128, M_/128, 3), 256, gemm_smem>>>(xf, x, ve, cosb, sinb, Wgate);

    const int fsmem = (FQ + 4 * FKV) * (int)sizeof(__half);  // 104448 B
    cudaFuncSetAttribute(flash_mma, cudaFuncAttributeMaxDynamicSharedMemorySize, fsmem);
    flash_mma<<<dim3(T_/128, NH_, B_), 256, fsmem>>>();

    gemm_proj<<<dim3(C_/128, M_/128), 256, gemm_smem>>>(yf, out);
}

// round 11
// speedup vs baseline: 8.5368x; 1.1591x over previous
#include <cuda_runtime.h>
#include <cuda_fp16.h>
#include <math.h>

// Problem constants
#define B_       2
#define T_       2048
#define C_       2048
#define NH_      16
#define HD_      128
#define GATE_CH_ 32
#define M_       (B_*T_)   // 4096 rows

// ---------------------------------------------------------------------------
// Scratch (device globals: allocation-free per harness rules)
// ---------------------------------------------------------------------------
__device__ __half g_xf[(size_t)M_*C_];
__device__ __half g_yf[(size_t)M_*C_];
__device__ __half g_qf[(size_t)M_*C_];
__device__ __half g_kf[(size_t)M_*C_];
__device__ __half g_vf[(size_t)M_*C_];
__device__ __half g_wt[4][(size_t)C_*C_];   // transposed [N][K] Wq,Wk,Wv,Wproj

// ---------------------------------------------------------------------------
// PTX helpers
// ---------------------------------------------------------------------------
__device__ __forceinline__ unsigned smem_u32(const void* p) {
    unsigned a;
    asm("{ .reg .u64 t; cvta.to.shared.u64 t, %1; cvt.u32.u64 %0, t; }"
        : "=r"(a) : "l"(p));
    return a;
}

#define CP_ASYNC16(dst_u32, src_ptr) \
    asm volatile("cp.async.cg.shared.global [%0], [%1], 16;" \
                 :: "r"(dst_u32), "l"(src_ptr))
#define CP_COMMIT() asm volatile("cp.async.commit_group;" ::: "memory")
#define CP_WAIT0()  asm volatile("cp.async.wait_group 0;" ::: "memory")
#define CP_WAIT1()  asm volatile("cp.async.wait_group 1;" ::: "memory")

__device__ __forceinline__ void ldmatrix_x4(unsigned* r, unsigned addr) {
    asm volatile("ldmatrix.sync.aligned.m8n8.x4.shared.b16 {%0,%1,%2,%3}, [%4];"
                 : "=r"(r[0]), "=r"(r[1]), "=r"(r[2]), "=r"(r[3]) : "r"(addr));
}
__device__ __forceinline__ void ldmatrix_x4_trans(unsigned* r, unsigned addr) {
    asm volatile("ldmatrix.sync.aligned.m8n8.x4.trans.shared.b16 {%0,%1,%2,%3}, [%4];"
                 : "=r"(r[0]), "=r"(r[1]), "=r"(r[2]), "=r"(r[3]) : "r"(addr));
}
__device__ __forceinline__ void mma_f16(float* c, const unsigned* a, const unsigned* b) {
    asm volatile(
        "mma.sync.aligned.m16n8k16.row.col.f32.f16.f16.f32 "
        "{%0,%1,%2,%3}, {%4,%5,%6,%7}, {%8,%9}, {%0,%1,%2,%3};"
        : "+f"(c[0]), "+f"(c[1]), "+f"(c[2]), "+f"(c[3])
        : "r"(a[0]), "r"(a[1]), "r"(a[2]), "r"(a[3]), "r"(b[0]), "r"(b[1]));
}
__device__ __forceinline__ unsigned pack_h2(float lo, float hi) {
    __half2 h = __float22half2_rn(make_float2(lo, hi));
    return *reinterpret_cast<unsigned*>(&h);
}
__device__ __forceinline__ float ex2(float x) {
    float y;
    asm("ex2.approx.f32 %0, %1;" : "=f"(y) : "f"(x));
    return y;
}
__device__ __forceinline__ float warp_sum(float v) {
    #pragma unroll
    for (int d = 16; d >= 1; d >>= 1) v += __shfl_xor_sync(0xffffffffu, v, d);
    return v;
}

// scale * log2(e), folded into q at QKV epilogue
#define QSC (0.08838834764831845f * 1.4426950408889634f)
// fixed softmax reference (log2 units). |t| <= 16.33 by Cauchy-Schwarz on
// RMS-normed q,k, so p = 2^(t-5) in [2^-21.3, 2^11.3]: provably no fp16
// overflow and no subnormal flush-to-zero of any term.
#define FMAX_REF 5.0f

// ---------------------------------------------------------------------------
// prep_inputs: z<4: transpose W[K][N] fp32 -> g_wt[z][N][K] fp16;
//              z=4: convert x fp32 -> g_xf fp16.
// grid (64, 64, 5), block (32, 8).
// ---------------------------------------------------------------------------
__global__ __launch_bounds__(256) void prep_inputs(
    const float* __restrict__ x,
    const float* __restrict__ Wq, const float* __restrict__ Wk,
    const float* __restrict__ Wv, const float* __restrict__ Wproj)
{
    __shared__ float tile[32][33];
    const int z = blockIdx.z;
    const int tid = threadIdx.y * 32 + threadIdx.x;

    if (z == 4) {
        // convert x: 2,097,152 float4 over 4096 blocks x 256 thr = 2 each
        const int idx0 = (blockIdx.y * 64 + blockIdx.x) * 256 + tid;
        #pragma unroll
        for (int r = 0; r < 2; r++) {
            const int i = idx0 + r * (64 * 64 * 256);
            float4 v = ((const float4*)x)[i];
            __half2* op = (__half2*)(g_xf + (size_t)i * 4);
            op[0] = __float22half2_rn(make_float2(v.x, v.y));
            op[1] = __float22half2_rn(make_float2(v.z, v.w));
        }
        return;
    }

    const float* W = (z == 0) ? Wq : (z == 1) ? Wk : (z == 2) ? Wv : Wproj;
    __half* out = g_wt[z];
    int k0 = blockIdx.y * 32, n0 = blockIdx.x * 32;
    int tx = threadIdx.x, ty = threadIdx.y;
    #pragma unroll
    for (int r = 0; r < 4; r++)
        tile[ty + 8 * r][tx] = W[(size_t)(k0 + ty + 8 * r) * C_ + n0 + tx];
    __syncthreads();
    #pragma unroll
    for (int r = 0; r < 4; r++) {
        float v = tile[tx][ty + 8 * r];
        out[(size_t)(n0 + ty + 8 * r) * C_ + k0 + tx] = __float2half(v);
    }
}

// ---------------------------------------------------------------------------
// HMMA fp16 GEMM mainloop. 128x128 CTA tile, 8 warps (4x2), k-chunk 64,
// cp.async 3-stage pipeline. Loads for chunk c+2 are spread across the four
// k16 MMA blocks; ONE barrier per chunk (write target c+2 == c-1 mod 3 is
// protected by the top barrier).
// ---------------------------------------------------------------------------
#define KC        64
#define AS_STRIDE 72                        // fp16 elems per smem row (144B)
#define TILE_E    (128 * AS_STRIDE)         // 9216 elems
#define STAGE_E   (2 * TILE_E)              // A | B
#define NSTAGE    3

__device__ __forceinline__ void gemm_mainloop(
    const __half* __restrict__ A, const __half* __restrict__ Bm,
    int m0, int n0, int K, __half* smb, float acc[2][8][4])
{
    const int tid = threadIdx.x, wid = tid >> 5, lane = tid & 31;
    const int NCH = K / KC;
    const int wm = wid & 3;
    const int wn = wid >> 2;

    auto load_slice = [&](int c, int s, int i) {
        const int k0 = c * KC;
        __half* base = smb + s * STAGE_E;
        int cidx = tid + i * 256;          // 0..1023
        int row  = cidx >> 3;
        int col8 = (cidx & 7) * 8;
        unsigned so = smem_u32(base + row * AS_STRIDE + col8);
        CP_ASYNC16(so,              A  + (size_t)(m0 + row) * K + k0 + col8);
        CP_ASYNC16(so + TILE_E * 2, Bm + (size_t)(n0 + row) * K + k0 + col8);
    };

    #pragma unroll
    for (int mt = 0; mt < 2; mt++)
        #pragma unroll
        for (int nt = 0; nt < 8; nt++)
            #pragma unroll
            for (int r = 0; r < 4; r++) acc[mt][nt][r] = 0.f;

    #pragma unroll
    for (int i = 0; i < 4; i++) load_slice(0, 0, i);
    CP_COMMIT();
    #pragma unroll
    for (int i = 0; i < 4; i++) load_slice(1, 1, i);
    CP_COMMIT();

    const int a_row = wm * 32 + (lane & 15);
    const int a_k8  = (lane >> 4) * 8;
    const int b_r   = lane & 7;
    const int b_grp = lane >> 3;
    const int b_row = wn * 64 + (b_grp >> 1) * 8 + b_r;
    const int b_k8  = (b_grp & 1) * 8;

    for (int c = 0; c < NCH; c++) {
        if (c + 1 < NCH) CP_WAIT1();
        else             CP_WAIT0();
        __syncthreads();

        const __half* st = smb + (c % NSTAGE) * STAGE_E;
        const __half* sA = st;
        const __half* sB = st + TILE_E;
        const bool pf = (c + 2 < NCH);
        const int  ps = (c + 2) % NSTAGE;

        #pragma unroll
        for (int k16 = 0; k16 < 4; k16++) {
            if (pf) load_slice(c + 2, ps, k16);
            const int kb = k16 * 16;
            unsigned ah[2][4];
            #pragma unroll
            for (int mt = 0; mt < 2; mt++)
                ldmatrix_x4(ah[mt], smem_u32(sA + (a_row + mt * 16) * AS_STRIDE + kb + a_k8));
            unsigned bh[4][4];
            #pragma unroll
            for (int j = 0; j < 4; j++)
                ldmatrix_x4(bh[j], smem_u32(sB + (b_row + j * 16) * AS_STRIDE + kb + b_k8));
            #pragma unroll
            for (int j = 0; j < 4; j++)
                #pragma unroll
                for (int t = 0; t < 2; t++)
                    #pragma unroll
                    for (int mt = 0; mt < 2; mt++)
                        mma_f16(acc[mt][j * 2 + t], ah[mt], bh[j] + t * 2);
        }
        if (pf) CP_COMMIT();
    }
    __syncthreads();   // protect epilogue smem reuse
}

// ---------------------------------------------------------------------------
// Fused QKV GEMM + prep epilogue. z=0: q (rope+rms, pre-scaled by QSC);
// z=1: k (rope+rms); z=2: v + gate*ve. 128 cols per tile = one full head.
// ---------------------------------------------------------------------------
#define EST 130   // fp32 epilogue smem row stride

__global__ __launch_bounds__(256, 2) void gemm_qkv_fused(
    const __half* __restrict__ A,
    const float* __restrict__ x, const float* __restrict__ ve,
    const float* __restrict__ cosb, const float* __restrict__ sinb,
    const float* __restrict__ Wgate)
{
    extern __shared__ __half smb[];
    const int z = blockIdx.z;
    const int m0 = blockIdx.y * 128, n0 = blockIdx.x * 128;

    float acc[2][8][4];
    gemm_mainloop(A, g_wt[z], m0, n0, C_, smb, acc);

    // spill fp32 tile to smem (stage buffers are free now)
    const int tid = threadIdx.x, wid = tid >> 5, lane = tid & 31;
    const int wm = wid & 3, wn = wid >> 2;
    const int cg = lane >> 2, ct = lane & 3;
    float* ft = (float*)smb;
    #pragma unroll
    for (int mt = 0; mt < 2; mt++) {
        const int r = wm * 32 + mt * 16 + cg;
        #pragma unroll
        for (int nt = 0; nt < 8; nt++) {
            const int cc = wn * 64 + nt * 8 + ct * 2;
            ft[r * EST + cc]           = acc[mt][nt][0];
            ft[r * EST + cc + 1]       = acc[mt][nt][1];
            ft[(r + 8) * EST + cc]     = acc[mt][nt][2];
            ft[(r + 8) * EST + cc + 1] = acc[mt][nt][3];
        }
    }
    __syncthreads();

    const int h = n0 >> 7;   // head index
    if (z < 2) {
        __half* gout = (z == 0) ? g_qf : g_kf;
        const float post = (z == 0) ? QSC : 1.f;
        for (int rr = 0; rr < 16; rr++) {
            const int r = wid * 16 + rr;
            const int row = m0 + r;
            const int t = row & (T_ - 1);
            const float* fr = ft + r * EST;
            const float* cr = cosb + (size_t)t * 64;
            const float* sr = sinb + (size_t)t * 64;
            const int d0 = lane, d1 = lane + 32;
            float x1a = fr[d0], x2a = fr[d0 + 64];
            float x1b = fr[d1], x2b = fr[d1 + 64];
            float ca = cr[d0], sa = sr[d0], cb = cr[d1], sb = sr[d1];
            float o1a =  x1a * ca + x2a * sa;
            float o2a = -x1a * sa + x2a * ca;
            float o1b =  x1b * cb + x2b * sb;
            float o2b = -x1b * sb + x2b * cb;
            float ss = warp_sum(o1a*o1a + o2a*o2a + o1b*o1b + o2b*o2b);
            float rn = rsqrtf(ss * (1.f / 128.f) + 1e-6f) * post;
            __half* dst = gout + (size_t)row * C_ + n0;
            dst[d0]      = __float2half(o1a * rn);
            dst[d0 + 64] = __float2half(o2a * rn);
            dst[d1]      = __float2half(o1b * rn);
            dst[d1 + 64] = __float2half(o2b * rn);
        }
    } else {
        for (int rr = 0; rr < 16; rr++) {
            const int r = wid * 16 + rr;
            const int row = m0 + r;
            const float* fr = ft + r * EST;
            float sg = warp_sum(x[(size_t)row * C_ + lane] * Wgate[lane * NH_ + h]);
            float gt = 2.f / (1.f + __expf(-sg));
            __half* dst = g_vf + (size_t)row * C_ + n0;
            const float* vep = ve + (size_t)row * C_ + n0;
            #pragma unroll
            for (int i2 = 0; i2 < 4; i2++) {
                const int d = lane + i2 * 32;
                dst[d] = __float2half(fr[d] + gt * vep[d]);
            }
        }
    }
}

// proj GEMM: plain fp32 epilogue to out
__global__ __launch_bounds__(256, 2) void gemm_proj(
    const __half* __restrict__ A, float* __restrict__ Cm)
{
    extern __shared__ __half smb[];
    const int m0 = blockIdx.y * 128, n0 = blockIdx.x * 128;
    float acc[2][8][4];
    gemm_mainloop(A, g_wt[3], m0, n0, C_, smb, acc);

    const int tid = threadIdx.x, wid = tid >> 5, lane = tid & 31;
    const int wm = wid & 3, wn = wid >> 2;
    const int cg = lane >> 2, ct = lane & 3;
    #pragma unroll
    for (int mt = 0; mt < 2; mt++) {
        const int row = m0 + wm * 32 + mt * 16 + cg;
        #pragma unroll
        for (int nt = 0; nt < 8; nt++) {
            const int col = n0 + wn * 64 + nt * 8 + ct * 2;
            *(float2*)(Cm + (size_t)row * C_ + col)       = make_float2(acc[mt][nt][0], acc[mt][nt][1]);
            *(float2*)(Cm + (size_t)(row + 8) * C_ + col) = make_float2(acc[mt][nt][2], acc[mt][nt][3]);
        }
    }
}

// ---------------------------------------------------------------------------
// HMMA fp16 flash attention (causal). BM=128, BN=64, HD=128.
// Fixed-reference softmax; l via ones-column MMA. KV loads for kt+1 are
// spread across the QK k16 loop; one barrier per kt at loop top.
// ---------------------------------------------------------------------------
#define FST    136                 // smem row stride (fp16 elems), 272B
#define FKV    (64 * FST)
#define FQ     (128 * FST)

__global__ __launch_bounds__(256, 2) void flash_mma()
{
    extern __shared__ __half fsm[];
    __half* sQ  = fsm;                      // [128][FST]
    __half* sKV = sQ + FQ;                  // 2 stages x (K|V)[64][FST]

    const int tid = threadIdx.x, wid = tid >> 5, lane = tid & 31;
    const int qb = gridDim.x - 1 - blockIdx.x;   // big tiles first
    const int h  = blockIdx.y;
    const int b  = blockIdx.z;

    const size_t qrow0 = (size_t)(b * T_ + qb * 128) * C_ + h * HD_;
    const size_t krow0 = (size_t)(b * T_) * C_ + h * HD_;

    auto load_kv_slice = [&](int kt, int s, int i) {
        __half* base = sKV + s * (2 * FKV);
        const size_t kb0 = krow0 + (size_t)(kt * 64) * C_;
        int idx = tid + i * 256;
        int r = idx >> 4, c8 = (idx & 15) * 8;
        size_t go = kb0 + (size_t)r * C_ + c8;
        unsigned off = r * FST + c8;
        CP_ASYNC16(smem_u32(base + off),       g_kf + go);
        CP_ASYNC16(smem_u32(base + FKV + off), g_vf + go);
    };

    for (int i = tid; i < 2048; i += 256) {
        int r = i >> 4, c8 = (i & 15) * 8;
        CP_ASYNC16(smem_u32(sQ + r * FST + c8), g_qf + qrow0 + (size_t)r * C_ + c8);
    }
    #pragma unroll
    for (int i = 0; i < 4; i++) load_kv_slice(0, 0, i);
    CP_COMMIT();
    CP_WAIT0();
    __syncthreads();

    const int g  = lane >> 2;
    const int t4 = lane & 3;
    const int a_row = wid * 16 + (lane & 15);
    const int a_c8  = (lane >> 4) * 8;
    const int b_row = (lane & 7) + ((lane >> 4) << 3);
    const int b_c8  = ((lane >> 3) & 1) * 8;
    const int v_row = lane & 15;
    const int v_c8  = (lane >> 4) * 8;

    // ones B-fragment: column n=0 of an m16n8k16 B tile is all 1.0 (fp16).
    unsigned bones[2];
    bones[0] = bones[1] = (lane < 4) ? 0x3C003C00u : 0u;

    float lacc[4] = {0.f, 0.f, 0.f, 0.f};
    float oacc[16][4];
    #pragma unroll
    for (int dt = 0; dt < 16; dt++)
        #pragma unroll
        for (int r = 0; r < 4; r++) oacc[dt][r] = 0.f;

    const int nkt = 2 * qb + 2;

    for (int kt = 0; kt < nkt; kt++) {
        const int s = kt & 1;
        if (kt > 0) { CP_WAIT0(); __syncthreads(); }

        __half* Kh = sKV + s * (2 * FKV);
        __half* Vh = Kh + FKV;
        const bool pf = (kt + 1 < nkt);

        // --- S = Q K^T (Q pre-scaled by QSC), KV(kt+1) loads interleaved ---
        float sacc[8][4];
        #pragma unroll
        for (int nt = 0; nt < 8; nt++)
            #pragma unroll
            for (int r = 0; r < 4; r++) sacc[nt][r] = 0.f;

        #pragma unroll
        for (int k16 = 0; k16 < 8; k16++) {
            if (pf && !(k16 & 1)) load_kv_slice(kt + 1, s ^ 1, k16 >> 1);
            unsigned ah[4];
            ldmatrix_x4(ah, smem_u32(sQ + a_row * FST + k16 * 16 + a_c8));
            #pragma unroll
            for (int nt2 = 0; nt2 < 4; nt2++) {
                unsigned bh[4];
                ldmatrix_x4(bh, smem_u32(Kh + (nt2 * 16 + b_row) * FST + k16 * 16 + b_c8));
                #pragma unroll
                for (int t = 0; t < 2; t++)
                    mma_f16(sacc[nt2 * 2 + t], ah, bh + 2 * t);
            }
        }
        if (pf) CP_COMMIT();

        if (kt >= 2 * qb) {
            const int row0 = qb * 128 + wid * 16 + g;
            #pragma unroll
            for (int nt = 0; nt < 8; nt++) {
                const int col = kt * 64 + nt * 8 + 2 * t4;
                if (col     > row0)     sacc[nt][0] = -1e30f;
                if (col + 1 > row0)     sacc[nt][1] = -1e30f;
                if (col     > row0 + 8) sacc[nt][2] = -1e30f;
                if (col + 1 > row0 + 8) sacc[nt][3] = -1e30f;
            }
        }

        // --- p = 2^(t - FMAX_REF) ---
        #pragma unroll
        for (int nt = 0; nt < 8; nt++) {
            sacc[nt][0] = ex2(sacc[nt][0] - FMAX_REF);
            sacc[nt][1] = ex2(sacc[nt][1] - FMAX_REF);
            sacc[nt][2] = ex2(sacc[nt][2] - FMAX_REF);
            sacc[nt][3] = ex2(sacc[nt][3] - FMAX_REF);
        }

        // --- pack all P fragments up front, then l-MMAs, then PV ---
        unsigned ph[4][4];
        #pragma unroll
        for (int kt2 = 0; kt2 < 4; kt2++) {
            #pragma unroll
            for (int half = 0; half < 2; half++) {
                const float* sp = sacc[2 * kt2 + half];
                ph[kt2][half * 2 + 0] = pack_h2(sp[0], sp[1]);
                ph[kt2][half * 2 + 1] = pack_h2(sp[2], sp[3]);
            }
        }
        #pragma unroll
        for (int kt2 = 0; kt2 < 4; kt2++)
            mma_f16(lacc, ph[kt2], bones);

        #pragma unroll
        for (int kt2 = 0; kt2 < 4; kt2++) {
            #pragma unroll
            for (int dp = 0; dp < 4; dp++) {
                unsigned vh[2][4];
                #pragma unroll
                for (int d = 0; d < 2; d++) {
                    const int dt2 = dp * 2 + d;
                    ldmatrix_x4_trans(vh[d], smem_u32(Vh + (kt2 * 16 + v_row) * FST + dt2 * 16 + v_c8));
                }
                #pragma unroll
                for (int d = 0; d < 2; d++)
                    #pragma unroll
                    for (int n = 0; n < 2; n++)
                        mma_f16(oacc[(dp * 2 + d) * 2 + n], ph[kt2], vh[d] + 2 * n);
            }
        }
    }

    // epilogue: broadcast l from ct==0 lanes, normalize, store fp16
    float l0 = __shfl_sync(0xffffffffu, lacc[0], lane & 28);
    float l1 = __shfl_sync(0xffffffffu, lacc[2], lane & 28);
    const float inv0 = 1.f / l0, inv1 = 1.f / l1;
    __half* yb = g_yf + (size_t)(b * T_ + qb * 128 + wid * 16) * C_ + h * HD_;
    #pragma unroll
    for (int dt = 0; dt < 16; dt++) {
        const int col = dt * 8 + 2 * t4;
        *(__half2*)(yb + (size_t)g * C_ + col) =
            __float22half2_rn(make_float2(oacc[dt][0] * inv0, oacc[dt][1] * inv0));
        *(__half2*)(yb + (size_t)(g + 8) * C_ + col) =
            __float22half2_rn(make_float2(oacc[dt][2] * inv1, oacc[dt][3] * inv1));
    }
}

// ---------------------------------------------------------------------------
// Launch
// ---------------------------------------------------------------------------
extern "C" void kernel_launch(void* const* d_in, const int* in_sizes, int n_in,
                              void* d_out, int out_size)
{
    (void)in_sizes; (void)n_in; (void)out_size;
    const float* x     = (const float*)d_in[0];
    const float* ve    = (const float*)d_in[1];
    const float* cosb  = (const float*)d_in[2];
    const float* sinb  = (const float*)d_in[3];
    const float* Wq    = (const float*)d_in[4];
    const float* Wk    = (const float*)d_in[5];
    const float* Wv    = (const float*)d_in[6];
    const float* Wgate = (const float*)d_in[7];
    const float* Wproj = (const float*)d_in[8];
    float* out = (float*)d_out;

    __half *xf, *yf;
    cudaGetSymbolAddress((void**)&xf, g_xf);
    cudaGetSymbolAddress((void**)&yf, g_yf);

    prep_inputs<<<dim3(64, 64, 5), dim3(32, 8)>>>(x, Wq, Wk, Wv, Wproj);

    const int gemm_smem = NSTAGE * STAGE_E * (int)sizeof(__half);  // 110592 B
    cudaFuncSetAttribute(gemm_qkv_fused, cudaFuncAttributeMaxDynamicSharedMemorySize, gemm_smem);
    cudaFuncSetAttribute(gemm_proj,      cudaFuncAttributeMaxDynamicSharedMemorySize, gemm_smem);
    gemm_qkv_fused<<<dim3(C_/128, M_/128, 3), 256, gemm_smem>>>(xf, x, ve, cosb, sinb, Wgate);

    const int fsmem = (FQ + 4 * FKV) * (int)sizeof(__half);  // 104448 B
    cudaFuncSetAttribute(flash_mma, cudaFuncAttributeMaxDynamicSharedMemorySize, fsmem);
    flash_mma<<<dim3(T_/128, NH_, B_), 256, fsmem>>>();

    gemm_proj<<<dim3(C_/128, M_/128), 256, gemm_smem>>>(yf, out);
}

// round 12
// speedup vs baseline: 8.6103x; 1.0086x over previous
#include <cuda_runtime.h>
#include <cuda_fp16.h>
#include <math.h>

// Problem constants
#define B_       2
#define T_       2048
#define C_       2048
#define NH_      16
#define HD_      128
#define GATE_CH_ 32
#define M_       (B_*T_)   // 4096 rows

// ---------------------------------------------------------------------------
// Scratch (device globals: allocation-free per harness rules)
// ---------------------------------------------------------------------------
__device__ __half g_xf[(size_t)M_*C_];
__device__ __half g_yf[(size_t)M_*C_];
__device__ __half g_qf[(size_t)M_*C_];
__device__ __half g_kf[(size_t)M_*C_];
__device__ __half g_vf[(size_t)M_*C_];
__device__ __half g_wt[4][(size_t)C_*C_];   // transposed [N][K] Wq,Wk,Wv,Wproj

// ---------------------------------------------------------------------------
// PTX helpers
// ---------------------------------------------------------------------------
__device__ __forceinline__ unsigned smem_u32(const void* p) {
    unsigned a;
    asm("{ .reg .u64 t; cvta.to.shared.u64 t, %1; cvt.u32.u64 %0, t; }"
        : "=r"(a) : "l"(p));
    return a;
}

#define CP_ASYNC16(dst_u32, src_ptr) \
    asm volatile("cp.async.cg.shared.global [%0], [%1], 16;" \
                 :: "r"(dst_u32), "l"(src_ptr))
#define CP_COMMIT() asm volatile("cp.async.commit_group;" ::: "memory")
#define CP_WAIT0()  asm volatile("cp.async.wait_group 0;" ::: "memory")
#define CP_WAIT1()  asm volatile("cp.async.wait_group 1;" ::: "memory")

__device__ __forceinline__ void ldmatrix_x4(unsigned* r, unsigned addr) {
    asm volatile("ldmatrix.sync.aligned.m8n8.x4.shared.b16 {%0,%1,%2,%3}, [%4];"
                 : "=r"(r[0]), "=r"(r[1]), "=r"(r[2]), "=r"(r[3]) : "r"(addr));
}
__device__ __forceinline__ void ldmatrix_x4_trans(unsigned* r, unsigned addr) {
    asm volatile("ldmatrix.sync.aligned.m8n8.x4.trans.shared.b16 {%0,%1,%2,%3}, [%4];"
                 : "=r"(r[0]), "=r"(r[1]), "=r"(r[2]), "=r"(r[3]) : "r"(addr));
}
__device__ __forceinline__ void mma_f16(float* c, const unsigned* a, const unsigned* b) {
    asm volatile(
        "mma.sync.aligned.m16n8k16.row.col.f32.f16.f16.f32 "
        "{%0,%1,%2,%3}, {%4,%5,%6,%7}, {%8,%9}, {%0,%1,%2,%3};"
        : "+f"(c[0]), "+f"(c[1]), "+f"(c[2]), "+f"(c[3])
        : "r"(a[0]), "r"(a[1]), "r"(a[2]), "r"(a[3]), "r"(b[0]), "r"(b[1]));
}
__device__ __forceinline__ unsigned pack_h2(float lo, float hi) {
    __half2 h = __float22half2_rn(make_float2(lo, hi));
    return *reinterpret_cast<unsigned*>(&h);
}
// two fp16 exp2's in one MUFU op
__device__ __forceinline__ unsigned ex2_h2(unsigned x) {
    unsigned y;
    asm("ex2.approx.f16x2 %0, %1;" : "=r"(y) : "r"(x));
    return y;
}
__device__ __forceinline__ float warp_sum(float v) {
    #pragma unroll
    for (int d = 16; d >= 1; d >>= 1) v += __shfl_xor_sync(0xffffffffu, v, d);
    return v;
}

// scale * log2(e), folded into q at QKV epilogue
#define QSC (0.08838834764831845f * 1.4426950408889634f)
// fixed softmax reference (log2 units). |t| <= 16.33 by Cauchy-Schwarz on
// RMS-normed q,k, so p = 2^(t-5) in [2^-21.3, 2^11.3]: provably no fp16
// overflow and no subnormal flush-to-zero of any term.
#define FMAX_REF 5.0f

// ---------------------------------------------------------------------------
// prep_inputs: z<4: transpose W[K][N] fp32 -> g_wt[z][N][K] fp16;
//              z=4: convert x fp32 -> g_xf fp16.
// grid (64, 64, 5), block (32, 8).
// ---------------------------------------------------------------------------
__global__ __launch_bounds__(256) void prep_inputs(
    const float* __restrict__ x,
    const float* __restrict__ Wq, const float* __restrict__ Wk,
    const float* __restrict__ Wv, const float* __restrict__ Wproj)
{
    __shared__ float tile[32][33];
    const int z = blockIdx.z;
    const int tid = threadIdx.y * 32 + threadIdx.x;

    if (z == 4) {
        const int idx0 = (blockIdx.y * 64 + blockIdx.x) * 256 + tid;
        #pragma unroll
        for (int r = 0; r < 2; r++) {
            const int i = idx0 + r * (64 * 64 * 256);
            float4 v = ((const float4*)x)[i];
            __half2* op = (__half2*)(g_xf + (size_t)i * 4);
            op[0] = __float22half2_rn(make_float2(v.x, v.y));
            op[1] = __float22half2_rn(make_float2(v.z, v.w));
        }
        return;
    }

    const float* W = (z == 0) ? Wq : (z == 1) ? Wk : (z == 2) ? Wv : Wproj;
    __half* out = g_wt[z];
    int k0 = blockIdx.y * 32, n0 = blockIdx.x * 32;
    int tx = threadIdx.x, ty = threadIdx.y;
    #pragma unroll
    for (int r = 0; r < 4; r++)
        tile[ty + 8 * r][tx] = W[(size_t)(k0 + ty + 8 * r) * C_ + n0 + tx];
    __syncthreads();
    #pragma unroll
    for (int r = 0; r < 4; r++) {
        float v = tile[tx][ty + 8 * r];
        out[(size_t)(n0 + ty + 8 * r) * C_ + k0 + tx] = __float2half(v);
    }
}

// ---------------------------------------------------------------------------
// HMMA fp16 GEMM mainloop. 128x128 CTA tile, 8 warps (4x2), k-chunk 64,
// cp.async 3-stage pipeline, loads spread across the k16 blocks,
// one barrier per chunk.
// ---------------------------------------------------------------------------
#define KC        64
#define AS_STRIDE 72                        // fp16 elems per smem row (144B)
#define TILE_E    (128 * AS_STRIDE)         // 9216 elems
#define STAGE_E   (2 * TILE_E)              // A | B
#define NSTAGE    3

__device__ __forceinline__ void gemm_mainloop(
    const __half* __restrict__ A, const __half* __restrict__ Bm,
    int m0, int n0, int K, __half* smb, float acc[2][8][4])
{
    const int tid = threadIdx.x, wid = tid >> 5, lane = tid & 31;
    const int NCH = K / KC;
    const int wm = wid & 3;
    const int wn = wid >> 2;

    auto load_slice = [&](int c, int s, int i) {
        const int k0 = c * KC;
        __half* base = smb + s * STAGE_E;
        int cidx = tid + i * 256;          // 0..1023
        int row  = cidx >> 3;
        int col8 = (cidx & 7) * 8;
        unsigned so = smem_u32(base + row * AS_STRIDE + col8);
        CP_ASYNC16(so,              A  + (size_t)(m0 + row) * K + k0 + col8);
        CP_ASYNC16(so + TILE_E * 2, Bm + (size_t)(n0 + row) * K + k0 + col8);
    };

    #pragma unroll
    for (int mt = 0; mt < 2; mt++)
        #pragma unroll
        for (int nt = 0; nt < 8; nt++)
            #pragma unroll
            for (int r = 0; r < 4; r++) acc[mt][nt][r] = 0.f;

    #pragma unroll
    for (int i = 0; i < 4; i++) load_slice(0, 0, i);
    CP_COMMIT();
    #pragma unroll
    for (int i = 0; i < 4; i++) load_slice(1, 1, i);
    CP_COMMIT();

    const int a_row = wm * 32 + (lane & 15);
    const int a_k8  = (lane >> 4) * 8;
    const int b_r   = lane & 7;
    const int b_grp = lane >> 3;
    const int b_row = wn * 64 + (b_grp >> 1) * 8 + b_r;
    const int b_k8  = (b_grp & 1) * 8;

    for (int c = 0; c < NCH; c++) {
        if (c + 1 < NCH) CP_WAIT1();
        else             CP_WAIT0();
        __syncthreads();

        const __half* st = smb + (c % NSTAGE) * STAGE_E;
        const __half* sA = st;
        const __half* sB = st + TILE_E;
        const bool pf = (c + 2 < NCH);
        const int  ps = (c + 2) % NSTAGE;

        #pragma unroll
        for (int k16 = 0; k16 < 4; k16++) {
            if (pf) load_slice(c + 2, ps, k16);
            const int kb = k16 * 16;
            unsigned ah[2][4];
            #pragma unroll
            for (int mt = 0; mt < 2; mt++)
                ldmatrix_x4(ah[mt], smem_u32(sA + (a_row + mt * 16) * AS_STRIDE + kb + a_k8));
            unsigned bh[4][4];
            #pragma unroll
            for (int j = 0; j < 4; j++)
                ldmatrix_x4(bh[j], smem_u32(sB + (b_row + j * 16) * AS_STRIDE + kb + b_k8));
            #pragma unroll
            for (int j = 0; j < 4; j++)
                #pragma unroll
                for (int t = 0; t < 2; t++)
                    #pragma unroll
                    for (int mt = 0; mt < 2; mt++)
                        mma_f16(acc[mt][j * 2 + t], ah[mt], bh[j] + t * 2);
        }
        if (pf) CP_COMMIT();
    }
    __syncthreads();   // protect epilogue smem reuse
}

// ---------------------------------------------------------------------------
// Fused QKV GEMM + prep epilogue. z=0: q (rope+rms, pre-scaled by QSC);
// z=1: k (rope+rms); z=2: v + gate*ve. 128 cols per tile = one full head.
// ---------------------------------------------------------------------------
#define EST 130   // fp32 epilogue smem row stride

__global__ __launch_bounds__(256, 2) void gemm_qkv_fused(
    const __half* __restrict__ A,
    const float* __restrict__ x, const float* __restrict__ ve,
    const float* __restrict__ cosb, const float* __restrict__ sinb,
    const float* __restrict__ Wgate)
{
    extern __shared__ __half smb[];
    const int z = blockIdx.z;
    const int m0 = blockIdx.y * 128, n0 = blockIdx.x * 128;

    float acc[2][8][4];
    gemm_mainloop(A, g_wt[z], m0, n0, C_, smb, acc);

    // spill fp32 tile to smem (stage buffers are free now)
    const int tid = threadIdx.x, wid = tid >> 5, lane = tid & 31;
    const int wm = wid & 3, wn = wid >> 2;
    const int cg = lane >> 2, ct = lane & 3;
    float* ft = (float*)smb;
    #pragma unroll
    for (int mt = 0; mt < 2; mt++) {
        const int r = wm * 32 + mt * 16 + cg;
        #pragma unroll
        for (int nt = 0; nt < 8; nt++) {
            const int cc = wn * 64 + nt * 8 + ct * 2;
            ft[r * EST + cc]           = acc[mt][nt][0];
            ft[r * EST + cc + 1]       = acc[mt][nt][1];
            ft[(r + 8) * EST + cc]     = acc[mt][nt][2];
            ft[(r + 8) * EST + cc + 1] = acc[mt][nt][3];
        }
    }
    __syncthreads();

    const int h = n0 >> 7;   // head index
    if (z < 2) {
        __half* gout = (z == 0) ? g_qf : g_kf;
        const float post = (z == 0) ? QSC : 1.f;
        for (int rr = 0; rr < 16; rr++) {
            const int r = wid * 16 + rr;
            const int row = m0 + r;
            const int t = row & (T_ - 1);
            const float* fr = ft + r * EST;
            const float* cr = cosb + (size_t)t * 64;
            const float* sr = sinb + (size_t)t * 64;
            const int d0 = lane, d1 = lane + 32;
            float x1a = fr[d0], x2a = fr[d0 + 64];
            float x1b = fr[d1], x2b = fr[d1 + 64];
            float ca = cr[d0], sa = sr[d0], cb = cr[d1], sb = sr[d1];
            float o1a =  x1a * ca + x2a * sa;
            float o2a = -x1a * sa + x2a * ca;
            float o1b =  x1b * cb + x2b * sb;
            float o2b = -x1b * sb + x2b * cb;
            float ss = warp_sum(o1a*o1a + o2a*o2a + o1b*o1b + o2b*o2b);
            float rn = rsqrtf(ss * (1.f / 128.f) + 1e-6f) * post;
            __half* dst = gout + (size_t)row * C_ + n0;
            dst[d0]      = __float2half(o1a * rn);
            dst[d0 + 64] = __float2half(o2a * rn);
            dst[d1]      = __float2half(o1b * rn);
            dst[d1 + 64] = __float2half(o2b * rn);
        }
    } else {
        for (int rr = 0; rr < 16; rr++) {
            const int r = wid * 16 + rr;
            const int row = m0 + r;
            const float* fr = ft + r * EST;
            float sg = warp_sum(x[(size_t)row * C_ + lane] * Wgate[lane * NH_ + h]);
            float gt = 2.f / (1.f + __expf(-sg));
            __half* dst = g_vf + (size_t)row * C_ + n0;
            const float* vep = ve + (size_t)row * C_ + n0;
            #pragma unroll
            for (int i2 = 0; i2 < 4; i2++) {
                const int d = lane + i2 * 32;
                dst[d] = __float2half(fr[d] + gt * vep[d]);
            }
        }
    }
}

// proj GEMM: plain fp32 epilogue to out
__global__ __launch_bounds__(256, 2) void gemm_proj(
    const __half* __restrict__ A, float* __restrict__ Cm)
{
    extern __shared__ __half smb[];
    const int m0 = blockIdx.y * 128, n0 = blockIdx.x * 128;
    float acc[2][8][4];
    gemm_mainloop(A, g_wt[3], m0, n0, C_, smb, acc);

    const int tid = threadIdx.x, wid = tid >> 5, lane = tid & 31;
    const int wm = wid & 3, wn = wid >> 2;
    const int cg = lane >> 2, ct = lane & 3;
    #pragma unroll
    for (int mt = 0; mt < 2; mt++) {
        const int row = m0 + wm * 32 + mt * 16 + cg;
        #pragma unroll
        for (int nt = 0; nt < 8; nt++) {
            const int col = n0 + wn * 64 + nt * 8 + ct * 2;
            *(float2*)(Cm + (size_t)row * C_ + col)       = make_float2(acc[mt][nt][0], acc[mt][nt][1]);
            *(float2*)(Cm + (size_t)(row + 8) * C_ + col) = make_float2(acc[mt][nt][2], acc[mt][nt][3]);
        }
    }
}

// ---------------------------------------------------------------------------
// HMMA fp16 flash attention (causal). BM=128, BN=64, HD=128.
// Fixed-reference softmax; P computed with ex2.approx.f16x2 (half MUFU ops,
// output pre-packed for MMA). l via ones-column MMA. KV loads for kt+1 spread
// across the QK k16 loop; one barrier per kt.
// ---------------------------------------------------------------------------
#define FST    136                 // smem row stride (fp16 elems), 272B
#define FKV    (64 * FST)
#define FQ     (128 * FST)

__global__ __launch_bounds__(256, 2) void flash_mma()
{
    extern __shared__ __half fsm[];
    __half* sQ  = fsm;                      // [128][FST]
    __half* sKV = sQ + FQ;                  // 2 stages x (K|V)[64][FST]

    const int tid = threadIdx.x, wid = tid >> 5, lane = tid & 31;
    const int qb = gridDim.x - 1 - blockIdx.x;   // big tiles first
    const int h  = blockIdx.y;
    const int b  = blockIdx.z;

    const size_t qrow0 = (size_t)(b * T_ + qb * 128) * C_ + h * HD_;
    const size_t krow0 = (size_t)(b * T_) * C_ + h * HD_;

    auto load_kv_slice = [&](int kt, int s, int i) {
        __half* base = sKV + s * (2 * FKV);
        const size_t kb0 = krow0 + (size_t)(kt * 64) * C_;
        int idx = tid + i * 256;
        int r = idx >> 4, c8 = (idx & 15) * 8;
        size_t go = kb0 + (size_t)r * C_ + c8;
        unsigned off = r * FST + c8;
        CP_ASYNC16(smem_u32(base + off),       g_kf + go);
        CP_ASYNC16(smem_u32(base + FKV + off), g_vf + go);
    };

    for (int i = tid; i < 2048; i += 256) {
        int r = i >> 4, c8 = (i & 15) * 8;
        CP_ASYNC16(smem_u32(sQ + r * FST + c8), g_qf + qrow0 + (size_t)r * C_ + c8);
    }
    #pragma unroll
    for (int i = 0; i < 4; i++) load_kv_slice(0, 0, i);
    CP_COMMIT();
    CP_WAIT0();
    __syncthreads();

    const int g  = lane >> 2;
    const int t4 = lane & 3;
    const int a_row = wid * 16 + (lane & 15);
    const int a_c8  = (lane >> 4) * 8;
    const int b_row = (lane & 7) + ((lane >> 4) << 3);
    const int b_c8  = ((lane >> 3) & 1) * 8;
    const int v_row = lane & 15;
    const int v_c8  = (lane >> 4) * 8;

    // ones B-fragment: column n=0 of an m16n8k16 B tile is all 1.0 (fp16).
    unsigned bones[2];
    bones[0] = bones[1] = (lane < 4) ? 0x3C003C00u : 0u;

    float lacc[4] = {0.f, 0.f, 0.f, 0.f};
    float oacc[16][4];
    #pragma unroll
    for (int dt = 0; dt < 16; dt++)
        #pragma unroll
        for (int r = 0; r < 4; r++) oacc[dt][r] = 0.f;

    const int nkt = 2 * qb + 2;

    for (int kt = 0; kt < nkt; kt++) {
        const int s = kt & 1;
        if (kt > 0) { CP_WAIT0(); __syncthreads(); }

        __half* Kh = sKV + s * (2 * FKV);
        __half* Vh = Kh + FKV;
        const bool pf = (kt + 1 < nkt);

        // --- S = Q K^T (Q pre-scaled by QSC), KV(kt+1) loads interleaved ---
        float sacc[8][4];
        #pragma unroll
        for (int nt = 0; nt < 8; nt++)
            #pragma unroll
            for (int r = 0; r < 4; r++) sacc[nt][r] = 0.f;

        #pragma unroll
        for (int k16 = 0; k16 < 8; k16++) {
            if (pf && !(k16 & 1)) load_kv_slice(kt + 1, s ^ 1, k16 >> 1);
            unsigned ah[4];
            ldmatrix_x4(ah, smem_u32(sQ + a_row * FST + k16 * 16 + a_c8));
            #pragma unroll
            for (int nt2 = 0; nt2 < 4; nt2++) {
                unsigned bh[4];
                ldmatrix_x4(bh, smem_u32(Kh + (nt2 * 16 + b_row) * FST + k16 * 16 + b_c8));
                #pragma unroll
                for (int t = 0; t < 2; t++)
                    mma_f16(sacc[nt2 * 2 + t], ah, bh + 2 * t);
            }
        }
        if (pf) CP_COMMIT();

        if (kt >= 2 * qb) {
            const int row0 = qb * 128 + wid * 16 + g;
            #pragma unroll
            for (int nt = 0; nt < 8; nt++) {
                const int col = kt * 64 + nt * 8 + 2 * t4;
                if (col     > row0)     sacc[nt][0] = -1e30f;
                if (col + 1 > row0)     sacc[nt][1] = -1e30f;
                if (col     > row0 + 8) sacc[nt][2] = -1e30f;
                if (col + 1 > row0 + 8) sacc[nt][3] = -1e30f;
            }
        }

        // --- P = 2^(t - FMAX_REF) via f16x2 MUFU; result is MMA-ready ---
        // (masked t -> -inf in fp16 -> p = 0)
        unsigned ph[4][4];
        #pragma unroll
        for (int kt2 = 0; kt2 < 4; kt2++) {
            #pragma unroll
            for (int half = 0; half < 2; half++) {
                const float* sp = sacc[2 * kt2 + half];
                ph[kt2][half * 2 + 0] =
                    ex2_h2(pack_h2(sp[0] - FMAX_REF, sp[1] - FMAX_REF));
                ph[kt2][half * 2 + 1] =
                    ex2_h2(pack_h2(sp[2] - FMAX_REF, sp[3] - FMAX_REF));
            }
        }
        #pragma unroll
        for (int kt2 = 0; kt2 < 4; kt2++)
            mma_f16(lacc, ph[kt2], bones);

        #pragma unroll
        for (int kt2 = 0; kt2 < 4; kt2++) {
            #pragma unroll
            for (int dp = 0; dp < 4; dp++) {
                unsigned vh[2][4];
                #pragma unroll
                for (int d = 0; d < 2; d++) {
                    const int dt2 = dp * 2 + d;
                    ldmatrix_x4_trans(vh[d], smem_u32(Vh + (kt2 * 16 + v_row) * FST + dt2 * 16 + v_c8));
                }
                #pragma unroll
                for (int d = 0; d < 2; d++)
                    #pragma unroll
                    for (int n = 0; n < 2; n++)
                        mma_f16(oacc[(dp * 2 + d) * 2 + n], ph[kt2], vh[d] + 2 * n);
            }
        }
    }

    // epilogue: broadcast l from ct==0 lanes, normalize, store fp16
    float l0 = __shfl_sync(0xffffffffu, lacc[0], lane & 28);
    float l1 = __shfl_sync(0xffffffffu, lacc[2], lane & 28);
    const float inv0 = 1.f / l0, inv1 = 1.f / l1;
    __half* yb = g_yf + (size_t)(b * T_ + qb * 128 + wid * 16) * C_ + h * HD_;
    #pragma unroll
    for (int dt = 0; dt < 16; dt++) {
        const int col = dt * 8 + 2 * t4;
        *(__half2*)(yb + (size_t)g * C_ + col) =
            __float22half2_rn(make_float2(oacc[dt][0] * inv0, oacc[dt][1] * inv0));
        *(__half2*)(yb + (size_t)(g + 8) * C_ + col) =
            __float22half2_rn(make_float2(oacc[dt][2] * inv1, oacc[dt][3] * inv1));
    }
}

// ---------------------------------------------------------------------------
// Launch
// ---------------------------------------------------------------------------
extern "C" void kernel_launch(void* const* d_in, const int* in_sizes, int n_in,
                              void* d_out, int out_size)
{
    (void)in_sizes; (void)n_in; (void)out_size;
    const float* x     = (const float*)d_in[0];
    const float* ve    = (const float*)d_in[1];
    const float* cosb  = (const float*)d_in[2];
    const float* sinb  = (const float*)d_in[3];
    const float* Wq    = (const float*)d_in[4];
    const float* Wk    = (const float*)d_in[5];
    const float* Wv    = (const float*)d_in[6];
    const float* Wgate = (const float*)d_in[7];
    const float* Wproj = (const float*)d_in[8];
    float* out = (float*)d_out;

    __half *xf, *yf;
    cudaGetSymbolAddress((void**)&xf, g_xf);
    cudaGetSymbolAddress((void**)&yf, g_yf);

    prep_inputs<<<dim3(64, 64, 5), dim3(32, 8)>>>(x, Wq, Wk, Wv, Wproj);

    const int gemm_smem = NSTAGE * STAGE_E * (int)sizeof(__half);  // 110592 B
    cudaFuncSetAttribute(gemm_qkv_fused, cudaFuncAttributeMaxDynamicSharedMemorySize, gemm_smem);
    cudaFuncSetAttribute(gemm_proj,      cudaFuncAttributeMaxDynamicSharedMemorySize, gemm_smem);
    gemm_qkv_fused<<<dim3(C_/128, M_/128, 3), 256, gemm_smem>>>(xf, x, ve, cosb, sinb, Wgate);

    const int fsmem = (FQ + 4 * FKV) * (int)sizeof(__half);  // 104448 B
    cudaFuncSetAttribute(flash_mma, cudaFuncAttributeMaxDynamicSharedMemorySize, fsmem);
    flash_mma<<<dim3(T_/128, NH_, B_), 256, fsmem>>>();

    gemm_proj<<<dim3(C_/128, M_/128), 256, gemm_smem>>>(yf, out);
}